// round 12
// baseline (speedup 1.0000x reference)
#include <cuda_runtime.h>
#include <cuda_fp16.h>
#include <math.h>
#include <stdint.h>

#define Bb 64
#define Ss 256
#define BS (Bb*Ss)
#define DL 300
#define DA 74
#define DV 35
#define DH 128
#define EK 320
#define VOCAB 30522

// fp32 scratch
__device__ float g_xg_gru[6u*BS*192];
__device__ float g_tstep[(unsigned)BS*384];
__device__ float g_xg_lstm[2u*BS*512];
__device__ float g_xg_rgn[2u*BS*384];
__device__ float g_rgn_out[2u*Bb*128];
// fp16 scratch
__device__ __half g_seq_h[3u*BS*DH];
__device__ __half g_x_h[3u*BS*DH];
__device__ __half g_xT_h[3u*(unsigned)Bb*128*Ss];
__device__ __half g_P_h[6u*(unsigned)Bb*Ss*Ss];
__device__ __half g_tstep_h[(unsigned)BS*384];
__device__ __half g_sf_h[(unsigned)BS*256];
__device__ __half g_ac_h[(unsigned)BS*96];
__device__ __half g_vid_h[(unsigned)BS*64];
__device__ __half g_emb_h[(unsigned)VOCAB*EK];
__device__ __half g_WT_h[798720];

typedef unsigned long long ull;

__device__ __forceinline__ uint32_t s2u(const void* p) {
    return (uint32_t)__cvta_generic_to_shared(p);
}
__device__ __forceinline__ void cpa16(uint32_t dst, const void* src, int bytes) {
    asm volatile("cp.async.cg.shared.global [%0], [%1], 16, %2;"
                 :: "r"(dst), "l"(src), "r"(bytes));
}
__device__ __forceinline__ void mma_f16(float c[4], const uint32_t a[4], const uint32_t b[2]) {
    asm volatile(
        "mma.sync.aligned.m16n8k16.row.col.f32.f16.f16.f32 "
        "{%0,%1,%2,%3}, {%4,%5,%6,%7}, {%8,%9}, {%0,%1,%2,%3};"
        : "+f"(c[0]), "+f"(c[1]), "+f"(c[2]), "+f"(c[3])
        : "r"(a[0]), "r"(a[1]), "r"(a[2]), "r"(a[3]), "r"(b[0]), "r"(b[1]));
}
__device__ __forceinline__ ull pk(float x, float y) {
    ull r; asm("mov.b64 %0,{%1,%2};" : "=l"(r) : "f"(x), "f"(y)); return r;
}
__device__ __forceinline__ float2 upk(ull v) {
    float2 f; asm("mov.b64 {%0,%1},%2;" : "=f"(f.x), "=f"(f.y) : "l"(v)); return f;
}
__device__ __forceinline__ void ffma2(ull &d, ull a, ull b) {
    asm volatile("fma.rn.f32x2 %0, %1, %2, %0;" : "+l"(d) : "l"(a), "l"(b));
}
__device__ __forceinline__ void lds2x64(ull &a, ull &b, uint32_t addr) {
    asm volatile("ld.shared.v2.b64 {%0,%1},[%2];" : "=l"(a), "=l"(b) : "r"(addr));
}
__device__ __forceinline__ float sigf(float x) { return 1.f/(1.f + __expf(-x)); }
__device__ __forceinline__ float tanhfast(float x) {
    float y; asm("tanh.approx.f32 %0,%1;" : "=f"(y) : "f"(x)); return y;
}

// ---------------------------------------------------------------------------
// Prep: wtrans jobs [0,780) | emb convert [780,2688) | ac+vid convert [2688,3200)
// ---------------------------------------------------------------------------
#define PREP_WT 780
#define PREP_EMB 1908
#define PREP_CONV 512
__global__ void prep_all(const float* __restrict__ gru_Wi,
                         const float* __restrict__ lstm_Wi,
                         const float* __restrict__ rgn_Wx,
                         const float* __restrict__ pa,
                         const float* __restrict__ pv,
                         const float* __restrict__ pl,
                         __half* __restrict__ WT,
                         const float* __restrict__ ac, __half* __restrict__ ach,
                         const float* __restrict__ vid, __half* __restrict__ vidh,
                         const float* __restrict__ emb, __half* __restrict__ embh)
{
    int bid = blockIdx.x;
    int tx = threadIdx.x, ty = threadIdx.y;
    int tid = ty*32 + tx;

    if (bid >= PREP_WT + PREP_EMB) {
        // ac / vid conversions (grid-stride)
        const long TOT_A = (long)BS*96;
        const long TOT_V = (long)BS*64;
        long t = (long)(bid - PREP_WT - PREP_EMB)*256 + tid;
        long stride = (long)PREP_CONV*256;
        for (long i = t; i < TOT_A + TOT_V; i += stride) {
            if (i < TOT_A) {
                long row = i/96; int k = (int)(i - row*96);
                ach[i] = (k<74) ? __float2half(ac[row*74 + k]) : __float2half(0.f);
            } else {
                long j = i - TOT_A;
                long row = j/64; int k = (int)(j - row*64);
                vidh[j] = (k<35) ? __float2half(vid[row*35 + k]) : __float2half(0.f);
            }
        }
        return;
    }
    if (bid >= PREP_WT) {
        // emb conversion: 16 rows/block, 16 threads/row, 20 cols/thread
        int rb = (bid - PREP_WT)*16 + (tid>>4);
        if (rb >= VOCAB) return;
        int c0 = (tid&15)*20;
        __half* orow = embh + (long)rb*EK + c0;
        if (c0 >= DL) {
#pragma unroll
            for (int i=0;i<20;i+=2) *(__half2*)&orow[i] = __floats2half2_rn(0.f,0.f);
        } else {
            const float* irow = emb + (long)rb*DL + c0;
#pragma unroll
            for (int i=0;i<20;i+=4) {
                float4 v = *(const float4*)&irow[i];
                *(__half2*)&orow[i]   = __floats2half2_rn(v.x, v.y);
                *(__half2*)&orow[i+2] = __floats2half2_rn(v.z, v.w);
            }
        }
        return;
    }

    __half* gruT  = WT;
    __half* lstmT = gruT + 6*192*128;
    __half* rgnT  = lstmT + 2l*512*384;
    __half* projaT = rgnT + 2l*384*256;
    __half* projvT = projaT + 128*96;
    __half* projlT = projvT + 128*64;

    const float* in; __half* out;
    int K, N, KP, k0, n0;
    if (bid < 144) {
        int z = bid/24, rem = bid%24;
        K = 128; N = 192; KP = 128;
        k0 = (rem%4)*32; n0 = (rem/4)*32;
        in = gru_Wi + (long)z*K*N; out = gruT + (long)z*N*KP;
    } else if (bid < 528) {
        int b2 = bid-144; int z = b2/192, rem = b2%192;
        K = 384; N = 512; KP = 384;
        k0 = (rem%12)*32; n0 = (rem/12)*32;
        in = lstm_Wi + (long)z*K*N; out = lstmT + (long)z*N*KP;
    } else if (bid < 720) {
        int b2 = bid-528; int z = b2/96, rem = b2%96;
        K = 256; N = 384; KP = 256;
        k0 = (rem%8)*32; n0 = (rem/8)*32;
        in = rgn_Wx + (long)z*K*N; out = rgnT + (long)z*N*KP;
    } else if (bid < 732) {
        int rem = bid-720;
        K = 74; N = 128; KP = 96;
        k0 = (rem%3)*32; n0 = (rem/3)*32;
        in = pa; out = projaT;
    } else if (bid < 740) {
        int rem = bid-732;
        K = 35; N = 128; KP = 64;
        k0 = (rem%2)*32; n0 = (rem/2)*32;
        in = pv; out = projvT;
    } else {
        int rem = bid-740;
        K = 300; N = 128; KP = 320;
        k0 = (rem%10)*32; n0 = (rem/10)*32;
        in = pl; out = projlT;
    }

    __shared__ float t[32][33];
#pragma unroll
    for (int i=0;i<32;i+=8) {
        int k = k0+ty+i, n = n0+tx;
        t[ty+i][tx] = (k<K && n<N) ? in[(long)k*N+n] : 0.f;
    }
    __syncthreads();
#pragma unroll
    for (int i=0;i<32;i+=8) {
        int n = n0+ty+i, k = k0+tx;
        if (n<N && k<KP) out[(long)n*KP+k] = __float2half(t[tx][ty+i]);
    }
}

// ---------------------------------------------------------------------------
// FP16 NT GEMM (unchanged).
// ---------------------------------------------------------------------------
#define HSTR 20
#define HA_WORDS (128*HSTR)
#define HSTG (2*HA_WORDS)

template<int MODE, int OUT16>
__launch_bounds__(256, 2)
__global__ void gemm_h(const __half* __restrict__ A, const __half* __restrict__ B,
                       const float* __restrict__ bias, void* __restrict__ Cv,
                       int M, int N, int K,
                       long sA, long sB, long sBias, long sC, int ldc)
{
    extern __shared__ uint32_t smp[];
    int z = blockIdx.z;
    const __half* Ab = A + (MODE==1 ? (long)(z>>1)*sA : (long)z*sA);
    const __half* Bp = B + (long)z*sB;
    const float* bp = bias + (long)z*sBias;

    int m0 = blockIdx.y*128, n0 = blockIdx.x*128;
    int tid = threadIdx.x;
    int warp = tid>>5, lane = tid&31;
    int g = lane>>2, tig = lane&3;
    int wm = (warp&1)*64, wn = (warp>>1)*32;

    float c[4][4][4];
#pragma unroll
    for (int mt=0;mt<4;mt++)
#pragma unroll
        for (int nt=0;nt<4;nt++)
#pragma unroll
            for (int i=0;i<4;i++) c[mt][nt][i]=0.f;

    int lrow = tid>>1;
    int lseg = (tid&1)*8;
    const __half* arow = Ab + (long)(m0+lrow)*K;
    const __half* brow = Bp + (long)(n0+lrow)*K;
    bool bok = (n0+lrow) < N;

    auto load_tile = [&](int st, int k0) {
        uint32_t* As = smp + st*HSTG;
        uint32_t* Bs = As + HA_WORDS;
        cpa16(s2u(&As[lrow*HSTR + lseg]),     arow + k0 + lseg*2,     16);
        cpa16(s2u(&As[lrow*HSTR + lseg + 4]), arow + k0 + lseg*2 + 8, 16);
        cpa16(s2u(&Bs[lrow*HSTR + lseg]),     bok ? (brow + k0 + lseg*2)     : brow, bok?16:0);
        cpa16(s2u(&Bs[lrow*HSTR + lseg + 4]), bok ? (brow + k0 + lseg*2 + 8) : brow, bok?16:0);
    };
    auto compute = [&](int st) {
        const uint32_t* As = smp + st*HSTG;
        const uint32_t* Bs = As + HA_WORDS;
#pragma unroll
        for (int ks=0;ks<2;ks++) {
            uint32_t a[4][4], b[4][2];
#pragma unroll
            for (int mt=0;mt<4;mt++) {
                int base = (wm + mt*16 + g)*HSTR + ks*8 + tig;
                a[mt][0] = As[base];
                a[mt][1] = As[base + 8*HSTR];
                a[mt][2] = As[base + 4];
                a[mt][3] = As[base + 8*HSTR + 4];
            }
#pragma unroll
            for (int nt=0;nt<4;nt++) {
                int base = (wn + nt*8 + g)*HSTR + ks*8 + tig;
                b[nt][0] = Bs[base];
                b[nt][1] = Bs[base + 4];
            }
#pragma unroll
            for (int mt=0;mt<4;mt++)
#pragma unroll
                for (int nt=0;nt<4;nt++)
                    mma_f16(c[mt][nt], a[mt], b[nt]);
        }
    };

    int ktn = K>>5;
    load_tile(0, 0);
    asm volatile("cp.async.commit_group;");
    if (ktn > 1) load_tile(1, 32);
    asm volatile("cp.async.commit_group;");
    for (int kt=0; kt<ktn; kt++) {
        asm volatile("cp.async.wait_group 1;");
        __syncthreads();
        if (kt+2 < ktn) load_tile((kt+2)%3, (kt+2)*32);
        asm volatile("cp.async.commit_group;");
        compute(kt%3);
        __syncthreads();
    }

#pragma unroll
    for (int mt=0;mt<4;mt++) {
        long m = m0 + wm + mt*16 + g;
#pragma unroll
        for (int nt=0;nt<4;nt++) {
            int n = n0 + wn + nt*8 + tig*2;
            if (n < N) {
                float bx = bp[n], by = bp[n+1];
                float v00 = c[mt][nt][0]+bx, v01 = c[mt][nt][1]+by;
                float v10 = c[mt][nt][2]+bx, v11 = c[mt][nt][3]+by;
                if (OUT16) {
                    __half* Cb = (__half*)Cv + (long)z*sC;
                    *(__half2*)&Cb[m*ldc + n] = __floats2half2_rn(v00, v01);
                    *(__half2*)&Cb[(m+8)*ldc + n] = __floats2half2_rn(v10, v11);
                } else {
                    float* Cb = (float*)Cv + (long)z*sC;
                    float2 v0; v0.x = v00; v0.y = v01;
                    float2 v1; v1.x = v10; v1.y = v11;
                    *(float2*)&Cb[m*ldc + n] = v0;
                    *(float2*)&Cb[(m+8)*ldc + n] = v1;
                }
            }
        }
    }
}

// ---------------------------------------------------------------------------
// Fat modality projection (unchanged).
// ---------------------------------------------------------------------------
__launch_bounds__(256, 2)
__global__ void proj3_h(const __half* __restrict__ emb_h, const __half* __restrict__ ac_h,
                        const __half* __restrict__ vid_h, const __half* __restrict__ WT,
                        const float* __restrict__ bl, const float* __restrict__ ba,
                        const float* __restrict__ bv, const int* __restrict__ gidx,
                        __half* __restrict__ seq_h)
{
    extern __shared__ uint32_t smp[];
    const __half* projaT = WT + 6*192*128 + 2l*512*384 + 2l*384*256;
    const __half* projvT = projaT + 128*96;
    const __half* projlT = projvT + 128*64;

    int z = blockIdx.z;
    int K = (z==0) ? EK : ((z==1) ? 96 : 64);
    const __half* Ab = (z==0) ? emb_h : ((z==1) ? ac_h : vid_h);
    const __half* Bp = (z==0) ? projlT : ((z==1) ? projaT : projvT);
    const float* bp = (z==0) ? bl : ((z==1) ? ba : bv);
    __half* Cb = seq_h + (long)z*BS*DH;

    int m0 = blockIdx.y*128;
    int tid = threadIdx.x;
    int warp = tid>>5, lane = tid&31;
    int g = lane>>2, tig = lane&3;
    int wm = (warp&1)*64, wn = (warp>>1)*32;

    float c[4][4][4];
#pragma unroll
    for (int mt=0;mt<4;mt++)
#pragma unroll
        for (int nt=0;nt<4;nt++)
#pragma unroll
            for (int i=0;i<4;i++) c[mt][nt][i]=0.f;

    int lrow = tid>>1;
    int lseg = (tid&1)*8;
    long arow_m = m0 + lrow;
    const __half* arow = Ab + (z==0 ? (long)gidx[arow_m] : arow_m)*(long)K;
    const __half* brow = Bp + (long)lrow*K;

    auto load_tile = [&](int st, int k0) {
        uint32_t* As = smp + st*HSTG;
        uint32_t* Bs = As + HA_WORDS;
        cpa16(s2u(&As[lrow*HSTR + lseg]),     arow + k0 + lseg*2,     16);
        cpa16(s2u(&As[lrow*HSTR + lseg + 4]), arow + k0 + lseg*2 + 8, 16);
        cpa16(s2u(&Bs[lrow*HSTR + lseg]),     brow + k0 + lseg*2,     16);
        cpa16(s2u(&Bs[lrow*HSTR + lseg + 4]), brow + k0 + lseg*2 + 8, 16);
    };
    auto compute = [&](int st) {
        const uint32_t* As = smp + st*HSTG;
        const uint32_t* Bs = As + HA_WORDS;
#pragma unroll
        for (int ks=0;ks<2;ks++) {
            uint32_t a[4][4], b[4][2];
#pragma unroll
            for (int mt=0;mt<4;mt++) {
                int base = (wm + mt*16 + g)*HSTR + ks*8 + tig;
                a[mt][0] = As[base];
                a[mt][1] = As[base + 8*HSTR];
                a[mt][2] = As[base + 4];
                a[mt][3] = As[base + 8*HSTR + 4];
            }
#pragma unroll
            for (int nt=0;nt<4;nt++) {
                int base = (wn + nt*8 + g)*HSTR + ks*8 + tig;
                b[nt][0] = Bs[base];
                b[nt][1] = Bs[base + 4];
            }
#pragma unroll
            for (int mt=0;mt<4;mt++)
#pragma unroll
                for (int nt=0;nt<4;nt++)
                    mma_f16(c[mt][nt], a[mt], b[nt]);
        }
    };

    int ktn = K>>5;
    load_tile(0, 0);
    asm volatile("cp.async.commit_group;");
    if (ktn > 1) load_tile(1, 32);
    asm volatile("cp.async.commit_group;");
    for (int kt=0; kt<ktn; kt++) {
        asm volatile("cp.async.wait_group 1;");
        __syncthreads();
        if (kt+2 < ktn) load_tile((kt+2)%3, (kt+2)*32);
        asm volatile("cp.async.commit_group;");
        compute(kt%3);
        __syncthreads();
    }

#pragma unroll
    for (int mt=0;mt<4;mt++) {
        long m = m0 + wm + mt*16 + g;
#pragma unroll
        for (int nt=0;nt<4;nt++) {
            int n = wn + nt*8 + tig*2;
            float bx = bp[n], by = bp[n+1];
            *(__half2*)&Cb[m*128 + n] = __floats2half2_rn(c[mt][nt][0]+bx, c[mt][nt][1]+by);
            *(__half2*)&Cb[(m+8)*128 + n] = __floats2half2_rn(c[mt][nt][2]+bx, c[mt][nt][3]+by);
        }
    }
}

// ---------------------------------------------------------------------------
// Fat: fused QK^T+softmax + x transpose (unchanged).
// ---------------------------------------------------------------------------
#define QA64 (64*HSTR)
#define QB256 (256*HSTR)
#define Q64_STG (QA64 + QB256)

__launch_bounds__(256, 2)
__global__ void qk_xt(const __half* __restrict__ x, __half* __restrict__ P,
                      __half* __restrict__ xT, float scale)
{
    extern __shared__ uint32_t smp[];
    int bid = blockIdx.x;
    int tid = threadIdx.x;

    if (bid >= 1536) {
        __half* sm = (__half*)smp;
        int t = bid - 1536;
        int mb = t>>2;
        int m = mb>>6, b = mb&63;
        int s0 = (t&3)*64;
        const __half* src = x + ((long)m*BS + (long)b*Ss + s0)*128;
#pragma unroll
        for (int i=0;i<32;i++) {
            int idx = tid + i*256;
            int s = idx>>7, d = idx&127;
            sm[s*130 + d] = src[(long)s*128 + d];
        }
        __syncthreads();
        __half* dst = xT + (long)mb*128*Ss;
#pragma unroll
        for (int i=0;i<32;i++) {
            int idx = tid + i*256;
            int d = idx>>6, ss = idx&63;
            dst[(long)d*Ss + s0 + ss] = sm[ss*130 + d];
        }
        return;
    }

    const int qtab[6]  = {0,0,1,1,2,2};
    const int kvtab[6] = {1,2,0,2,0,1};
    int z = bid>>2;
    int p = z>>6, b = z&63;
    const __half* Ab = x + ((long)qtab[p]*BS + (long)b*Ss)*128;
    const __half* Bp = x + ((long)kvtab[p]*BS + (long)b*Ss)*128;
    __half* Cb = P + (long)z*Ss*Ss;
    int m0 = (bid&3)*64;
    int warp = tid>>5, lane = tid&31;
    int g = lane>>2, tig = lane&3;
    int wm = (warp&1)*32, wn = (warp>>1)*64;

    float c[2][8][4];
#pragma unroll
    for (int mt=0;mt<2;mt++)
#pragma unroll
        for (int nt=0;nt<8;nt++)
#pragma unroll
            for (int i=0;i<4;i++) c[mt][nt][i]=0.f;

    int arow_i = tid>>2;
    int aseg = (tid&3)*4;
    const __half* arow = Ab + (long)(m0+arow_i)*128;
    const __half* brow = Bp + (long)tid*128;

    auto load_tile = [&](int st, int k0) {
        uint32_t* As = smp + st*Q64_STG;
        uint32_t* Bs = As + QA64;
        cpa16(s2u(&As[arow_i*HSTR + aseg]), arow + k0 + aseg*2, 16);
#pragma unroll
        for (int h=0;h<4;h++)
            cpa16(s2u(&Bs[tid*HSTR + h*4]), brow + k0 + h*8, 16);
    };
    auto compute = [&](int st) {
        const uint32_t* As = smp + st*Q64_STG;
        const uint32_t* Bs = As + QA64;
#pragma unroll
        for (int ks=0;ks<2;ks++) {
            uint32_t a[2][4], bb[8][2];
#pragma unroll
            for (int mt=0;mt<2;mt++) {
                int base = (wm + mt*16 + g)*HSTR + ks*8 + tig;
                a[mt][0] = As[base];
                a[mt][1] = As[base + 8*HSTR];
                a[mt][2] = As[base + 4];
                a[mt][3] = As[base + 8*HSTR + 4];
            }
#pragma unroll
            for (int nt=0;nt<8;nt++) {
                int base = (wn + nt*8 + g)*HSTR + ks*8 + tig;
                bb[nt][0] = Bs[base];
                bb[nt][1] = Bs[base + 4];
            }
#pragma unroll
            for (int mt=0;mt<2;mt++)
#pragma unroll
                for (int nt=0;nt<8;nt++)
                    mma_f16(c[mt][nt], a[mt], bb[nt]);
        }
    };

    load_tile(0, 0);
    asm volatile("cp.async.commit_group;");
    load_tile(1, 32);
    asm volatile("cp.async.commit_group;");
    for (int kt=0; kt<4; kt++) {
        asm volatile("cp.async.wait_group 1;");
        __syncthreads();
        if (kt+2 < 4) load_tile((kt+2)%3, (kt+2)*32);
        asm volatile("cp.async.commit_group;");
        compute(kt%3);
        __syncthreads();
    }

#pragma unroll
    for (int mt=0;mt<2;mt++)
#pragma unroll
        for (int nt=0;nt<8;nt++)
#pragma unroll
            for (int i=0;i<4;i++) c[mt][nt][i] *= scale;

    float* red = (float*)smp;
    int wcol = warp>>1;
    float rmax[2][2], rinv[2][2];

#pragma unroll
    for (int mt=0;mt<2;mt++)
#pragma unroll
        for (int h=0;h<2;h++) {
            float m = -1e30f;
#pragma unroll
            for (int nt=0;nt<8;nt++)
                m = fmaxf(m, fmaxf(c[mt][nt][2*h], c[mt][nt][2*h+1]));
            m = fmaxf(m, __shfl_xor_sync(0xffffffffu, m, 1));
            m = fmaxf(m, __shfl_xor_sync(0xffffffffu, m, 2));
            if (tig == 0) red[(wm + mt*16 + g + h*8)*4 + wcol] = m;
        }
    __syncthreads();
#pragma unroll
    for (int mt=0;mt<2;mt++)
#pragma unroll
        for (int h=0;h<2;h++) {
            int r = wm + mt*16 + g + h*8;
            rmax[mt][h] = fmaxf(fmaxf(red[r*4], red[r*4+1]),
                                fmaxf(red[r*4+2], red[r*4+3]));
        }
    __syncthreads();
#pragma unroll
    for (int mt=0;mt<2;mt++)
#pragma unroll
        for (int h=0;h<2;h++) {
            float s = 0.f;
#pragma unroll
            for (int nt=0;nt<8;nt++) {
                float e0 = __expf(c[mt][nt][2*h]   - rmax[mt][h]);
                float e1 = __expf(c[mt][nt][2*h+1] - rmax[mt][h]);
                c[mt][nt][2*h]   = e0;
                c[mt][nt][2*h+1] = e1;
                s += e0 + e1;
            }
            s += __shfl_xor_sync(0xffffffffu, s, 1);
            s += __shfl_xor_sync(0xffffffffu, s, 2);
            if (tig == 0) red[(wm + mt*16 + g + h*8)*4 + wcol] = s;
        }
    __syncthreads();
#pragma unroll
    for (int mt=0;mt<2;mt++)
#pragma unroll
        for (int h=0;h<2;h++) {
            int r = wm + mt*16 + g + h*8;
            rinv[mt][h] = 1.f/(red[r*4] + red[r*4+1] + red[r*4+2] + red[r*4+3]);
        }
#pragma unroll
    for (int mt=0;mt<2;mt++)
#pragma unroll
        for (int h=0;h<2;h++) {
            long row = m0 + wm + mt*16 + g + h*8;
#pragma unroll
            for (int nt=0;nt<8;nt++) {
                int col = wn + nt*8 + tig*2;
                *(__half2*)&Cb[row*256 + col] =
                    __floats2half2_rn(c[mt][nt][2*h]   * rinv[mt][h],
                                      c[mt][nt][2*h+1] * rinv[mt][h]);
            }
        }
}

// ---------------------------------------------------------------------------
// Merged PV (unchanged).
// ---------------------------------------------------------------------------
__launch_bounds__(256, 2)
__global__ void pv_h(const __half* __restrict__ P, const __half* __restrict__ xT,
                     float* __restrict__ tstep, __half* __restrict__ tstep_h)
{
    extern __shared__ uint32_t smp[];
    const int kvtab[6] = {1,2,0,2,0,1};
    int z = blockIdx.z;
    int qq = z>>6, b = z&63;
    float* Cb = tstep + (long)qq*128 + (long)b*Ss*384;
    __half* Ch = tstep_h + (long)qq*128 + (long)b*Ss*384;

    int m0 = blockIdx.y*128;
    int tid = threadIdx.x;
    int warp = tid>>5, lane = tid&31;
    int g = lane>>2, tig = lane&3;
    int wm = (warp&1)*64, wn = (warp>>1)*32;

    float c[4][4][4];
#pragma unroll
    for (int mt=0;mt<4;mt++)
#pragma unroll
        for (int nt=0;nt<4;nt++)
#pragma unroll
            for (int i=0;i<4;i++) c[mt][nt][i]=0.f;

    int lrow = tid>>1;
    int lseg = (tid&1)*8;

    auto load_tile = [&](int st, int gk) {
        int p = 2*qq + (gk>>3);
        int k0 = (gk&7)*32;
        const __half* ar = P + ((long)p*64 + b)*(long)Ss*Ss + (long)(m0+lrow)*Ss + k0;
        const __half* br = xT + ((long)kvtab[p]*64 + b)*128l*Ss + (long)lrow*Ss + k0;
        uint32_t* As = smp + st*HSTG;
        uint32_t* Bs = As + HA_WORDS;
        cpa16(s2u(&As[lrow*HSTR + lseg]),     ar + lseg*2,     16);
        cpa16(s2u(&As[lrow*HSTR + lseg + 4]), ar + lseg*2 + 8, 16);
        cpa16(s2u(&Bs[lrow*HSTR + lseg]),     br + lseg*2,     16);
        cpa16(s2u(&Bs[lrow*HSTR + lseg + 4]), br + lseg*2 + 8, 16);
    };
    auto compute = [&](int st) {
        const uint32_t* As = smp + st*HSTG;
        const uint32_t* Bs = As + HA_WORDS;
#pragma unroll
        for (int ks=0;ks<2;ks++) {
            uint32_t a[4][4], bb[4][2];
#pragma unroll
            for (int mt=0;mt<4;mt++) {
                int base = (wm + mt*16 + g)*HSTR + ks*8 + tig;
                a[mt][0] = As[base];
                a[mt][1] = As[base + 8*HSTR];
                a[mt][2] = As[base + 4];
                a[mt][3] = As[base + 8*HSTR + 4];
            }
#pragma unroll
            for (int nt=0;nt<4;nt++) {
                int base = (wn + nt*8 + g)*HSTR + ks*8 + tig;
                bb[nt][0] = Bs[base];
                bb[nt][1] = Bs[base + 4];
            }
#pragma unroll
            for (int mt=0;mt<4;mt++)
#pragma unroll
                for (int nt=0;nt<4;nt++)
                    mma_f16(c[mt][nt], a[mt], bb[nt]);
        }
    };

    load_tile(0, 0);
    asm volatile("cp.async.commit_group;");
    load_tile(1, 1);
    asm volatile("cp.async.commit_group;");
    for (int gk=0; gk<16; gk++) {
        asm volatile("cp.async.wait_group 1;");
        __syncthreads();
        if (gk+2 < 16) load_tile((gk+2)%3, gk+2);
        asm volatile("cp.async.commit_group;");
        compute(gk%3);
        __syncthreads();
    }

#pragma unroll
    for (int mt=0;mt<4;mt++) {
        long m = m0 + wm + mt*16 + g;
#pragma unroll
        for (int nt=0;nt<4;nt++) {
            int n = wn + nt*8 + tig*2;
            float2 o0 = *(const float2*)&Cb[m*384 + n];
            float2 o1 = *(const float2*)&Cb[(m+8)*384 + n];
            float2 v0, v1;
            v0.x = c[mt][nt][0]+o0.x; v0.y = c[mt][nt][1]+o0.y;
            v1.x = c[mt][nt][2]+o1.x; v1.y = c[mt][nt][3]+o1.y;
            *(float2*)&Cb[m*384 + n] = v0;
            *(float2*)&Cb[(m+8)*384 + n] = v1;
            *(__half2*)&Ch[m*384 + n] = __floats2half2_rn(v0.x, v0.y);
            *(__half2*)&Ch[(m+8)*384 + n] = __floats2half2_rn(v1.x, v1.y);
        }
    }
}

// ---------------------------------------------------------------------------
// biGRU — gate-interleaved (tid = j*4+g), shfl gate exchange, ping-pong h,
// ONE barrier per step. 256 threads, grid 384.
// ---------------------------------------------------------------------------
__launch_bounds__(256, 3)
__global__ void gru_rec(const float* __restrict__ xg_all, const float* __restrict__ Wh,
                        const float* __restrict__ bh, __half* __restrict__ x_h,
                        float* __restrict__ tstep)
{
    int bx = blockIdx.x;
    int m = bx>>7, d = (bx>>6)&1, b = bx&63, md = m*2+d;
    int tid = threadIdx.x;
    int j = tid>>2, g = tid&3;
    bool act = (g < 3);
    int col = g*64 + j;

    ull w2[32];
#pragma unroll
    for (int q=0;q<32;q++)
        w2[q] = act ? pk(Wh[((long)md*64 + 2*q)*192 + col],
                         Wh[((long)md*64 + 2*q+1)*192 + col]) : 0ull;
    float bhj = act ? bh[md*192 + col] : 0.f;

    __shared__ alignas(16) float h_s[2][64];
    uint32_t hsa = s2u(h_s);
    if (tid < 64) h_s[0][tid] = 0.f;
    float h_reg = 0.f;

    const float* xg = xg_all + ((long)md*BS + (long)b*Ss)*192;
    int s0 = d ? (Ss-1) : 0;
    float xg_cur = act ? xg[(long)s0*192 + col] : 0.f;
    __syncthreads();

    for (int t=0;t<Ss;t++) {
        int s = d ? (Ss-1-t) : t;
        int sn = d ? (Ss-2-t) : (t+1);
        sn = sn < 0 ? 0 : (sn > Ss-1 ? Ss-1 : sn);
        float xg_nxt = act ? xg[(long)sn*192 + col] : 0.f;
        uint32_t hb = hsa + (t&1)*256;
        ull a0 = pk(bhj,0.f), a1 = 0ull, a2 = 0ull, a3 = 0ull;
#pragma unroll
        for (int q=0;q<8;q++) {
            ull h0,h1,h2,h3;
            lds2x64(h0,h1, hb + q*32);
            lds2x64(h2,h3, hb + q*32 + 16);
            ffma2(a0,h0,w2[4*q]);   ffma2(a1,h1,w2[4*q+1]);
            ffma2(a2,h2,w2[4*q+2]); ffma2(a3,h3,w2[4*q+3]);
        }
        float2 f0=upk(a0), f1=upk(a1), f2=upk(a2), f3=upk(a3);
        float acc = (f0.x+f0.y)+(f1.x+f1.y)+(f2.x+f2.y)+(f3.x+f3.y);
        float r = 0.f, z = 0.f, n = 0.f;
        if (g==0) r = sigf(acc + xg_cur);
        if (g==1) z = sigf(acc + xg_cur);
        float rv = __shfl_sync(0xffffffffu, r, 0, 4);
        if (g==2) n = tanhfast(xg_cur + rv*acc);
        float nv = __shfl_sync(0xffffffffu, n, 2, 4);
        float zv = __shfl_sync(0xffffffffu, z, 1, 4);
        if (g==0) {
            float hn = (1.f-zv)*nv + zv*h_reg;
            h_reg = hn;
            h_s[(t+1)&1][j] = hn;
            long row = (long)b*Ss + s;
            x_h[((long)m*BS + row)*128 + d*64 + j] = __float2half(hn);
            tstep[row*384 + m*128 + d*64 + j] = hn;
        }
        __syncthreads();
        xg_cur = xg_nxt;
    }
}

// ---------------------------------------------------------------------------
// biLSTM — gate-interleaved (i,f,g,o in lanes 4j..4j+3), shfl exchange,
// ping-pong h, ONE barrier per step. 512 threads.
// ---------------------------------------------------------------------------
__launch_bounds__(512, 1)
__global__ void lstm_rec(const float* __restrict__ xg_all, const float* __restrict__ Wh,
                         const float* __restrict__ bh, __half* __restrict__ sf_h)
{
    extern __shared__ unsigned char smraw[];
    ull*   Wlo2 = (ull*)smraw;                       // [16][512] (k 96..127)
    float* h_s  = (float*)(smraw + 16*512*8);        // [2][128]
    int bx = blockIdx.x, d = bx>>6, b = bx&63;
    int tid = threadIdx.x;
    int j = tid>>2, g = tid&3;                       // gate: 0=i 1=f 2=g 3=o
    int col = g*128 + j;

    const float* Whd = Wh + (long)d*128*512;
    ull w2[48];
#pragma unroll
    for (int q=0;q<48;q++)
        w2[q] = pk(Whd[(long)(2*q)*512 + col], Whd[(long)(2*q+1)*512 + col]);
    for (int q=0;q<16;q++)
        Wlo2[q*512 + tid] = pk(Whd[(long)(96+2*q)*512 + col], Whd[(long)(97+2*q)*512 + col]);
    float bhj = bh[d*512 + col];
    float cst = 0.f;
    if (tid < 128) h_s[tid] = 0.f;
    uint32_t hsa = s2u(h_s);

    const float* xg = xg_all + ((long)d*BS + (long)b*Ss)*512;
    int s0 = d ? (Ss-1) : 0;
    float xg_cur = xg[(long)s0*512 + col];
    __syncthreads();

    for (int t=0;t<Ss;t++) {
        int s = d ? (Ss-1-t) : t;
        int sn = d ? (Ss-2-t) : (t+1);
        sn = sn < 0 ? 0 : (sn > Ss-1 ? Ss-1 : sn);
        float xg_nxt = xg[(long)sn*512 + col];
        uint32_t hb = hsa + (t&1)*512;
        ull a0 = pk(bhj,0.f), a1 = 0ull, a2 = 0ull, a3 = 0ull;
#pragma unroll
        for (int q=0;q<12;q++) {
            ull h0,h1,h2,h3;
            lds2x64(h0,h1, hb + q*32);
            lds2x64(h2,h3, hb + q*32 + 16);
            ffma2(a0,h0,w2[4*q]);   ffma2(a1,h1,w2[4*q+1]);
            ffma2(a2,h2,w2[4*q+2]); ffma2(a3,h3,w2[4*q+3]);
        }
#pragma unroll
        for (int q=0;q<8;q++) {
            ull h0,h1; lds2x64(h0,h1, hb + 384 + q*16);
            ffma2(a0,h0, Wlo2[(2*q)*512 + tid]);
            ffma2(a1,h1, Wlo2[(2*q+1)*512 + tid]);
        }
        float2 f0=upk(a0), f1=upk(a1), f2=upk(a2), f3=upk(a3);
        float pre = (f0.x+f0.y)+(f1.x+f1.y)+(f2.x+f2.y)+(f3.x+f3.y) + xg_cur;
        float fv = __shfl_sync(0xffffffffu, pre, 1, 4);
        float gv = __shfl_sync(0xffffffffu, pre, 2, 4);
        float ov = __shfl_sync(0xffffffffu, pre, 3, 4);
        if (g==0) {
            cst = sigf(fv)*cst + sigf(pre)*tanhfast(gv);
            float h = sigf(ov)*tanhfast(cst);
            h_s[((t+1)&1)*128 + j] = h;
            sf_h[((long)b*Ss + s)*256 + d*128 + j] = __float2half(h);
        }
        __syncthreads();
        xg_cur = xg_nxt;
    }
}

// ---------------------------------------------------------------------------
// RGN — gate-interleaved (r,z,n in lanes 4j..4j+2), shfl exchange, ping-pong h,
// ONE barrier per step. 512 threads, 132 KB smem (weights k 64..127).
// ---------------------------------------------------------------------------
__launch_bounds__(512, 1)
__global__ void rgn_rec(const float* __restrict__ xg_all, const float* __restrict__ Wh,
                        const float* __restrict__ state0, const float* __restrict__ state1,
                        float* __restrict__ outbuf)
{
    extern __shared__ unsigned char smraw[];
    ull*   Wlo2 = (ull*)smraw;                       // [32][512] (k 64..127)
    float* h_s  = (float*)(smraw + 32*512*8);        // [2][128]
    int bx = blockIdx.x, kk = bx>>6, b = bx&63;
    int tid = threadIdx.x;
    int j = tid>>2, g = tid&3;
    bool act = (g < 3);
    int col = g*128 + j;

    const float* Whd = Wh + (long)kk*128*384;
    ull w2[32];
#pragma unroll
    for (int q=0;q<32;q++)
        w2[q] = act ? pk(Whd[(long)(2*q)*384 + col], Whd[(long)(2*q+1)*384 + col]) : 0ull;
    for (int q=0;q<32;q++)
        Wlo2[q*512 + tid] = act ? pk(Whd[(long)(64+2*q)*384 + col],
                                     Whd[(long)(65+2*q)*384 + col]) : 0ull;
    float h_reg = 0.f;
    if (tid < 128) {
        float v = (kk==0?state0:state1)[b*128 + tid];
        h_s[tid] = v;
    }
    if (g==0) h_reg = (kk==0?state0:state1)[b*128 + j];
    uint32_t hsa = s2u(h_s);

    const float* xg = xg_all + ((long)kk*BS + (long)b*Ss)*384;
    int s0 = kk ? (Ss-1) : 0;
    float xg_cur = act ? xg[(long)s0*384 + col] : 0.f;
    __syncthreads();

    for (int t=0;t<Ss;t++) {
        int sn = kk ? (Ss-2-t) : (t+1);
        sn = sn < 0 ? 0 : (sn > Ss-1 ? Ss-1 : sn);
        float xg_nxt = act ? xg[(long)sn*384 + col] : 0.f;
        uint32_t hb = hsa + (t&1)*512;
        ull a0 = 0ull, a1 = 0ull, a2 = 0ull, a3 = 0ull;
#pragma unroll
        for (int q=0;q<8;q++) {
            ull h0,h1,h2,h3;
            lds2x64(h0,h1, hb + q*32);
            lds2x64(h2,h3, hb + q*32 + 16);
            ffma2(a0,h0,w2[4*q]);   ffma2(a1,h1,w2[4*q+1]);
            ffma2(a2,h2,w2[4*q+2]); ffma2(a3,h3,w2[4*q+3]);
        }
#pragma unroll
        for (int q=0;q<16;q++) {
            ull h0,h1; lds2x64(h0,h1, hb + 256 + q*16);
            ffma2(a0,h0, Wlo2[(2*q)*512 + tid]);
            ffma2(a1,h1, Wlo2[(2*q+1)*512 + tid]);
        }
        float2 f0=upk(a0), f1=upk(a1), f2=upk(a2), f3=upk(a3);
        float acc = (f0.x+f0.y)+(f1.x+f1.y)+(f2.x+f2.y)+(f3.x+f3.y);
        float r = 0.f, z = 0.f, n = 0.f;
        if (g==0) r = sigf(acc + xg_cur);
        if (g==1) z = sigf(acc + xg_cur);
        float rv = __shfl_sync(0xffffffffu, r, 0, 4);
        if (g==2) n = tanhfast(xg_cur + rv*acc);
        float nv = __shfl_sync(0xffffffffu, n, 2, 4);
        float zv = __shfl_sync(0xffffffffu, z, 1, 4);
        if (g==0) {
            h_reg = (1.f-zv)*nv + zv*h_reg;
            h_s[((t+1)&1)*128 + j] = h_reg;
        }
        __syncthreads();
        xg_cur = xg_nxt;
    }
    if (g==0) outbuf[((long)kk*64 + b)*128 + j] = h_reg;
}

__launch_bounds__(32)
__global__ void final_fc(const float* __restrict__ outbuf,
                         const float* __restrict__ fc1W, const float* __restrict__ fc1b,
                         const float* __restrict__ fc2W, const float* __restrict__ fc2b,
                         float* __restrict__ out)
{
    int b = blockIdx.x, t = threadIdx.x;
    float acc = fc1b[t];
    for (int k=0;k<128;k++) {
        float x = outbuf[b*128+k] + outbuf[64*128 + b*128 + k];
        acc += x * fc1W[k*32 + t];
    }
    float h = acc > 0.f ? acc : 0.01f*acc;
    float v = h * fc2W[t];
#pragma unroll
    for (int o=16;o;o>>=1) v += __shfl_xor_sync(0xffffffffu, v, o);
    if (t==0) out[b] = v + fc2b[0];
}

extern "C" void kernel_launch(void* const* d_in, const int* in_sizes, int n_in,
                              void* d_out, int out_size)
{
    (void)in_sizes; (void)n_in; (void)out_size;
    const int*   sentences = (const int*)  d_in[0];
    const float* acoustic  = (const float*)d_in[1];
    const float* video     = (const float*)d_in[2];
    const float* state0    = (const float*)d_in[3];
    const float* state1    = (const float*)d_in[4];
    const float* emb       = (const float*)d_in[5];
    const float* proj_l_W  = (const float*)d_in[6];
    const float* proj_l_b  = (const float*)d_in[7];
    const float* proj_a_W  = (const float*)d_in[8];
    const float* proj_a_b  = (const float*)d_in[9];
    const float* proj_v_W  = (const float*)d_in[10];
    const float* proj_v_b  = (const float*)d_in[11];
    const float* gru_Wi    = (const float*)d_in[12];
    const float* gru_Wh    = (const float*)d_in[13];
    const float* gru_bi    = (const float*)d_in[14];
    const float* gru_bh    = (const float*)d_in[15];
    const float* lstm_Wi   = (const float*)d_in[16];
    const float* lstm_Wh   = (const float*)d_in[17];
    const float* lstm_bi   = (const float*)d_in[18];
    const float* lstm_bh   = (const float*)d_in[19];
    const float* rgn_Wx    = (const float*)d_in[20];
    const float* rgn_Wh    = (const float*)d_in[21];
    const float* rgn_b     = (const float*)d_in[22];
    const float* fc1_W     = (const float*)d_in[23];
    const float* fc1_b     = (const float*)d_in[24];
    const float* fc2_W     = (const float*)d_in[25];
    const float* fc2_b     = (const float*)d_in[26];
    float* out = (float*)d_out;

    float *xg_gru,*tstep,*xg_lstm,*xg_rgn,*rgn_out;
    __half *seq_h,*x_h,*xT_h,*P_h,*tstep_h,*sf_h,*WT_h,*ac_h,*vid_h,*emb_h;
    cudaGetSymbolAddress((void**)&xg_gru, g_xg_gru);
    cudaGetSymbolAddress((void**)&tstep, g_tstep);
    cudaGetSymbolAddress((void**)&xg_lstm, g_xg_lstm);
    cudaGetSymbolAddress((void**)&xg_rgn, g_xg_rgn);
    cudaGetSymbolAddress((void**)&rgn_out, g_rgn_out);
    cudaGetSymbolAddress((void**)&seq_h, g_seq_h);
    cudaGetSymbolAddress((void**)&x_h, g_x_h);
    cudaGetSymbolAddress((void**)&xT_h, g_xT_h);
    cudaGetSymbolAddress((void**)&P_h, g_P_h);
    cudaGetSymbolAddress((void**)&tstep_h, g_tstep_h);
    cudaGetSymbolAddress((void**)&sf_h, g_sf_h);
    cudaGetSymbolAddress((void**)&WT_h, g_WT_h);
    cudaGetSymbolAddress((void**)&ac_h, g_ac_h);
    cudaGetSymbolAddress((void**)&vid_h, g_vid_h);
    cudaGetSymbolAddress((void**)&emb_h, g_emb_h);
    __half* gruT  = WT_h;
    __half* lstmT = gruT + 6*192*128;
    __half* rgnT  = lstmT + 2l*512*384;

    const size_t shm_h    = 3u*HSTG*4u;
    const size_t shm_qk   = 3u*Q64_STG*4u;
    const size_t shm_lstm = 16*512*8 + 2*128*4 + 256;
    const size_t shm_rgn  = 32*512*8 + 2*128*4 + 256;
    cudaFuncSetAttribute(gemm_h<0,0>, cudaFuncAttributeMaxDynamicSharedMemorySize, (int)shm_h);
    cudaFuncSetAttribute(gemm_h<1,0>, cudaFuncAttributeMaxDynamicSharedMemorySize, (int)shm_h);
    cudaFuncSetAttribute(proj3_h, cudaFuncAttributeMaxDynamicSharedMemorySize, (int)shm_h);
    cudaFuncSetAttribute(qk_xt, cudaFuncAttributeMaxDynamicSharedMemorySize, (int)shm_qk);
    cudaFuncSetAttribute(pv_h, cudaFuncAttributeMaxDynamicSharedMemorySize, (int)shm_h);
    cudaFuncSetAttribute(lstm_rec, cudaFuncAttributeMaxDynamicSharedMemorySize, (int)shm_lstm);
    cudaFuncSetAttribute(rgn_rec,  cudaFuncAttributeMaxDynamicSharedMemorySize, (int)shm_rgn);

    // 1. prep (one launch)
    prep_all<<<PREP_WT + PREP_EMB + PREP_CONV, dim3(32,8)>>>(
        gru_Wi, lstm_Wi, rgn_Wx, proj_a_W, proj_v_W, proj_l_W, WT_h,
        acoustic, ac_h, video, vid_h, emb, emb_h);

    // 2. fat modality projections
    proj3_h<<<dim3(1, BS/128, 3), 256, shm_h>>>(
        emb_h, ac_h, vid_h, WT_h, proj_l_b, proj_a_b, proj_v_b, sentences, seq_h);

    // 3. GRU input projections (z=6)
    gemm_h<1,0><<<dim3(2, BS/128, 6), 256, shm_h>>>(
        seq_h, gruT, gru_bi, xg_gru, BS, 192, 128,
        (long)BS*DH, 192l*128, 192, (long)BS*192, 192);

    // 4. biGRU
    gru_rec<<<3*2*64, 256>>>(xg_gru, gru_Wh, gru_bh, x_h, tstep);

    // 5. fat qk+softmax + x transpose
    const float scale = 0.08838834764831845f;
    qk_xt<<<2304, 256, shm_qk>>>(x_h, P_h, xT_h, scale);

    // 6. merged PV
    pv_h<<<dim3(1, 2, 192), 256, shm_h>>>(P_h, xT_h, tstep, tstep_h);

    // 7. LSTM input projections (z=2)
    gemm_h<0,0><<<dim3(4, BS/128, 2), 256, shm_h>>>(
        tstep_h, lstmT, lstm_bi, xg_lstm, BS, 512, 384,
        0, 512l*384, 512, (long)BS*512, 512);

    // 8. biLSTM
    lstm_rec<<<2*64, 512, shm_lstm>>>(xg_lstm, lstm_Wh, lstm_bh, sf_h);

    // 9. RGN input projections (z=2)
    gemm_h<0,0><<<dim3(3, BS/128, 2), 256, shm_h>>>(
        sf_h, rgnT, rgn_b, xg_rgn, BS, 384, 256,
        0, 384l*256, 384, (long)BS*384, 384);

    // 10. RGN
    rgn_rec<<<2*64, 512, shm_rgn>>>(xg_rgn, rgn_Wh, state0, state1, rgn_out);

    // 11. final FC
    final_fc<<<Bb, 32>>>(rgn_out, fc1_W, fc1_b, fc2_W, fc2_b, out);
}

// round 13
// speedup vs baseline: 1.3183x; 1.3183x over previous
#include <cuda_runtime.h>
#include <cuda_fp16.h>
#include <math.h>
#include <stdint.h>

#define Bb 64
#define Ss 256
#define BS (Bb*Ss)
#define DL 300
#define DA 74
#define DV 35
#define DH 128

// fp32 scratch
__device__ float g_xg_gru[6u*BS*192];
__device__ float g_xg_lstm[2u*BS*512];
__device__ float g_xg_rgn[2u*BS*384];
__device__ float g_rgn_out[2u*Bb*128];
// fp16 scratch
__device__ __half g_seq_h[3u*BS*DH];
__device__ __half g_x_h[3u*BS*DH];
__device__ __half g_xT_h[3u*(unsigned)Bb*128*Ss];
__device__ __half g_P_h[6u*(unsigned)Bb*Ss*Ss];
__device__ __half g_tstep_h[(unsigned)BS*384];
__device__ __half g_sf_h[(unsigned)BS*256];
__device__ __half g_ac_h[(unsigned)BS*96];
__device__ __half g_vid_h[(unsigned)BS*64];
__device__ __half g_WT_h[757760];

typedef unsigned long long ull;

__device__ __forceinline__ uint32_t s2u(const void* p) {
    return (uint32_t)__cvta_generic_to_shared(p);
}
__device__ __forceinline__ void cpa16(uint32_t dst, const void* src, int bytes) {
    asm volatile("cp.async.cg.shared.global [%0], [%1], 16, %2;"
                 :: "r"(dst), "l"(src), "r"(bytes));
}
__device__ __forceinline__ void mma_tf32(float c[4], const uint32_t a[4], const uint32_t b[2]) {
    asm volatile(
        "mma.sync.aligned.m16n8k8.row.col.f32.tf32.tf32.f32 "
        "{%0,%1,%2,%3}, {%4,%5,%6,%7}, {%8,%9}, {%0,%1,%2,%3};"
        : "+f"(c[0]), "+f"(c[1]), "+f"(c[2]), "+f"(c[3])
        : "r"(a[0]), "r"(a[1]), "r"(a[2]), "r"(a[3]), "r"(b[0]), "r"(b[1]));
}
__device__ __forceinline__ void mma_f16(float c[4], const uint32_t a[4], const uint32_t b[2]) {
    asm volatile(
        "mma.sync.aligned.m16n8k16.row.col.f32.f16.f16.f32 "
        "{%0,%1,%2,%3}, {%4,%5,%6,%7}, {%8,%9}, {%0,%1,%2,%3};"
        : "+f"(c[0]), "+f"(c[1]), "+f"(c[2]), "+f"(c[3])
        : "r"(a[0]), "r"(a[1]), "r"(a[2]), "r"(a[3]), "r"(b[0]), "r"(b[1]));
}
__device__ __forceinline__ ull pk(float x, float y) {
    ull r; asm("mov.b64 %0,{%1,%2};" : "=l"(r) : "f"(x), "f"(y)); return r;
}
__device__ __forceinline__ float2 upk(ull v) {
    float2 f; asm("mov.b64 {%0,%1},%2;" : "=f"(f.x), "=f"(f.y) : "l"(v)); return f;
}
__device__ __forceinline__ void ffma2(ull &d, ull a, ull b) {
    asm volatile("fma.rn.f32x2 %0, %1, %2, %0;" : "+l"(d) : "l"(a), "l"(b));
}
__device__ __forceinline__ void lds2x64(ull &a, ull &b, uint32_t addr) {
    asm volatile("ld.shared.v2.b64 {%0,%1},[%2];" : "=l"(a), "=l"(b) : "r"(addr));
}
__device__ __forceinline__ float sigf(float x) { return 1.f/(1.f + __expf(-x)); }
__device__ __forceinline__ float tanhfast(float x) {
    float y; asm("tanh.approx.f32 %0,%1;" : "=f"(y) : "f"(x)); return y;
}

// ---------------------------------------------------------------------------
// ALL weight transposes in one launch (740 tiles).
// ---------------------------------------------------------------------------
__global__ void wtrans_all(const float* __restrict__ gru_Wi,
                           const float* __restrict__ lstm_Wi,
                           const float* __restrict__ rgn_Wx,
                           const float* __restrict__ pa,
                           const float* __restrict__ pv,
                           __half* __restrict__ WT)
{
    __half* gruT  = WT;
    __half* lstmT = gruT + 6*192*128;
    __half* rgnT  = lstmT + 2l*512*384;
    __half* projaT = rgnT + 2l*384*256;
    __half* projvT = projaT + 128*96;

    int bid = blockIdx.x;
    const float* in; __half* out;
    int K, N, KP, k0, n0;
    if (bid < 144) {
        int z = bid/24, rem = bid%24;
        K = 128; N = 192; KP = 128;
        k0 = (rem%4)*32; n0 = (rem/4)*32;
        in = gru_Wi + (long)z*K*N; out = gruT + (long)z*N*KP;
    } else if (bid < 528) {
        int b2 = bid-144; int z = b2/192, rem = b2%192;
        K = 384; N = 512; KP = 384;
        k0 = (rem%12)*32; n0 = (rem/12)*32;
        in = lstm_Wi + (long)z*K*N; out = lstmT + (long)z*N*KP;
    } else if (bid < 720) {
        int b2 = bid-528; int z = b2/96, rem = b2%96;
        K = 256; N = 384; KP = 256;
        k0 = (rem%8)*32; n0 = (rem/8)*32;
        in = rgn_Wx + (long)z*K*N; out = rgnT + (long)z*N*KP;
    } else if (bid < 732) {
        int rem = bid-720;
        K = 74; N = 128; KP = 96;
        k0 = (rem%3)*32; n0 = (rem/3)*32;
        in = pa; out = projaT;
    } else {
        int rem = bid-732;
        K = 35; N = 128; KP = 64;
        k0 = (rem%2)*32; n0 = (rem/2)*32;
        in = pv; out = projvT;
    }

    __shared__ float t[32][33];
    int tx = threadIdx.x, ty = threadIdx.y;
#pragma unroll
    for (int i=0;i<32;i+=8) {
        int k = k0+ty+i, n = n0+tx;
        t[ty+i][tx] = (k<K && n<N) ? in[(long)k*N+n] : 0.f;
    }
    __syncthreads();
#pragma unroll
    for (int i=0;i<32;i+=8) {
        int n = n0+ty+i, k = k0+tx;
        if (n<N && k<KP) out[(long)n*KP+k] = __float2half(t[tx][ty+i]);
    }
}

// both input conversions in one launch
__global__ void conv2(const float* __restrict__ ac, __half* __restrict__ ach,
                      const float* __restrict__ vid, __half* __restrict__ vidh)
{
    const long TOT_A = (long)BS*96;
    const long TOT_V = (long)BS*64;
    for (long i = (long)blockIdx.x*blockDim.x + threadIdx.x; i < TOT_A + TOT_V;
         i += (long)gridDim.x*blockDim.x) {
        if (i < TOT_A) {
            long row = i/96; int k = (int)(i - row*96);
            ach[i] = (k<74) ? __float2half(ac[row*74 + k]) : __float2half(0.f);
        } else {
            long j = i - TOT_A;
            long row = j/64; int k = (int)(j - row*64);
            vidh[j] = (k<35) ? __float2half(vid[row*35 + k]) : __float2half(0.f);
        }
    }
}

// ---------------------------------------------------------------------------
// x_h -> xT_h transpose
// ---------------------------------------------------------------------------
__global__ void xtrans(const __half* __restrict__ xin, __half* __restrict__ xout)
{
    __shared__ __half sm[64][130];
    int mb = blockIdx.x;
    int m = mb>>6, b = mb&63;
    int s0 = blockIdx.y*64;
    int tid = threadIdx.x;
    const __half* src = xin + ((long)m*BS + (long)b*Ss + s0)*128;
#pragma unroll
    for (int i=0;i<32;i++) {
        int idx = tid + i*256;
        int s = idx>>7, d = idx&127;
        sm[s][d] = src[(long)s*128 + d];
    }
    __syncthreads();
    __half* dst = xout + (long)mb*128*Ss;
#pragma unroll
    for (int i=0;i<32;i++) {
        int idx = tid + i*256;
        int d = idx>>6, ss = idx&63;
        dst[(long)d*Ss + s0 + ss] = sm[ss][d];
    }
}

// ---------------------------------------------------------------------------
// TF32 GEMM (embedding projection only). fp16 output, 3-stage pipeline.
// ---------------------------------------------------------------------------
#define ASTR 36
#define BSTR 136
#define AWORDS (128*ASTR)
#define STG_WORDS (2*AWORDS)

__launch_bounds__(256, 2)
__global__ void gemm_tf(const float* __restrict__ A, const float* __restrict__ W,
                        const float* __restrict__ bias, __half* __restrict__ C,
                        int M, int N, int K, int ldc,
                        const int* __restrict__ gidx)
{
    extern __shared__ uint32_t smp[];
    int m0 = blockIdx.y*128, n0 = blockIdx.x*128;
    int tid = threadIdx.x;
    int warp = tid>>5, lane = tid&31;
    int g = lane>>2, tig = lane&3;
    int wm = (warp&1)*64, wn = (warp>>1)*32;

    float c[4][4][4];
#pragma unroll
    for (int mt=0;mt<4;mt++)
#pragma unroll
        for (int nt=0;nt<4;nt++)
#pragma unroll
            for (int i=0;i<4;i++) c[mt][nt][i]=0.f;

    int lrow = tid>>3;
    int akq  = (tid&7)*4;
    const float* arp[4];
#pragma unroll
    for (int p=0;p<4;p++)
        arp[p] = A + (long)gidx[m0 + lrow + p*32]*(long)K;
    int bnk = tid>>5;
    int bn4 = (tid&31)*4;

    auto load_tile = [&](int st, int k0) {
        uint32_t* As = smp + st*STG_WORDS;
        uint32_t* Bs = As + AWORDS;
#pragma unroll
        for (int p=0;p<4;p++) {
            int gk = k0 + akq;
            int bytes = (K - gk)*4; bytes = bytes<0?0:(bytes>16?16:bytes);
            const float* src = bytes ? (arp[p] + gk) : A;
            cpa16(s2u(&As[(lrow + p*32)*ASTR + akq]), src, bytes);
        }
#pragma unroll
        for (int p=0;p<4;p++) {
            int k = bnk + p*8;
            int ok = ((k0+k) < K) && ((n0+bn4) < N);
            const float* src = ok ? (W + (long)(k0+k)*N + n0 + bn4) : W;
            cpa16(s2u(&Bs[k*BSTR + bn4]), src, ok ? 16 : 0);
        }
    };
    auto compute = [&](int st) {
        const uint32_t* As = smp + st*STG_WORDS;
        const uint32_t* Bs = As + AWORDS;
#pragma unroll
        for (int ks=0;ks<4;ks++) {
            uint32_t a[4][4], b[4][2];
#pragma unroll
            for (int mt=0;mt<4;mt++) {
                int base = (wm + mt*16 + g)*ASTR + ks*8 + tig;
                a[mt][0] = As[base];
                a[mt][1] = As[base + 8*ASTR];
                a[mt][2] = As[base + 4];
                a[mt][3] = As[base + 8*ASTR + 4];
            }
#pragma unroll
            for (int nt=0;nt<4;nt++) {
                int base = (ks*8 + tig)*BSTR + wn + nt*8 + g;
                b[nt][0] = Bs[base];
                b[nt][1] = Bs[base + 4*BSTR];
            }
#pragma unroll
            for (int mt=0;mt<4;mt++)
#pragma unroll
                for (int nt=0;nt<4;nt++)
                    mma_tf32(c[mt][nt], a[mt], b[nt]);
        }
    };

    int ktn = (K+31)>>5;
    load_tile(0, 0);
    asm volatile("cp.async.commit_group;");
    if (ktn > 1) load_tile(1, 32);
    asm volatile("cp.async.commit_group;");
    for (int kt=0; kt<ktn; kt++) {
        asm volatile("cp.async.wait_group 1;");
        __syncthreads();
        if (kt+2 < ktn) load_tile((kt+2)%3, (kt+2)*32);
        asm volatile("cp.async.commit_group;");
        compute(kt%3);
        __syncthreads();
    }

#pragma unroll
    for (int mt=0;mt<4;mt++) {
        long m = m0 + wm + mt*16 + g;
#pragma unroll
        for (int nt=0;nt<4;nt++) {
            int n = n0 + wn + nt*8 + tig*2;
            if (n < N) {
                float bx = bias[n], by = bias[n+1];
                *(__half2*)&C[m*ldc + n] = __floats2half2_rn(c[mt][nt][0]+bx, c[mt][nt][1]+by);
                *(__half2*)&C[(m+8)*ldc + n] = __floats2half2_rn(c[mt][nt][2]+bx, c[mt][nt][3]+by);
            }
        }
    }
}

// ---------------------------------------------------------------------------
// FP16 NT GEMM. OUT16: 0 = fp32 C, 1 = fp16 C. MODE 1: A shared per 2 z.
// ---------------------------------------------------------------------------
#define HSTR 20
#define HA_WORDS (128*HSTR)
#define HSTG (2*HA_WORDS)

template<int MODE, int OUT16>
__launch_bounds__(256, 2)
__global__ void gemm_h(const __half* __restrict__ A, const __half* __restrict__ B,
                       const float* __restrict__ bias, void* __restrict__ Cv,
                       int M, int N, int K,
                       long sA, long sB, long sBias, long sC, int ldc)
{
    extern __shared__ uint32_t smp[];
    int z = blockIdx.z;
    const __half* Ab = A + (MODE==1 ? (long)(z>>1)*sA : (long)z*sA);
    const __half* Bp = B + (long)z*sB;
    const float* bp = bias + (long)z*sBias;

    int m0 = blockIdx.y*128, n0 = blockIdx.x*128;
    int tid = threadIdx.x;
    int warp = tid>>5, lane = tid&31;
    int g = lane>>2, tig = lane&3;
    int wm = (warp&1)*64, wn = (warp>>1)*32;

    float c[4][4][4];
#pragma unroll
    for (int mt=0;mt<4;mt++)
#pragma unroll
        for (int nt=0;nt<4;nt++)
#pragma unroll
            for (int i=0;i<4;i++) c[mt][nt][i]=0.f;

    int lrow = tid>>1;
    int lseg = (tid&1)*8;
    const __half* arow = Ab + (long)(m0+lrow)*K;
    const __half* brow = Bp + (long)(n0+lrow)*K;
    bool bok = (n0+lrow) < N;

    auto load_tile = [&](int st, int k0) {
        uint32_t* As = smp + st*HSTG;
        uint32_t* Bs = As + HA_WORDS;
        cpa16(s2u(&As[lrow*HSTR + lseg]),     arow + k0 + lseg*2,     16);
        cpa16(s2u(&As[lrow*HSTR + lseg + 4]), arow + k0 + lseg*2 + 8, 16);
        cpa16(s2u(&Bs[lrow*HSTR + lseg]),     bok ? (brow + k0 + lseg*2)     : brow, bok?16:0);
        cpa16(s2u(&Bs[lrow*HSTR + lseg + 4]), bok ? (brow + k0 + lseg*2 + 8) : brow, bok?16:0);
    };
    auto compute = [&](int st) {
        const uint32_t* As = smp + st*HSTG;
        const uint32_t* Bs = As + HA_WORDS;
#pragma unroll
        for (int ks=0;ks<2;ks++) {
            uint32_t a[4][4], b[4][2];
#pragma unroll
            for (int mt=0;mt<4;mt++) {
                int base = (wm + mt*16 + g)*HSTR + ks*8 + tig;
                a[mt][0] = As[base];
                a[mt][1] = As[base + 8*HSTR];
                a[mt][2] = As[base + 4];
                a[mt][3] = As[base + 8*HSTR + 4];
            }
#pragma unroll
            for (int nt=0;nt<4;nt++) {
                int base = (wn + nt*8 + g)*HSTR + ks*8 + tig;
                b[nt][0] = Bs[base];
                b[nt][1] = Bs[base + 4];
            }
#pragma unroll
            for (int mt=0;mt<4;mt++)
#pragma unroll
                for (int nt=0;nt<4;nt++)
                    mma_f16(c[mt][nt], a[mt], b[nt]);
        }
    };

    int ktn = K>>5;
    load_tile(0, 0);
    asm volatile("cp.async.commit_group;");
    if (ktn > 1) load_tile(1, 32);
    asm volatile("cp.async.commit_group;");
    for (int kt=0; kt<ktn; kt++) {
        asm volatile("cp.async.wait_group 1;");
        __syncthreads();
        if (kt+2 < ktn) load_tile((kt+2)%3, (kt+2)*32);
        asm volatile("cp.async.commit_group;");
        compute(kt%3);
        __syncthreads();
    }

#pragma unroll
    for (int mt=0;mt<4;mt++) {
        long m = m0 + wm + mt*16 + g;
#pragma unroll
        for (int nt=0;nt<4;nt++) {
            int n = n0 + wn + nt*8 + tig*2;
            if (n < N) {
                float bx = bp[n], by = bp[n+1];
                float v00 = c[mt][nt][0]+bx, v01 = c[mt][nt][1]+by;
                float v10 = c[mt][nt][2]+bx, v11 = c[mt][nt][3]+by;
                if (OUT16) {
                    __half* Cb = (__half*)Cv + (long)z*sC;
                    *(__half2*)&Cb[m*ldc + n] = __floats2half2_rn(v00, v01);
                    *(__half2*)&Cb[(m+8)*ldc + n] = __floats2half2_rn(v10, v11);
                } else {
                    float* Cb = (float*)Cv + (long)z*sC;
                    float2 v0; v0.x = v00; v0.y = v01;
                    float2 v1; v1.x = v10; v1.y = v11;
                    *(float2*)&Cb[m*ldc + n] = v0;
                    *(float2*)&Cb[(m+8)*ldc + n] = v1;
                }
            }
        }
    }
}

// ---------------------------------------------------------------------------
// Fused fp16 QK^T + softmax -> P_h. Block tile 64x256, warp tile 32x64,
// 2 CTAs/SM. grid (1, 4, 384).
// ---------------------------------------------------------------------------
#define QA64 (64*HSTR)
#define QB256 (256*HSTR)
#define Q64_STG (QA64 + QB256)

__launch_bounds__(256, 2)
__global__ void qk_softmax_h(const __half* __restrict__ x, __half* __restrict__ P,
                             float scale)
{
    extern __shared__ uint32_t smp[];
    const int qtab[6]  = {0,0,1,1,2,2};
    const int kvtab[6] = {1,2,0,2,0,1};

    int z = blockIdx.z;
    int p = z>>6, b = z&63;
    const __half* Ab = x + ((long)qtab[p]*BS + (long)b*Ss)*128;
    const __half* Bp = x + ((long)kvtab[p]*BS + (long)b*Ss)*128;
    __half* Cb = P + (long)z*Ss*Ss;
    int m0 = blockIdx.y*64;
    int tid = threadIdx.x;
    int warp = tid>>5, lane = tid&31;
    int g = lane>>2, tig = lane&3;
    int wm = (warp&1)*32, wn = (warp>>1)*64;

    float c[2][8][4];
#pragma unroll
    for (int mt=0;mt<2;mt++)
#pragma unroll
        for (int nt=0;nt<8;nt++)
#pragma unroll
            for (int i=0;i<4;i++) c[mt][nt][i]=0.f;

    int arow_i = tid>>2;
    int aseg = (tid&3)*4;
    const __half* arow = Ab + (long)(m0+arow_i)*128;
    const __half* brow = Bp + (long)tid*128;

    auto load_tile = [&](int st, int k0) {
        uint32_t* As = smp + st*Q64_STG;
        uint32_t* Bs = As + QA64;
        cpa16(s2u(&As[arow_i*HSTR + aseg]), arow + k0 + aseg*2, 16);
#pragma unroll
        for (int h=0;h<4;h++)
            cpa16(s2u(&Bs[tid*HSTR + h*4]), brow + k0 + h*8, 16);
    };
    auto compute = [&](int st) {
        const uint32_t* As = smp + st*Q64_STG;
        const uint32_t* Bs = As + QA64;
#pragma unroll
        for (int ks=0;ks<2;ks++) {
            uint32_t a[2][4], bb[8][2];
#pragma unroll
            for (int mt=0;mt<2;mt++) {
                int base = (wm + mt*16 + g)*HSTR + ks*8 + tig;
                a[mt][0] = As[base];
                a[mt][1] = As[base + 8*HSTR];
                a[mt][2] = As[base + 4];
                a[mt][3] = As[base + 8*HSTR + 4];
            }
#pragma unroll
            for (int nt=0;nt<8;nt++) {
                int base = (wn + nt*8 + g)*HSTR + ks*8 + tig;
                bb[nt][0] = Bs[base];
                bb[nt][1] = Bs[base + 4];
            }
#pragma unroll
            for (int mt=0;mt<2;mt++)
#pragma unroll
                for (int nt=0;nt<8;nt++)
                    mma_f16(c[mt][nt], a[mt], bb[nt]);
        }
    };

    load_tile(0, 0);
    asm volatile("cp.async.commit_group;");
    load_tile(1, 32);
    asm volatile("cp.async.commit_group;");
    for (int kt=0; kt<4; kt++) {
        asm volatile("cp.async.wait_group 1;");
        __syncthreads();
        if (kt+2 < 4) load_tile((kt+2)%3, (kt+2)*32);
        asm volatile("cp.async.commit_group;");
        compute(kt%3);
        __syncthreads();
    }

#pragma unroll
    for (int mt=0;mt<2;mt++)
#pragma unroll
        for (int nt=0;nt<8;nt++)
#pragma unroll
            for (int i=0;i<4;i++) c[mt][nt][i] *= scale;

    float* red = (float*)smp;
    int wcol = warp>>1;
    float rmax[2][2], rinv[2][2];

#pragma unroll
    for (int mt=0;mt<2;mt++)
#pragma unroll
        for (int h=0;h<2;h++) {
            float m = -1e30f;
#pragma unroll
            for (int nt=0;nt<8;nt++)
                m = fmaxf(m, fmaxf(c[mt][nt][2*h], c[mt][nt][2*h+1]));
            m = fmaxf(m, __shfl_xor_sync(0xffffffffu, m, 1));
            m = fmaxf(m, __shfl_xor_sync(0xffffffffu, m, 2));
            if (tig == 0) red[(wm + mt*16 + g + h*8)*4 + wcol] = m;
        }
    __syncthreads();
#pragma unroll
    for (int mt=0;mt<2;mt++)
#pragma unroll
        for (int h=0;h<2;h++) {
            int r = wm + mt*16 + g + h*8;
            rmax[mt][h] = fmaxf(fmaxf(red[r*4], red[r*4+1]),
                                fmaxf(red[r*4+2], red[r*4+3]));
        }
    __syncthreads();
#pragma unroll
    for (int mt=0;mt<2;mt++)
#pragma unroll
        for (int h=0;h<2;h++) {
            float s = 0.f;
#pragma unroll
            for (int nt=0;nt<8;nt++) {
                float e0 = __expf(c[mt][nt][2*h]   - rmax[mt][h]);
                float e1 = __expf(c[mt][nt][2*h+1] - rmax[mt][h]);
                c[mt][nt][2*h]   = e0;
                c[mt][nt][2*h+1] = e1;
                s += e0 + e1;
            }
            s += __shfl_xor_sync(0xffffffffu, s, 1);
            s += __shfl_xor_sync(0xffffffffu, s, 2);
            if (tig == 0) red[(wm + mt*16 + g + h*8)*4 + wcol] = s;
        }
    __syncthreads();
#pragma unroll
    for (int mt=0;mt<2;mt++)
#pragma unroll
        for (int h=0;h<2;h++) {
            int r = wm + mt*16 + g + h*8;
            rinv[mt][h] = 1.f/(red[r*4] + red[r*4+1] + red[r*4+2] + red[r*4+3]);
        }
#pragma unroll
    for (int mt=0;mt<2;mt++)
#pragma unroll
        for (int h=0;h<2;h++) {
            long row = m0 + wm + mt*16 + g + h*8;
#pragma unroll
            for (int nt=0;nt<8;nt++) {
                int col = wn + nt*8 + tig*2;
                *(__half2*)&Cb[row*256 + col] =
                    __floats2half2_rn(c[mt][nt][2*h]   * rinv[mt][h],
                                      c[mt][nt][2*h+1] * rinv[mt][h]);
            }
        }
}

// ---------------------------------------------------------------------------
// Merged PV: base read from x_h (fp16), writes tstep_h only. No fp32 tstep.
// ---------------------------------------------------------------------------
__launch_bounds__(256, 2)
__global__ void pv_h(const __half* __restrict__ P, const __half* __restrict__ xT,
                     const __half* __restrict__ x_h, __half* __restrict__ tstep_h)
{
    extern __shared__ uint32_t smp[];
    const int kvtab[6] = {1,2,0,2,0,1};
    int z = blockIdx.z;
    int qq = z>>6, b = z&63;
    const __half* baseq = x_h + ((long)qq*BS + (long)b*Ss)*128;
    __half* Ch = tstep_h + (long)qq*128 + (long)b*Ss*384;

    int m0 = blockIdx.y*128;
    int tid = threadIdx.x;
    int warp = tid>>5, lane = tid&31;
    int g = lane>>2, tig = lane&3;
    int wm = (warp&1)*64, wn = (warp>>1)*32;

    float c[4][4][4];
#pragma unroll
    for (int mt=0;mt<4;mt++)
#pragma unroll
        for (int nt=0;nt<4;nt++)
#pragma unroll
            for (int i=0;i<4;i++) c[mt][nt][i]=0.f;

    int lrow = tid>>1;
    int lseg = (tid&1)*8;

    auto load_tile = [&](int st, int gk) {
        int p = 2*qq + (gk>>3);
        int k0 = (gk&7)*32;
        const __half* ar = P + ((long)p*64 + b)*(long)Ss*Ss + (long)(m0+lrow)*Ss + k0;
        const __half* br = xT + ((long)kvtab[p]*64 + b)*128l*Ss + (long)lrow*Ss + k0;
        uint32_t* As = smp + st*HSTG;
        uint32_t* Bs = As + HA_WORDS;
        cpa16(s2u(&As[lrow*HSTR + lseg]),     ar + lseg*2,     16);
        cpa16(s2u(&As[lrow*HSTR + lseg + 4]), ar + lseg*2 + 8, 16);
        cpa16(s2u(&Bs[lrow*HSTR + lseg]),     br + lseg*2,     16);
        cpa16(s2u(&Bs[lrow*HSTR + lseg + 4]), br + lseg*2 + 8, 16);
    };
    auto compute = [&](int st) {
        const uint32_t* As = smp + st*HSTG;
        const uint32_t* Bs = As + HA_WORDS;
#pragma unroll
        for (int ks=0;ks<2;ks++) {
            uint32_t a[4][4], bb[4][2];
#pragma unroll
            for (int mt=0;mt<4;mt++) {
                int base = (wm + mt*16 + g)*HSTR + ks*8 + tig;
                a[mt][0] = As[base];
                a[mt][1] = As[base + 8*HSTR];
                a[mt][2] = As[base + 4];
                a[mt][3] = As[base + 8*HSTR + 4];
            }
#pragma unroll
            for (int nt=0;nt<4;nt++) {
                int base = (wn + nt*8 + g)*HSTR + ks*8 + tig;
                bb[nt][0] = Bs[base];
                bb[nt][1] = Bs[base + 4];
            }
#pragma unroll
            for (int mt=0;mt<4;mt++)
#pragma unroll
                for (int nt=0;nt<4;nt++)
                    mma_f16(c[mt][nt], a[mt], bb[nt]);
        }
    };

    load_tile(0, 0);
    asm volatile("cp.async.commit_group;");
    load_tile(1, 1);
    asm volatile("cp.async.commit_group;");
    for (int gk=0; gk<16; gk++) {
        asm volatile("cp.async.wait_group 1;");
        __syncthreads();
        if (gk+2 < 16) load_tile((gk+2)%3, gk+2);
        asm volatile("cp.async.commit_group;");
        compute(gk%3);
        __syncthreads();
    }

#pragma unroll
    for (int mt=0;mt<4;mt++) {
        long m = m0 + wm + mt*16 + g;
#pragma unroll
        for (int nt=0;nt<4;nt++) {
            int n = wn + nt*8 + tig*2;
            float2 b0 = __half22float2(*(const __half2*)&baseq[m*128 + n]);
            float2 b1 = __half22float2(*(const __half2*)&baseq[(m+8)*128 + n]);
            *(__half2*)&Ch[m*384 + n] =
                __floats2half2_rn(c[mt][nt][0]+b0.x, c[mt][nt][1]+b0.y);
            *(__half2*)&Ch[(m+8)*384 + n] =
                __floats2half2_rn(c[mt][nt][2]+b1.x, c[mt][nt][3]+b1.y);
        }
    }
}

// ---------------------------------------------------------------------------
// biGRU with next-step xg register prefetch (R9 layout; no fp32 tstep store).
// ---------------------------------------------------------------------------
__launch_bounds__(192, 3)
__global__ void gru_rec(const float* __restrict__ xg_all, const float* __restrict__ Wh,
                        const float* __restrict__ bh, __half* __restrict__ x_h)
{
    int bx = blockIdx.x;
    int m = bx>>7, d = (bx>>6)&1, b = bx&63, md = m*2+d;
    int j = threadIdx.x;
    ull w2[32];
#pragma unroll
    for (int q=0;q<32;q++)
        w2[q] = pk(Wh[((long)md*64 + 2*q)*192 + j], Wh[((long)md*64 + 2*q+1)*192 + j]);
    float bhj = bh[md*192 + j];
    __shared__ alignas(16) float h_s[64];
    __shared__ float pre_s[192], xn_s[64];
    uint32_t hsa = s2u(h_s);
    if (j<64) h_s[j]=0.f;
    const float* xg = xg_all + ((long)md*BS + (long)b*Ss)*192;
    int s0 = d ? (Ss-1) : 0;
    float xg_cur = xg[(long)s0*192 + j];
    for (int t=0;t<Ss;t++) {
        int s = d ? (Ss-1-t) : t;
        int sn = d ? (Ss-2-t) : (t+1);
        sn = sn < 0 ? 0 : (sn > Ss-1 ? Ss-1 : sn);
        __syncthreads();
        float xg_nxt = xg[(long)sn*192 + j];
        ull a0 = pk(bhj, 0.f), a1 = pk(0.f, 0.f);
#pragma unroll
        for (int q=0;q<16;q++) {
            ull h0,h1; lds2x64(h0,h1, hsa + q*16);
            ffma2(a0, h0, w2[2*q]);
            ffma2(a1, h1, w2[2*q+1]);
        }
        float2 f0 = upk(a0), f1 = upk(a1);
        float acc = f0.x + f0.y + f1.x + f1.y;
        float xgv = xg_cur;
        if (j<128) pre_s[j] = acc + xgv;
        else { pre_s[j] = acc; xn_s[j-128] = xgv; }
        __syncthreads();
        if (j<64) {
            float r = sigf(pre_s[j]);
            float zg = sigf(pre_s[64+j]);
            float n = tanhfast(xn_s[j] + r*pre_s[128+j]);
            float hn = (1.f-zg)*n + zg*h_s[j];
            h_s[j] = hn;
            long row = (long)b*Ss + s;
            x_h[((long)m*BS + row)*128 + d*64 + j] = __float2half(hn);
        }
        xg_cur = xg_nxt;
    }
}

// ---------------------------------------------------------------------------
// biLSTM with next-step xg register prefetch (R9 layout).
// ---------------------------------------------------------------------------
__launch_bounds__(512, 1)
__global__ void lstm_rec(const float* __restrict__ xg_all, const float* __restrict__ Wh,
                         const float* __restrict__ bh, __half* __restrict__ sf_h)
{
    extern __shared__ unsigned char smraw[];
    ull*   Wlo2  = (ull*)smraw;
    float* h_s   = (float*)(smraw + 16*512*8);
    float* pre_s = (float*)(smraw + 16*512*8 + 512);
    int bx = blockIdx.x, d = bx>>6, b = bx&63;
    int j = threadIdx.x;
    const float* Whd = Wh + (long)d*128*512;
    ull w2[48];
#pragma unroll
    for (int q=0;q<48;q++)
        w2[q] = pk(Whd[(long)(2*q)*512 + j], Whd[(long)(2*q+1)*512 + j]);
    for (int q=0;q<16;q++)
        Wlo2[q*512 + j] = pk(Whd[(long)(96+2*q)*512 + j], Whd[(long)(97+2*q)*512 + j]);
    float bhj = bh[d*512 + j];
    float c = 0.f;
    if (j<128) h_s[j]=0.f;
    uint32_t hsa = s2u(h_s);
    const float* xg = xg_all + ((long)d*BS + (long)b*Ss)*512;
    int s0 = d ? (Ss-1) : 0;
    float xg_cur = xg[(long)s0*512 + j];
    for (int t=0;t<Ss;t++) {
        int s = d ? (Ss-1-t) : t;
        int sn = d ? (Ss-2-t) : (t+1);
        sn = sn < 0 ? 0 : (sn > Ss-1 ? Ss-1 : sn);
        __syncthreads();
        float xg_nxt = xg[(long)sn*512 + j];
        ull a0 = pk(bhj, 0.f), a1 = pk(0.f, 0.f);
#pragma unroll
        for (int q=0;q<24;q++) {
            ull h0,h1; lds2x64(h0,h1, hsa + q*16);
            ffma2(a0, h0, w2[2*q]);
            ffma2(a1, h1, w2[2*q+1]);
        }
#pragma unroll
        for (int q=0;q<8;q++) {
            ull h0,h1; lds2x64(h0,h1, hsa + 384 + q*16);
            ffma2(a0, h0, Wlo2[(2*q)*512 + j]);
            ffma2(a1, h1, Wlo2[(2*q+1)*512 + j]);
        }
        float2 f0 = upk(a0), f1 = upk(a1);
        float acc = f0.x + f0.y + f1.x + f1.y + xg_cur;
        pre_s[j] = acc;
        __syncthreads();
        if (j<128) {
            float ig = pre_s[j], fg = pre_s[128+j], gg = pre_s[256+j], og = pre_s[384+j];
            c = sigf(fg)*c + sigf(ig)*tanhfast(gg);
            float h = sigf(og)*tanhfast(c);
            h_s[j] = h;
            sf_h[((long)b*Ss + s)*256 + d*128 + j] = __float2half(h);
        }
        xg_cur = xg_nxt;
    }
}

// ---------------------------------------------------------------------------
// RGN with next-step xg register prefetch (R9 layout, 384 thr, weights in regs).
// ---------------------------------------------------------------------------
__launch_bounds__(384, 1)
__global__ void rgn_rec(const float* __restrict__ xg_all, const float* __restrict__ Wh,
                        const float* __restrict__ state0, const float* __restrict__ state1,
                        float* __restrict__ outbuf)
{
    __shared__ alignas(16) float h_s[128];
    __shared__ float pre_s[384], xn_s[128];
    int bx = blockIdx.x, kk = bx>>6, b = bx&63;
    int j = threadIdx.x;
    const float* Whd = Wh + (long)kk*128*384;
    ull w2[64];
#pragma unroll
    for (int q=0;q<64;q++)
        w2[q] = pk(Whd[(long)(2*q)*384 + j], Whd[(long)(2*q+1)*384 + j]);
    if (j<128) h_s[j] = (kk==0?state0:state1)[b*128 + j];
    uint32_t hsa = s2u(h_s);
    const float* xg = xg_all + ((long)kk*BS + (long)b*Ss)*384;
    int s0 = kk ? (Ss-1) : 0;
    float xg_cur = xg[(long)s0*384 + j];
    for (int t=0;t<Ss;t++) {
        int sn = kk ? (Ss-2-t) : (t+1);
        sn = sn < 0 ? 0 : (sn > Ss-1 ? Ss-1 : sn);
        __syncthreads();
        float xg_nxt = xg[(long)sn*384 + j];
        ull a0 = pk(0.f, 0.f), a1 = pk(0.f, 0.f);
#pragma unroll
        for (int q=0;q<32;q++) {
            ull h0,h1; lds2x64(h0,h1, hsa + q*16);
            ffma2(a0, h0, w2[2*q]);
            ffma2(a1, h1, w2[2*q+1]);
        }
        float2 f0 = upk(a0), f1 = upk(a1);
        float acc = f0.x + f0.y + f1.x + f1.y;
        float xgv = xg_cur;
        if (j<256) pre_s[j] = acc + xgv;
        else { pre_s[j] = acc; xn_s[j-256] = xgv; }
        __syncthreads();
        if (j<128) {
            float r = sigf(pre_s[j]);
            float z = sigf(pre_s[128+j]);
            float n = tanhfast(xn_s[j] + r*pre_s[256+j]);
            h_s[j] = (1.f-z)*n + z*h_s[j];
        }
        xg_cur = xg_nxt;
    }
    __syncthreads();
    if (j<128) outbuf[((long)kk*64 + b)*128 + j] = h_s[j];
}

__launch_bounds__(32)
__global__ void final_fc(const float* __restrict__ outbuf,
                         const float* __restrict__ fc1W, const float* __restrict__ fc1b,
                         const float* __restrict__ fc2W, const float* __restrict__ fc2b,
                         float* __restrict__ out)
{
    int b = blockIdx.x, t = threadIdx.x;
    float acc = fc1b[t];
    for (int k=0;k<128;k++) {
        float x = outbuf[b*128+k] + outbuf[64*128 + b*128 + k];
        acc += x * fc1W[k*32 + t];
    }
    float h = acc > 0.f ? acc : 0.01f*acc;
    float v = h * fc2W[t];
#pragma unroll
    for (int o=16;o;o>>=1) v += __shfl_xor_sync(0xffffffffu, v, o);
    if (t==0) out[b] = v + fc2b[0];
}

extern "C" void kernel_launch(void* const* d_in, const int* in_sizes, int n_in,
                              void* d_out, int out_size)
{
    (void)in_sizes; (void)n_in; (void)out_size;
    const int*   sentences = (const int*)  d_in[0];
    const float* acoustic  = (const float*)d_in[1];
    const float* video     = (const float*)d_in[2];
    const float* state0    = (const float*)d_in[3];
    const float* state1    = (const float*)d_in[4];
    const float* emb       = (const float*)d_in[5];
    const float* proj_l_W  = (const float*)d_in[6];
    const float* proj_l_b  = (const float*)d_in[7];
    const float* proj_a_W  = (const float*)d_in[8];
    const float* proj_a_b  = (const float*)d_in[9];
    const float* proj_v_W  = (const float*)d_in[10];
    const float* proj_v_b  = (const float*)d_in[11];
    const float* gru_Wi    = (const float*)d_in[12];
    const float* gru_Wh    = (const float*)d_in[13];
    const float* gru_bi    = (const float*)d_in[14];
    const float* gru_bh    = (const float*)d_in[15];
    const float* lstm_Wi   = (const float*)d_in[16];
    const float* lstm_Wh   = (const float*)d_in[17];
    const float* lstm_bi   = (const float*)d_in[18];
    const float* lstm_bh   = (const float*)d_in[19];
    const float* rgn_Wx    = (const float*)d_in[20];
    const float* rgn_Wh    = (const float*)d_in[21];
    const float* rgn_b     = (const float*)d_in[22];
    const float* fc1_W     = (const float*)d_in[23];
    const float* fc1_b     = (const float*)d_in[24];
    const float* fc2_W     = (const float*)d_in[25];
    const float* fc2_b     = (const float*)d_in[26];
    float* out = (float*)d_out;

    float *xg_gru,*xg_lstm,*xg_rgn,*rgn_out;
    __half *seq_h,*x_h,*xT_h,*P_h,*tstep_h,*sf_h,*WT_h,*ac_h,*vid_h;
    cudaGetSymbolAddress((void**)&xg_gru, g_xg_gru);
    cudaGetSymbolAddress((void**)&xg_lstm, g_xg_lstm);
    cudaGetSymbolAddress((void**)&xg_rgn, g_xg_rgn);
    cudaGetSymbolAddress((void**)&rgn_out, g_rgn_out);
    cudaGetSymbolAddress((void**)&seq_h, g_seq_h);
    cudaGetSymbolAddress((void**)&x_h, g_x_h);
    cudaGetSymbolAddress((void**)&xT_h, g_xT_h);
    cudaGetSymbolAddress((void**)&P_h, g_P_h);
    cudaGetSymbolAddress((void**)&tstep_h, g_tstep_h);
    cudaGetSymbolAddress((void**)&sf_h, g_sf_h);
    cudaGetSymbolAddress((void**)&WT_h, g_WT_h);
    cudaGetSymbolAddress((void**)&ac_h, g_ac_h);
    cudaGetSymbolAddress((void**)&vid_h, g_vid_h);
    __half* gruT  = WT_h;
    __half* lstmT = gruT + 6*192*128;
    __half* rgnT  = lstmT + 2l*512*384;
    __half* projaT = rgnT + 2l*384*256;
    __half* projvT = projaT + 128*96;

    const size_t shm_tf3 = 3u*STG_WORDS*4u;
    const size_t shm_h   = 3u*HSTG*4u;
    const size_t shm_qk  = 3u*Q64_STG*4u;
    cudaFuncSetAttribute(gemm_tf, cudaFuncAttributeMaxDynamicSharedMemorySize, (int)shm_tf3);
    cudaFuncSetAttribute(gemm_h<0,0>, cudaFuncAttributeMaxDynamicSharedMemorySize, (int)shm_h);
    cudaFuncSetAttribute(gemm_h<1,0>, cudaFuncAttributeMaxDynamicSharedMemorySize, (int)shm_h);
    cudaFuncSetAttribute(gemm_h<0,1>, cudaFuncAttributeMaxDynamicSharedMemorySize, (int)shm_h);
    cudaFuncSetAttribute(qk_softmax_h, cudaFuncAttributeMaxDynamicSharedMemorySize, (int)shm_qk);
    cudaFuncSetAttribute(pv_h, cudaFuncAttributeMaxDynamicSharedMemorySize, (int)shm_h);
    cudaFuncSetAttribute(lstm_rec, cudaFuncAttributeMaxDynamicSharedMemorySize, 72*1024);

    // prep (2 launches)
    wtrans_all<<<740, dim3(32,8)>>>(gru_Wi, lstm_Wi, rgn_Wx, proj_a_W, proj_v_W, WT_h);
    conv2<<<1024, 256>>>(acoustic, ac_h, video, vid_h);

    // modality projections -> seq_h
    gemm_tf<<<dim3(1, BS/128, 1), 256, shm_tf3>>>(
        emb, proj_l_W, proj_l_b, seq_h, BS, 128, DL, 128, sentences);
    gemm_h<0,1><<<dim3(1, BS/128, 1), 256, shm_h>>>(
        ac_h, projaT, proj_a_b, seq_h + 1l*BS*DH, BS, 128, 96, 0, 0, 0, 0, 128);
    gemm_h<0,1><<<dim3(1, BS/128, 1), 256, shm_h>>>(
        vid_h, projvT, proj_v_b, seq_h + 2l*BS*DH, BS, 128, 64, 0, 0, 0, 0, 128);

    // GRU input projections (z=6)
    gemm_h<1,0><<<dim3(2, BS/128, 6), 256, shm_h>>>(
        seq_h, gruT, gru_bi, xg_gru, BS, 192, 128,
        (long)BS*DH, 192l*128, 192, (long)BS*192, 192);

    // biGRU (writes x_h only)
    gru_rec<<<3*2*64, 192>>>(xg_gru, gru_Wh, gru_bh, x_h);
    xtrans<<<dim3(192, 4), 256>>>(x_h, xT_h);

    // JCAF
    const float scale = 0.08838834764831845f;
    qk_softmax_h<<<dim3(1, 4, 384), 256, shm_qk>>>(x_h, P_h, scale);
    pv_h<<<dim3(1, 2, 192), 256, shm_h>>>(P_h, xT_h, x_h, tstep_h);

    // LSTM input projections (z=2)
    gemm_h<0,0><<<dim3(4, BS/128, 2), 256, shm_h>>>(
        tstep_h, lstmT, lstm_bi, xg_lstm, BS, 512, 384,
        0, 512l*384, 512, (long)BS*512, 512);

    lstm_rec<<<2*64, 512, 16*512*8 + 512 + 2048>>>(xg_lstm, lstm_Wh, lstm_bh, sf_h);

    // RGN input projections (z=2)
    gemm_h<0,0><<<dim3(3, BS/128, 2), 256, shm_h>>>(
        sf_h, rgnT, rgn_b, xg_rgn, BS, 384, 256,
        0, 384l*256, 384, (long)BS*384, 384);

    rgn_rec<<<2*64, 384>>>(xg_rgn, rgn_Wh, state0, state1, rgn_out);

    final_fc<<<Bb, 32>>>(rgn_out, fc1_W, fc1_b, fc2_W, fc2_b, out);
}

// round 14
// speedup vs baseline: 1.3200x; 1.0013x over previous
#include <cuda_runtime.h>
#include <cuda_fp16.h>
#include <math.h>
#include <stdint.h>

#define Bb 64
#define Ss 256
#define BS (Bb*Ss)
#define DL 300
#define DA 74
#define DV 35
#define DH 128

// fp32 scratch
__device__ float g_rgn_out[2u*Bb*128];
// fp16 scratch
__device__ __half g_xg_gru[6u*BS*192];
__device__ __half g_xg_lstm[2u*BS*512];
__device__ __half g_xg_rgn[2u*BS*384];
__device__ __half g_seq_h[3u*BS*DH];
__device__ __half g_x_h[3u*BS*DH];
__device__ __half g_xT_h[3u*(unsigned)Bb*128*Ss];
__device__ __half g_P_h[6u*(unsigned)Bb*Ss*Ss];
__device__ __half g_tstep_h[(unsigned)BS*384];
__device__ __half g_sf_h[(unsigned)BS*256];
__device__ __half g_av_h[(unsigned)BS*96 + (unsigned)BS*64];
__device__ __half g_WT_h[757760];

typedef unsigned long long ull;

__device__ __forceinline__ uint32_t s2u(const void* p) {
    return (uint32_t)__cvta_generic_to_shared(p);
}
__device__ __forceinline__ void cpa16(uint32_t dst, const void* src, int bytes) {
    asm volatile("cp.async.cg.shared.global [%0], [%1], 16, %2;"
                 :: "r"(dst), "l"(src), "r"(bytes));
}
__device__ __forceinline__ void mma_tf32(float c[4], const uint32_t a[4], const uint32_t b[2]) {
    asm volatile(
        "mma.sync.aligned.m16n8k8.row.col.f32.tf32.tf32.f32 "
        "{%0,%1,%2,%3}, {%4,%5,%6,%7}, {%8,%9}, {%0,%1,%2,%3};"
        : "+f"(c[0]), "+f"(c[1]), "+f"(c[2]), "+f"(c[3])
        : "r"(a[0]), "r"(a[1]), "r"(a[2]), "r"(a[3]), "r"(b[0]), "r"(b[1]));
}
__device__ __forceinline__ void mma_f16(float c[4], const uint32_t a[4], const uint32_t b[2]) {
    asm volatile(
        "mma.sync.aligned.m16n8k16.row.col.f32.f16.f16.f32 "
        "{%0,%1,%2,%3}, {%4,%5,%6,%7}, {%8,%9}, {%0,%1,%2,%3};"
        : "+f"(c[0]), "+f"(c[1]), "+f"(c[2]), "+f"(c[3])
        : "r"(a[0]), "r"(a[1]), "r"(a[2]), "r"(a[3]), "r"(b[0]), "r"(b[1]));
}
__device__ __forceinline__ ull pk(float x, float y) {
    ull r; asm("mov.b64 %0,{%1,%2};" : "=l"(r) : "f"(x), "f"(y)); return r;
}
__device__ __forceinline__ float2 upk(ull v) {
    float2 f; asm("mov.b64 {%0,%1},%2;" : "=f"(f.x), "=f"(f.y) : "l"(v)); return f;
}
__device__ __forceinline__ void ffma2(ull &d, ull a, ull b) {
    asm volatile("fma.rn.f32x2 %0, %1, %2, %0;" : "+l"(d) : "l"(a), "l"(b));
}
__device__ __forceinline__ void lds2x64(ull &a, ull &b, uint32_t addr) {
    asm volatile("ld.shared.v2.b64 {%0,%1},[%2];" : "=l"(a), "=l"(b) : "r"(addr));
}
__device__ __forceinline__ float sigf(float x) { return 1.f/(1.f + __expf(-x)); }
__device__ __forceinline__ float tanhfast(float x) {
    float y; asm("tanh.approx.f32 %0,%1;" : "=f"(y) : "f"(x)); return y;
}

// ---------------------------------------------------------------------------
// ALL weight transposes in one launch (740 tiles).
// ---------------------------------------------------------------------------
__global__ void wtrans_all(const float* __restrict__ gru_Wi,
                           const float* __restrict__ lstm_Wi,
                           const float* __restrict__ rgn_Wx,
                           const float* __restrict__ pa,
                           const float* __restrict__ pv,
                           __half* __restrict__ WT)
{
    __half* gruT  = WT;
    __half* lstmT = gruT + 6*192*128;
    __half* rgnT  = lstmT + 2l*512*384;
    __half* projaT = rgnT + 2l*384*256;
    __half* projvT = projaT + 128*96;

    int bid = blockIdx.x;
    const float* in; __half* out;
    int K, N, KP, k0, n0;
    if (bid < 144) {
        int z = bid/24, rem = bid%24;
        K = 128; N = 192; KP = 128;
        k0 = (rem%4)*32; n0 = (rem/4)*32;
        in = gru_Wi + (long)z*K*N; out = gruT + (long)z*N*KP;
    } else if (bid < 528) {
        int b2 = bid-144; int z = b2/192, rem = b2%192;
        K = 384; N = 512; KP = 384;
        k0 = (rem%12)*32; n0 = (rem/12)*32;
        in = lstm_Wi + (long)z*K*N; out = lstmT + (long)z*N*KP;
    } else if (bid < 720) {
        int b2 = bid-528; int z = b2/96, rem = b2%96;
        K = 256; N = 384; KP = 256;
        k0 = (rem%8)*32; n0 = (rem/8)*32;
        in = rgn_Wx + (long)z*K*N; out = rgnT + (long)z*N*KP;
    } else if (bid < 732) {
        int rem = bid-720;
        K = 74; N = 128; KP = 96;
        k0 = (rem%3)*32; n0 = (rem/3)*32;
        in = pa; out = projaT;
    } else {
        int rem = bid-732;
        K = 35; N = 128; KP = 64;
        k0 = (rem%2)*32; n0 = (rem/2)*32;
        in = pv; out = projvT;
    }

    __shared__ float t[32][33];
    int tx = threadIdx.x, ty = threadIdx.y;
#pragma unroll
    for (int i=0;i<32;i+=8) {
        int k = k0+ty+i, n = n0+tx;
        t[ty+i][tx] = (k<K && n<N) ? in[(long)k*N+n] : 0.f;
    }
    __syncthreads();
#pragma unroll
    for (int i=0;i<32;i+=8) {
        int n = n0+ty+i, k = k0+tx;
        if (n<N && k<KP) out[(long)n*KP+k] = __float2half(t[tx][ty+i]);
    }
}

// both input conversions in one launch (into contiguous av buffer)
__global__ void conv2(const float* __restrict__ ac, const float* __restrict__ vid,
                      __half* __restrict__ av)
{
    const long TOT_A = (long)BS*96;
    const long TOT_V = (long)BS*64;
    for (long i = (long)blockIdx.x*blockDim.x + threadIdx.x; i < TOT_A + TOT_V;
         i += (long)gridDim.x*blockDim.x) {
        if (i < TOT_A) {
            long row = i/96; int k = (int)(i - row*96);
            av[i] = (k<74) ? __float2half(ac[row*74 + k]) : __float2half(0.f);
        } else {
            long j = i - TOT_A;
            long row = j/64; int k = (int)(j - row*64);
            av[TOT_A + j] = (k<35) ? __float2half(vid[row*35 + k]) : __float2half(0.f);
        }
    }
}

// ---------------------------------------------------------------------------
// x_h -> xT_h transpose
// ---------------------------------------------------------------------------
__global__ void xtrans(const __half* __restrict__ xin, __half* __restrict__ xout)
{
    __shared__ __half sm[64][130];
    int mb = blockIdx.x;
    int m = mb>>6, b = mb&63;
    int s0 = blockIdx.y*64;
    int tid = threadIdx.x;
    const __half* src = xin + ((long)m*BS + (long)b*Ss + s0)*128;
#pragma unroll
    for (int i=0;i<32;i++) {
        int idx = tid + i*256;
        int s = idx>>7, d = idx&127;
        sm[s][d] = src[(long)s*128 + d];
    }
    __syncthreads();
    __half* dst = xout + (long)mb*128*Ss;
#pragma unroll
    for (int i=0;i<32;i++) {
        int idx = tid + i*256;
        int d = idx>>6, ss = idx&63;
        dst[(long)d*Ss + s0 + ss] = sm[ss][d];
    }
}

// ---------------------------------------------------------------------------
// TF32 GEMM (embedding projection only). fp16 output, 3-stage pipeline.
// ---------------------------------------------------------------------------
#define ASTR 36
#define BSTR 136
#define AWORDS (128*ASTR)
#define STG_WORDS (2*AWORDS)

__launch_bounds__(256, 2)
__global__ void gemm_tf(const float* __restrict__ A, const float* __restrict__ W,
                        const float* __restrict__ bias, __half* __restrict__ C,
                        int M, int N, int K, int ldc,
                        const int* __restrict__ gidx)
{
    extern __shared__ uint32_t smp[];
    int m0 = blockIdx.y*128, n0 = blockIdx.x*128;
    int tid = threadIdx.x;
    int warp = tid>>5, lane = tid&31;
    int g = lane>>2, tig = lane&3;
    int wm = (warp&1)*64, wn = (warp>>1)*32;

    float c[4][4][4];
#pragma unroll
    for (int mt=0;mt<4;mt++)
#pragma unroll
        for (int nt=0;nt<4;nt++)
#pragma unroll
            for (int i=0;i<4;i++) c[mt][nt][i]=0.f;

    int lrow = tid>>3;
    int akq  = (tid&7)*4;
    const float* arp[4];
#pragma unroll
    for (int p=0;p<4;p++)
        arp[p] = A + (long)gidx[m0 + lrow + p*32]*(long)K;
    int bnk = tid>>5;
    int bn4 = (tid&31)*4;

    auto load_tile = [&](int st, int k0) {
        uint32_t* As = smp + st*STG_WORDS;
        uint32_t* Bs = As + AWORDS;
#pragma unroll
        for (int p=0;p<4;p++) {
            int gk = k0 + akq;
            int bytes = (K - gk)*4; bytes = bytes<0?0:(bytes>16?16:bytes);
            const float* src = bytes ? (arp[p] + gk) : A;
            cpa16(s2u(&As[(lrow + p*32)*ASTR + akq]), src, bytes);
        }
#pragma unroll
        for (int p=0;p<4;p++) {
            int k = bnk + p*8;
            int ok = ((k0+k) < K) && ((n0+bn4) < N);
            const float* src = ok ? (W + (long)(k0+k)*N + n0 + bn4) : W;
            cpa16(s2u(&Bs[k*BSTR + bn4]), src, ok ? 16 : 0);
        }
    };
    auto compute = [&](int st) {
        const uint32_t* As = smp + st*STG_WORDS;
        const uint32_t* Bs = As + AWORDS;
#pragma unroll
        for (int ks=0;ks<4;ks++) {
            uint32_t a[4][4], b[4][2];
#pragma unroll
            for (int mt=0;mt<4;mt++) {
                int base = (wm + mt*16 + g)*ASTR + ks*8 + tig;
                a[mt][0] = As[base];
                a[mt][1] = As[base + 8*ASTR];
                a[mt][2] = As[base + 4];
                a[mt][3] = As[base + 8*ASTR + 4];
            }
#pragma unroll
            for (int nt=0;nt<4;nt++) {
                int base = (ks*8 + tig)*BSTR + wn + nt*8 + g;
                b[nt][0] = Bs[base];
                b[nt][1] = Bs[base + 4*BSTR];
            }
#pragma unroll
            for (int mt=0;mt<4;mt++)
#pragma unroll
                for (int nt=0;nt<4;nt++)
                    mma_tf32(c[mt][nt], a[mt], b[nt]);
        }
    };

    int ktn = (K+31)>>5;
    load_tile(0, 0);
    asm volatile("cp.async.commit_group;");
    if (ktn > 1) load_tile(1, 32);
    asm volatile("cp.async.commit_group;");
    for (int kt=0; kt<ktn; kt++) {
        asm volatile("cp.async.wait_group 1;");
        __syncthreads();
        if (kt+2 < ktn) load_tile((kt+2)%3, (kt+2)*32);
        asm volatile("cp.async.commit_group;");
        compute(kt%3);
        __syncthreads();
    }

#pragma unroll
    for (int mt=0;mt<4;mt++) {
        long m = m0 + wm + mt*16 + g;
#pragma unroll
        for (int nt=0;nt<4;nt++) {
            int n = n0 + wn + nt*8 + tig*2;
            if (n < N) {
                float bx = bias[n], by = bias[n+1];
                *(__half2*)&C[m*ldc + n] = __floats2half2_rn(c[mt][nt][0]+bx, c[mt][nt][1]+by);
                *(__half2*)&C[(m+8)*ldc + n] = __floats2half2_rn(c[mt][nt][2]+bx, c[mt][nt][3]+by);
            }
        }
    }
}

// ---------------------------------------------------------------------------
// FP16 NT GEMM. OUT16: 0 = fp32 C, 1 = fp16 C.
// MODE 0: generic z-batched; MODE 1: A shared per 2 z (GRU);
// MODE 2: merged ac/vid proj — z=0: K=96 slabs, z=1: K=64 (A,B,bias2 offsets).
// ---------------------------------------------------------------------------
#define HSTR 20
#define HA_WORDS (128*HSTR)
#define HSTG (2*HA_WORDS)

template<int MODE, int OUT16>
__launch_bounds__(256, 2)
__global__ void gemm_h(const __half* __restrict__ A, const __half* __restrict__ B,
                       const float* __restrict__ bias, void* __restrict__ Cv,
                       int M, int N, int K,
                       long sA, long sB, long sBias, long sC, int ldc,
                       const float* __restrict__ bias2)
{
    extern __shared__ uint32_t smp[];
    int z = blockIdx.z;
    const __half *Ab, *Bp;
    const float* bp;
    if (MODE == 2) {
        K  = z ? 64 : 96;
        Ab = z ? (A + (long)BS*96) : A;
        Bp = z ? (B + 128*96) : B;
        bp = z ? bias2 : bias;
    } else {
        Ab = A + (MODE==1 ? (long)(z>>1)*sA : (long)z*sA);
        Bp = B + (long)z*sB;
        bp = bias + (long)z*sBias;
    }

    int m0 = blockIdx.y*128, n0 = blockIdx.x*128;
    int tid = threadIdx.x;
    int warp = tid>>5, lane = tid&31;
    int g = lane>>2, tig = lane&3;
    int wm = (warp&1)*64, wn = (warp>>1)*32;

    float c[4][4][4];
#pragma unroll
    for (int mt=0;mt<4;mt++)
#pragma unroll
        for (int nt=0;nt<4;nt++)
#pragma unroll
            for (int i=0;i<4;i++) c[mt][nt][i]=0.f;

    int lrow = tid>>1;
    int lseg = (tid&1)*8;
    const __half* arow = Ab + (long)(m0+lrow)*K;
    const __half* brow = Bp + (long)(n0+lrow)*K;
    bool bok = (n0+lrow) < N;

    auto load_tile = [&](int st, int k0) {
        uint32_t* As = smp + st*HSTG;
        uint32_t* Bs = As + HA_WORDS;
        cpa16(s2u(&As[lrow*HSTR + lseg]),     arow + k0 + lseg*2,     16);
        cpa16(s2u(&As[lrow*HSTR + lseg + 4]), arow + k0 + lseg*2 + 8, 16);
        cpa16(s2u(&Bs[lrow*HSTR + lseg]),     bok ? (brow + k0 + lseg*2)     : brow, bok?16:0);
        cpa16(s2u(&Bs[lrow*HSTR + lseg + 4]), bok ? (brow + k0 + lseg*2 + 8) : brow, bok?16:0);
    };
    auto compute = [&](int st) {
        const uint32_t* As = smp + st*HSTG;
        const uint32_t* Bs = As + HA_WORDS;
#pragma unroll
        for (int ks=0;ks<2;ks++) {
            uint32_t a[4][4], b[4][2];
#pragma unroll
            for (int mt=0;mt<4;mt++) {
                int base = (wm + mt*16 + g)*HSTR + ks*8 + tig;
                a[mt][0] = As[base];
                a[mt][1] = As[base + 8*HSTR];
                a[mt][2] = As[base + 4];
                a[mt][3] = As[base + 8*HSTR + 4];
            }
#pragma unroll
            for (int nt=0;nt<4;nt++) {
                int base = (wn + nt*8 + g)*HSTR + ks*8 + tig;
                b[nt][0] = Bs[base];
                b[nt][1] = Bs[base + 4];
            }
#pragma unroll
            for (int mt=0;mt<4;mt++)
#pragma unroll
                for (int nt=0;nt<4;nt++)
                    mma_f16(c[mt][nt], a[mt], b[nt]);
        }
    };

    int ktn = K>>5;
    load_tile(0, 0);
    asm volatile("cp.async.commit_group;");
    if (ktn > 1) load_tile(1, 32);
    asm volatile("cp.async.commit_group;");
    for (int kt=0; kt<ktn; kt++) {
        asm volatile("cp.async.wait_group 1;");
        __syncthreads();
        if (kt+2 < ktn) load_tile((kt+2)%3, (kt+2)*32);
        asm volatile("cp.async.commit_group;");
        compute(kt%3);
        __syncthreads();
    }

#pragma unroll
    for (int mt=0;mt<4;mt++) {
        long m = m0 + wm + mt*16 + g;
#pragma unroll
        for (int nt=0;nt<4;nt++) {
            int n = n0 + wn + nt*8 + tig*2;
            if (n < N) {
                float bx = bp[n], by = bp[n+1];
                float v00 = c[mt][nt][0]+bx, v01 = c[mt][nt][1]+by;
                float v10 = c[mt][nt][2]+bx, v11 = c[mt][nt][3]+by;
                if (OUT16) {
                    __half* Cb = (__half*)Cv + (long)z*sC;
                    *(__half2*)&Cb[m*ldc + n] = __floats2half2_rn(v00, v01);
                    *(__half2*)&Cb[(m+8)*ldc + n] = __floats2half2_rn(v10, v11);
                } else {
                    float* Cb = (float*)Cv + (long)z*sC;
                    float2 v0; v0.x = v00; v0.y = v01;
                    float2 v1; v1.x = v10; v1.y = v11;
                    *(float2*)&Cb[m*ldc + n] = v0;
                    *(float2*)&Cb[(m+8)*ldc + n] = v1;
                }
            }
        }
    }
}

// ---------------------------------------------------------------------------
// Fused fp16 QK^T + softmax -> P_h. Block tile 64x256, warp tile 32x64,
// 2 CTAs/SM. grid (1, 4, 384).
// ---------------------------------------------------------------------------
#define QA64 (64*HSTR)
#define QB256 (256*HSTR)
#define Q64_STG (QA64 + QB256)

__launch_bounds__(256, 2)
__global__ void qk_softmax_h(const __half* __restrict__ x, __half* __restrict__ P,
                             float scale)
{
    extern __shared__ uint32_t smp[];
    const int qtab[6]  = {0,0,1,1,2,2};
    const int kvtab[6] = {1,2,0,2,0,1};

    int z = blockIdx.z;
    int p = z>>6, b = z&63;
    const __half* Ab = x + ((long)qtab[p]*BS + (long)b*Ss)*128;
    const __half* Bp = x + ((long)kvtab[p]*BS + (long)b*Ss)*128;
    __half* Cb = P + (long)z*Ss*Ss;
    int m0 = blockIdx.y*64;
    int tid = threadIdx.x;
    int warp = tid>>5, lane = tid&31;
    int g = lane>>2, tig = lane&3;
    int wm = (warp&1)*32, wn = (warp>>1)*64;

    float c[2][8][4];
#pragma unroll
    for (int mt=0;mt<2;mt++)
#pragma unroll
        for (int nt=0;nt<8;nt++)
#pragma unroll
            for (int i=0;i<4;i++) c[mt][nt][i]=0.f;

    int arow_i = tid>>2;
    int aseg = (tid&3)*4;
    const __half* arow = Ab + (long)(m0+arow_i)*128;
    const __half* brow = Bp + (long)tid*128;

    auto load_tile = [&](int st, int k0) {
        uint32_t* As = smp + st*Q64_STG;
        uint32_t* Bs = As + QA64;
        cpa16(s2u(&As[arow_i*HSTR + aseg]), arow + k0 + aseg*2, 16);
#pragma unroll
        for (int h=0;h<4;h++)
            cpa16(s2u(&Bs[tid*HSTR + h*4]), brow + k0 + h*8, 16);
    };
    auto compute = [&](int st) {
        const uint32_t* As = smp + st*Q64_STG;
        const uint32_t* Bs = As + QA64;
#pragma unroll
        for (int ks=0;ks<2;ks++) {
            uint32_t a[2][4], bb[8][2];
#pragma unroll
            for (int mt=0;mt<2;mt++) {
                int base = (wm + mt*16 + g)*HSTR + ks*8 + tig;
                a[mt][0] = As[base];
                a[mt][1] = As[base + 8*HSTR];
                a[mt][2] = As[base + 4];
                a[mt][3] = As[base + 8*HSTR + 4];
            }
#pragma unroll
            for (int nt=0;nt<8;nt++) {
                int base = (wn + nt*8 + g)*HSTR + ks*8 + tig;
                bb[nt][0] = Bs[base];
                bb[nt][1] = Bs[base + 4];
            }
#pragma unroll
            for (int mt=0;mt<2;mt++)
#pragma unroll
                for (int nt=0;nt<8;nt++)
                    mma_f16(c[mt][nt], a[mt], bb[nt]);
        }
    };

    load_tile(0, 0);
    asm volatile("cp.async.commit_group;");
    load_tile(1, 32);
    asm volatile("cp.async.commit_group;");
    for (int kt=0; kt<4; kt++) {
        asm volatile("cp.async.wait_group 1;");
        __syncthreads();
        if (kt+2 < 4) load_tile((kt+2)%3, (kt+2)*32);
        asm volatile("cp.async.commit_group;");
        compute(kt%3);
        __syncthreads();
    }

#pragma unroll
    for (int mt=0;mt<2;mt++)
#pragma unroll
        for (int nt=0;nt<8;nt++)
#pragma unroll
            for (int i=0;i<4;i++) c[mt][nt][i] *= scale;

    float* red = (float*)smp;
    int wcol = warp>>1;
    float rmax[2][2], rinv[2][2];

#pragma unroll
    for (int mt=0;mt<2;mt++)
#pragma unroll
        for (int h=0;h<2;h++) {
            float m = -1e30f;
#pragma unroll
            for (int nt=0;nt<8;nt++)
                m = fmaxf(m, fmaxf(c[mt][nt][2*h], c[mt][nt][2*h+1]));
            m = fmaxf(m, __shfl_xor_sync(0xffffffffu, m, 1));
            m = fmaxf(m, __shfl_xor_sync(0xffffffffu, m, 2));
            if (tig == 0) red[(wm + mt*16 + g + h*8)*4 + wcol] = m;
        }
    __syncthreads();
#pragma unroll
    for (int mt=0;mt<2;mt++)
#pragma unroll
        for (int h=0;h<2;h++) {
            int r = wm + mt*16 + g + h*8;
            rmax[mt][h] = fmaxf(fmaxf(red[r*4], red[r*4+1]),
                                fmaxf(red[r*4+2], red[r*4+3]));
        }
    __syncthreads();
#pragma unroll
    for (int mt=0;mt<2;mt++)
#pragma unroll
        for (int h=0;h<2;h++) {
            float s = 0.f;
#pragma unroll
            for (int nt=0;nt<8;nt++) {
                float e0 = __expf(c[mt][nt][2*h]   - rmax[mt][h]);
                float e1 = __expf(c[mt][nt][2*h+1] - rmax[mt][h]);
                c[mt][nt][2*h]   = e0;
                c[mt][nt][2*h+1] = e1;
                s += e0 + e1;
            }
            s += __shfl_xor_sync(0xffffffffu, s, 1);
            s += __shfl_xor_sync(0xffffffffu, s, 2);
            if (tig == 0) red[(wm + mt*16 + g + h*8)*4 + wcol] = s;
        }
    __syncthreads();
#pragma unroll
    for (int mt=0;mt<2;mt++)
#pragma unroll
        for (int h=0;h<2;h++) {
            int r = wm + mt*16 + g + h*8;
            rinv[mt][h] = 1.f/(red[r*4] + red[r*4+1] + red[r*4+2] + red[r*4+3]);
        }
#pragma unroll
    for (int mt=0;mt<2;mt++)
#pragma unroll
        for (int h=0;h<2;h++) {
            long row = m0 + wm + mt*16 + g + h*8;
#pragma unroll
            for (int nt=0;nt<8;nt++) {
                int col = wn + nt*8 + tig*2;
                *(__half2*)&Cb[row*256 + col] =
                    __floats2half2_rn(c[mt][nt][2*h]   * rinv[mt][h],
                                      c[mt][nt][2*h+1] * rinv[mt][h]);
            }
        }
}

// ---------------------------------------------------------------------------
// Merged PV: base read from x_h (fp16), writes tstep_h only.
// ---------------------------------------------------------------------------
__launch_bounds__(256, 2)
__global__ void pv_h(const __half* __restrict__ P, const __half* __restrict__ xT,
                     const __half* __restrict__ x_h, __half* __restrict__ tstep_h)
{
    extern __shared__ uint32_t smp[];
    const int kvtab[6] = {1,2,0,2,0,1};
    int z = blockIdx.z;
    int qq = z>>6, b = z&63;
    const __half* baseq = x_h + ((long)qq*BS + (long)b*Ss)*128;
    __half* Ch = tstep_h + (long)qq*128 + (long)b*Ss*384;

    int m0 = blockIdx.y*128;
    int tid = threadIdx.x;
    int warp = tid>>5, lane = tid&31;
    int g = lane>>2, tig = lane&3;
    int wm = (warp&1)*64, wn = (warp>>1)*32;

    float c[4][4][4];
#pragma unroll
    for (int mt=0;mt<4;mt++)
#pragma unroll
        for (int nt=0;nt<4;nt++)
#pragma unroll
            for (int i=0;i<4;i++) c[mt][nt][i]=0.f;

    int lrow = tid>>1;
    int lseg = (tid&1)*8;

    auto load_tile = [&](int st, int gk) {
        int p = 2*qq + (gk>>3);
        int k0 = (gk&7)*32;
        const __half* ar = P + ((long)p*64 + b)*(long)Ss*Ss + (long)(m0+lrow)*Ss + k0;
        const __half* br = xT + ((long)kvtab[p]*64 + b)*128l*Ss + (long)lrow*Ss + k0;
        uint32_t* As = smp + st*HSTG;
        uint32_t* Bs = As + HA_WORDS;
        cpa16(s2u(&As[lrow*HSTR + lseg]),     ar + lseg*2,     16);
        cpa16(s2u(&As[lrow*HSTR + lseg + 4]), ar + lseg*2 + 8, 16);
        cpa16(s2u(&Bs[lrow*HSTR + lseg]),     br + lseg*2,     16);
        cpa16(s2u(&Bs[lrow*HSTR + lseg + 4]), br + lseg*2 + 8, 16);
    };
    auto compute = [&](int st) {
        const uint32_t* As = smp + st*HSTG;
        const uint32_t* Bs = As + HA_WORDS;
#pragma unroll
        for (int ks=0;ks<2;ks++) {
            uint32_t a[4][4], bb[4][2];
#pragma unroll
            for (int mt=0;mt<4;mt++) {
                int base = (wm + mt*16 + g)*HSTR + ks*8 + tig;
                a[mt][0] = As[base];
                a[mt][1] = As[base + 8*HSTR];
                a[mt][2] = As[base + 4];
                a[mt][3] = As[base + 8*HSTR + 4];
            }
#pragma unroll
            for (int nt=0;nt<4;nt++) {
                int base = (wn + nt*8 + g)*HSTR + ks*8 + tig;
                bb[nt][0] = Bs[base];
                bb[nt][1] = Bs[base + 4];
            }
#pragma unroll
            for (int mt=0;mt<4;mt++)
#pragma unroll
                for (int nt=0;nt<4;nt++)
                    mma_f16(c[mt][nt], a[mt], bb[nt]);
        }
    };

    load_tile(0, 0);
    asm volatile("cp.async.commit_group;");
    load_tile(1, 1);
    asm volatile("cp.async.commit_group;");
    for (int gk=0; gk<16; gk++) {
        asm volatile("cp.async.wait_group 1;");
        __syncthreads();
        if (gk+2 < 16) load_tile((gk+2)%3, gk+2);
        asm volatile("cp.async.commit_group;");
        compute(gk%3);
        __syncthreads();
    }

#pragma unroll
    for (int mt=0;mt<4;mt++) {
        long m = m0 + wm + mt*16 + g;
#pragma unroll
        for (int nt=0;nt<4;nt++) {
            int n = wn + nt*8 + tig*2;
            float2 b0 = __half22float2(*(const __half2*)&baseq[m*128 + n]);
            float2 b1 = __half22float2(*(const __half2*)&baseq[(m+8)*128 + n]);
            *(__half2*)&Ch[m*384 + n] =
                __floats2half2_rn(c[mt][nt][0]+b0.x, c[mt][nt][1]+b0.y);
            *(__half2*)&Ch[(m+8)*384 + n] =
                __floats2half2_rn(c[mt][nt][2]+b1.x, c[mt][nt][3]+b1.y);
        }
    }
}

// ---------------------------------------------------------------------------
// biGRU (R9 layout, fp16 xg).
// ---------------------------------------------------------------------------
__launch_bounds__(192, 3)
__global__ void gru_rec(const __half* __restrict__ xg_all, const float* __restrict__ Wh,
                        const float* __restrict__ bh, __half* __restrict__ x_h)
{
    int bx = blockIdx.x;
    int m = bx>>7, d = (bx>>6)&1, b = bx&63, md = m*2+d;
    int j = threadIdx.x;
    ull w2[32];
#pragma unroll
    for (int q=0;q<32;q++)
        w2[q] = pk(Wh[((long)md*64 + 2*q)*192 + j], Wh[((long)md*64 + 2*q+1)*192 + j]);
    float bhj = bh[md*192 + j];
    __shared__ alignas(16) float h_s[64];
    __shared__ float pre_s[192], xn_s[64];
    uint32_t hsa = s2u(h_s);
    if (j<64) h_s[j]=0.f;
    const __half* xg = xg_all + ((long)md*BS + (long)b*Ss)*192;
    int s0 = d ? (Ss-1) : 0;
    float xg_cur = __half2float(xg[(long)s0*192 + j]);
    for (int t=0;t<Ss;t++) {
        int s = d ? (Ss-1-t) : t;
        int sn = d ? (Ss-2-t) : (t+1);
        sn = sn < 0 ? 0 : (sn > Ss-1 ? Ss-1 : sn);
        __syncthreads();
        float xg_nxt = __half2float(xg[(long)sn*192 + j]);
        ull a0 = pk(bhj, 0.f), a1 = pk(0.f, 0.f);
#pragma unroll
        for (int q=0;q<16;q++) {
            ull h0,h1; lds2x64(h0,h1, hsa + q*16);
            ffma2(a0, h0, w2[2*q]);
            ffma2(a1, h1, w2[2*q+1]);
        }
        float2 f0 = upk(a0), f1 = upk(a1);
        float acc = f0.x + f0.y + f1.x + f1.y;
        float xgv = xg_cur;
        if (j<128) pre_s[j] = acc + xgv;
        else { pre_s[j] = acc; xn_s[j-128] = xgv; }
        __syncthreads();
        if (j<64) {
            float r = sigf(pre_s[j]);
            float zg = sigf(pre_s[64+j]);
            float n = tanhfast(xn_s[j] + r*pre_s[128+j]);
            float hn = (1.f-zg)*n + zg*h_s[j];
            h_s[j] = hn;
            long row = (long)b*Ss + s;
            x_h[((long)m*BS + row)*128 + d*64 + j] = __float2half(hn);
        }
        xg_cur = xg_nxt;
    }
}

// ---------------------------------------------------------------------------
// biLSTM (R9 layout, fp16 xg).
// ---------------------------------------------------------------------------
__launch_bounds__(512, 1)
__global__ void lstm_rec(const __half* __restrict__ xg_all, const float* __restrict__ Wh,
                         const float* __restrict__ bh, __half* __restrict__ sf_h)
{
    extern __shared__ unsigned char smraw[];
    ull*   Wlo2  = (ull*)smraw;
    float* h_s   = (float*)(smraw + 16*512*8);
    float* pre_s = (float*)(smraw + 16*512*8 + 512);
    int bx = blockIdx.x, d = bx>>6, b = bx&63;
    int j = threadIdx.x;
    const float* Whd = Wh + (long)d*128*512;
    ull w2[48];
#pragma unroll
    for (int q=0;q<48;q++)
        w2[q] = pk(Whd[(long)(2*q)*512 + j], Whd[(long)(2*q+1)*512 + j]);
    for (int q=0;q<16;q++)
        Wlo2[q*512 + j] = pk(Whd[(long)(96+2*q)*512 + j], Whd[(long)(97+2*q)*512 + j]);
    float bhj = bh[d*512 + j];
    float c = 0.f;
    if (j<128) h_s[j]=0.f;
    uint32_t hsa = s2u(h_s);
    const __half* xg = xg_all + ((long)d*BS + (long)b*Ss)*512;
    int s0 = d ? (Ss-1) : 0;
    float xg_cur = __half2float(xg[(long)s0*512 + j]);
    for (int t=0;t<Ss;t++) {
        int s = d ? (Ss-1-t) : t;
        int sn = d ? (Ss-2-t) : (t+1);
        sn = sn < 0 ? 0 : (sn > Ss-1 ? Ss-1 : sn);
        __syncthreads();
        float xg_nxt = __half2float(xg[(long)sn*512 + j]);
        ull a0 = pk(bhj, 0.f), a1 = pk(0.f, 0.f);
#pragma unroll
        for (int q=0;q<24;q++) {
            ull h0,h1; lds2x64(h0,h1, hsa + q*16);
            ffma2(a0, h0, w2[2*q]);
            ffma2(a1, h1, w2[2*q+1]);
        }
#pragma unroll
        for (int q=0;q<8;q++) {
            ull h0,h1; lds2x64(h0,h1, hsa + 384 + q*16);
            ffma2(a0, h0, Wlo2[(2*q)*512 + j]);
            ffma2(a1, h1, Wlo2[(2*q+1)*512 + j]);
        }
        float2 f0 = upk(a0), f1 = upk(a1);
        float acc = f0.x + f0.y + f1.x + f1.y + xg_cur;
        pre_s[j] = acc;
        __syncthreads();
        if (j<128) {
            float ig = pre_s[j], fg = pre_s[128+j], gg = pre_s[256+j], og = pre_s[384+j];
            c = sigf(fg)*c + sigf(ig)*tanhfast(gg);
            float h = sigf(og)*tanhfast(c);
            h_s[j] = h;
            sf_h[((long)b*Ss + s)*256 + d*128 + j] = __float2half(h);
        }
        xg_cur = xg_nxt;
    }
}

// ---------------------------------------------------------------------------
// RGN (R9 layout, fp16 xg).
// ---------------------------------------------------------------------------
__launch_bounds__(384, 1)
__global__ void rgn_rec(const __half* __restrict__ xg_all, const float* __restrict__ Wh,
                        const float* __restrict__ state0, const float* __restrict__ state1,
                        float* __restrict__ outbuf)
{
    __shared__ alignas(16) float h_s[128];
    __shared__ float pre_s[384], xn_s[128];
    int bx = blockIdx.x, kk = bx>>6, b = bx&63;
    int j = threadIdx.x;
    const float* Whd = Wh + (long)kk*128*384;
    ull w2[64];
#pragma unroll
    for (int q=0;q<64;q++)
        w2[q] = pk(Whd[(long)(2*q)*384 + j], Whd[(long)(2*q+1)*384 + j]);
    if (j<128) h_s[j] = (kk==0?state0:state1)[b*128 + j];
    uint32_t hsa = s2u(h_s);
    const __half* xg = xg_all + ((long)kk*BS + (long)b*Ss)*384;
    int s0 = kk ? (Ss-1) : 0;
    float xg_cur = __half2float(xg[(long)s0*384 + j]);
    for (int t=0;t<Ss;t++) {
        int sn = kk ? (Ss-2-t) : (t+1);
        sn = sn < 0 ? 0 : (sn > Ss-1 ? Ss-1 : sn);
        __syncthreads();
        float xg_nxt = __half2float(xg[(long)sn*384 + j]);
        ull a0 = pk(0.f, 0.f), a1 = pk(0.f, 0.f);
#pragma unroll
        for (int q=0;q<32;q++) {
            ull h0,h1; lds2x64(h0,h1, hsa + q*16);
            ffma2(a0, h0, w2[2*q]);
            ffma2(a1, h1, w2[2*q+1]);
        }
        float2 f0 = upk(a0), f1 = upk(a1);
        float acc = f0.x + f0.y + f1.x + f1.y;
        float xgv = xg_cur;
        if (j<256) pre_s[j] = acc + xgv;
        else { pre_s[j] = acc; xn_s[j-256] = xgv; }
        __syncthreads();
        if (j<128) {
            float r = sigf(pre_s[j]);
            float z = sigf(pre_s[128+j]);
            float n = tanhfast(xn_s[j] + r*pre_s[256+j]);
            h_s[j] = (1.f-z)*n + z*h_s[j];
        }
        xg_cur = xg_nxt;
    }
    __syncthreads();
    if (j<128) outbuf[((long)kk*64 + b)*128 + j] = h_s[j];
}

__launch_bounds__(32)
__global__ void final_fc(const float* __restrict__ outbuf,
                         const float* __restrict__ fc1W, const float* __restrict__ fc1b,
                         const float* __restrict__ fc2W, const float* __restrict__ fc2b,
                         float* __restrict__ out)
{
    int b = blockIdx.x, t = threadIdx.x;
    float acc = fc1b[t];
    for (int k=0;k<128;k++) {
        float x = outbuf[b*128+k] + outbuf[64*128 + b*128 + k];
        acc += x * fc1W[k*32 + t];
    }
    float h = acc > 0.f ? acc : 0.01f*acc;
    float v = h * fc2W[t];
#pragma unroll
    for (int o=16;o;o>>=1) v += __shfl_xor_sync(0xffffffffu, v, o);
    if (t==0) out[b] = v + fc2b[0];
}

extern "C" void kernel_launch(void* const* d_in, const int* in_sizes, int n_in,
                              void* d_out, int out_size)
{
    (void)in_sizes; (void)n_in; (void)out_size;
    const int*   sentences = (const int*)  d_in[0];
    const float* acoustic  = (const float*)d_in[1];
    const float* video     = (const float*)d_in[2];
    const float* state0    = (const float*)d_in[3];
    const float* state1    = (const float*)d_in[4];
    const float* emb       = (const float*)d_in[5];
    const float* proj_l_W  = (const float*)d_in[6];
    const float* proj_l_b  = (const float*)d_in[7];
    const float* proj_a_W  = (const float*)d_in[8];
    const float* proj_a_b  = (const float*)d_in[9];
    const float* proj_v_W  = (const float*)d_in[10];
    const float* proj_v_b  = (const float*)d_in[11];
    const float* gru_Wi    = (const float*)d_in[12];
    const float* gru_Wh    = (const float*)d_in[13];
    const float* gru_bi    = (const float*)d_in[14];
    const float* gru_bh    = (const float*)d_in[15];
    const float* lstm_Wi   = (const float*)d_in[16];
    const float* lstm_Wh   = (const float*)d_in[17];
    const float* lstm_bi   = (const float*)d_in[18];
    const float* lstm_bh   = (const float*)d_in[19];
    const float* rgn_Wx    = (const float*)d_in[20];
    const float* rgn_Wh    = (const float*)d_in[21];
    const float* rgn_b     = (const float*)d_in[22];
    const float* fc1_W     = (const float*)d_in[23];
    const float* fc1_b     = (const float*)d_in[24];
    const float* fc2_W     = (const float*)d_in[25];
    const float* fc2_b     = (const float*)d_in[26];
    float* out = (float*)d_out;

    float *rgn_out;
    __half *xg_gru,*xg_lstm,*xg_rgn;
    __half *seq_h,*x_h,*xT_h,*P_h,*tstep_h,*sf_h,*WT_h,*av_h;
    cudaGetSymbolAddress((void**)&xg_gru, g_xg_gru);
    cudaGetSymbolAddress((void**)&xg_lstm, g_xg_lstm);
    cudaGetSymbolAddress((void**)&xg_rgn, g_xg_rgn);
    cudaGetSymbolAddress((void**)&rgn_out, g_rgn_out);
    cudaGetSymbolAddress((void**)&seq_h, g_seq_h);
    cudaGetSymbolAddress((void**)&x_h, g_x_h);
    cudaGetSymbolAddress((void**)&xT_h, g_xT_h);
    cudaGetSymbolAddress((void**)&P_h, g_P_h);
    cudaGetSymbolAddress((void**)&tstep_h, g_tstep_h);
    cudaGetSymbolAddress((void**)&sf_h, g_sf_h);
    cudaGetSymbolAddress((void**)&WT_h, g_WT_h);
    cudaGetSymbolAddress((void**)&av_h, g_av_h);
    __half* gruT  = WT_h;
    __half* lstmT = gruT + 6*192*128;
    __half* rgnT  = lstmT + 2l*512*384;
    __half* projaT = rgnT + 2l*384*256;

    const size_t shm_tf3 = 3u*STG_WORDS*4u;
    const size_t shm_h   = 3u*HSTG*4u;
    const size_t shm_qk  = 3u*Q64_STG*4u;
    cudaFuncSetAttribute(gemm_tf, cudaFuncAttributeMaxDynamicSharedMemorySize, (int)shm_tf3);
    cudaFuncSetAttribute(gemm_h<0,1>, cudaFuncAttributeMaxDynamicSharedMemorySize, (int)shm_h);
    cudaFuncSetAttribute(gemm_h<1,1>, cudaFuncAttributeMaxDynamicSharedMemorySize, (int)shm_h);
    cudaFuncSetAttribute(gemm_h<2,1>, cudaFuncAttributeMaxDynamicSharedMemorySize, (int)shm_h);
    cudaFuncSetAttribute(qk_softmax_h, cudaFuncAttributeMaxDynamicSharedMemorySize, (int)shm_qk);
    cudaFuncSetAttribute(pv_h, cudaFuncAttributeMaxDynamicSharedMemorySize, (int)shm_h);
    cudaFuncSetAttribute(lstm_rec, cudaFuncAttributeMaxDynamicSharedMemorySize, 72*1024);

    // prep (2 launches)
    wtrans_all<<<740, dim3(32,8)>>>(gru_Wi, lstm_Wi, rgn_Wx, proj_a_W, proj_v_W, WT_h);
    conv2<<<1024, 256>>>(acoustic, video, av_h);

    // modality projections -> seq_h
    gemm_tf<<<dim3(1, BS/128, 1), 256, shm_tf3>>>(
        emb, proj_l_W, proj_l_b, seq_h, BS, 128, DL, 128, sentences);
    gemm_h<2,1><<<dim3(1, BS/128, 2), 256, shm_h>>>(
        av_h, projaT, proj_a_b, seq_h + 1l*BS*DH, BS, 128, 0,
        0, 0, 0, (long)BS*DH, 128, proj_v_b);

    // GRU input projections (z=6) -> fp16 xg
    gemm_h<1,1><<<dim3(2, BS/128, 6), 256, shm_h>>>(
        seq_h, gruT, gru_bi, xg_gru, BS, 192, 128,
        (long)BS*DH, 192l*128, 192, (long)BS*192, 192, nullptr);

    // biGRU (writes x_h only)
    gru_rec<<<3*2*64, 192>>>(xg_gru, gru_Wh, gru_bh, x_h);
    xtrans<<<dim3(192, 4), 256>>>(x_h, xT_h);

    // JCAF
    const float scale = 0.08838834764831845f;
    qk_softmax_h<<<dim3(1, 4, 384), 256, shm_qk>>>(x_h, P_h, scale);
    pv_h<<<dim3(1, 2, 192), 256, shm_h>>>(P_h, xT_h, x_h, tstep_h);

    // LSTM input projections (z=2) -> fp16 xg
    gemm_h<0,1><<<dim3(4, BS/128, 2), 256, shm_h>>>(
        tstep_h, lstmT, lstm_bi, xg_lstm, BS, 512, 384,
        0, 512l*384, 512, (long)BS*512, 512, nullptr);

    lstm_rec<<<2*64, 512, 16*512*8 + 512 + 2048>>>(xg_lstm, lstm_Wh, lstm_bh, sf_h);

    // RGN input projections (z=2) -> fp16 xg
    gemm_h<0,1><<<dim3(3, BS/128, 2), 256, shm_h>>>(
        sf_h, rgnT, rgn_b, xg_rgn, BS, 384, 256,
        0, 384l*256, 384, (long)BS*384, 384, nullptr);

    rgn_rec<<<2*64, 384>>>(xg_rgn, rgn_Wh, state0, state1, rgn_out);

    final_fc<<<Bb, 32>>>(rgn_out, fc1_W, fc1_b, fc2_W, fc2_b, out);
}

// round 15
// speedup vs baseline: 1.3252x; 1.0040x over previous
#include <cuda_runtime.h>
#include <cuda_fp16.h>
#include <math.h>
#include <stdint.h>

#define Bb 64
#define Ss 256
#define BS (Bb*Ss)
#define DL 300
#define DA 74
#define DV 35
#define DH 128

// fp32 scratch
__device__ float g_rgn_out[2u*Bb*128];
// fp16 scratch
__device__ __half g_xg_gru[6u*BS*192];
__device__ __half g_xg_lstm[2u*BS*512];
__device__ __half g_xg_rgn[2u*BS*384];
__device__ __half g_seq_h[3u*BS*DH];
__device__ __half g_x_h[3u*BS*DH];
__device__ __half g_xT_h[3u*(unsigned)Bb*128*Ss];
__device__ __half g_P_h[6u*(unsigned)Bb*Ss*Ss];
__device__ __half g_tstep_h[(unsigned)BS*384];
__device__ __half g_sf_h[(unsigned)BS*256];
__device__ __half g_av_h[(unsigned)BS*96 + (unsigned)BS*64];
__device__ __half g_WT_h[757760];

typedef unsigned long long ull;

__device__ __forceinline__ uint32_t s2u(const void* p) {
    return (uint32_t)__cvta_generic_to_shared(p);
}
__device__ __forceinline__ void cpa16(uint32_t dst, const void* src, int bytes) {
    asm volatile("cp.async.cg.shared.global [%0], [%1], 16, %2;"
                 :: "r"(dst), "l"(src), "r"(bytes));
}
__device__ __forceinline__ void mma_tf32(float c[4], const uint32_t a[4], const uint32_t b[2]) {
    asm volatile(
        "mma.sync.aligned.m16n8k8.row.col.f32.tf32.tf32.f32 "
        "{%0,%1,%2,%3}, {%4,%5,%6,%7}, {%8,%9}, {%0,%1,%2,%3};"
        : "+f"(c[0]), "+f"(c[1]), "+f"(c[2]), "+f"(c[3])
        : "r"(a[0]), "r"(a[1]), "r"(a[2]), "r"(a[3]), "r"(b[0]), "r"(b[1]));
}
__device__ __forceinline__ void mma_f16(float c[4], const uint32_t a[4], const uint32_t b[2]) {
    asm volatile(
        "mma.sync.aligned.m16n8k16.row.col.f32.f16.f16.f32 "
        "{%0,%1,%2,%3}, {%4,%5,%6,%7}, {%8,%9}, {%0,%1,%2,%3};"
        : "+f"(c[0]), "+f"(c[1]), "+f"(c[2]), "+f"(c[3])
        : "r"(a[0]), "r"(a[1]), "r"(a[2]), "r"(a[3]), "r"(b[0]), "r"(b[1]));
}
__device__ __forceinline__ ull pk(float x, float y) {
    ull r; asm("mov.b64 %0,{%1,%2};" : "=l"(r) : "f"(x), "f"(y)); return r;
}
__device__ __forceinline__ float2 upk(ull v) {
    float2 f; asm("mov.b64 {%0,%1},%2;" : "=f"(f.x), "=f"(f.y) : "l"(v)); return f;
}
__device__ __forceinline__ void ffma2(ull &d, ull a, ull b) {
    asm volatile("fma.rn.f32x2 %0, %1, %2, %0;" : "+l"(d) : "l"(a), "l"(b));
}
__device__ __forceinline__ void lds2x64(ull &a, ull &b, uint32_t addr) {
    asm volatile("ld.shared.v2.b64 {%0,%1},[%2];" : "=l"(a), "=l"(b) : "r"(addr));
}
__device__ __forceinline__ float sigf(float x) { return 1.f/(1.f + __expf(-x)); }
__device__ __forceinline__ float tanhfast(float x) {
    float y; asm("tanh.approx.f32 %0,%1;" : "=f"(y) : "f"(x)); return y;
}

// ---------------------------------------------------------------------------
// ALL weight transposes in one launch (740 tiles).
// ---------------------------------------------------------------------------
__global__ void wtrans_all(const float* __restrict__ gru_Wi,
                           const float* __restrict__ lstm_Wi,
                           const float* __restrict__ rgn_Wx,
                           const float* __restrict__ pa,
                           const float* __restrict__ pv,
                           __half* __restrict__ WT)
{
    __half* gruT  = WT;
    __half* lstmT = gruT + 6*192*128;
    __half* rgnT  = lstmT + 2l*512*384;
    __half* projaT = rgnT + 2l*384*256;
    __half* projvT = projaT + 128*96;

    int bid = blockIdx.x;
    const float* in; __half* out;
    int K, N, KP, k0, n0;
    if (bid < 144) {
        int z = bid/24, rem = bid%24;
        K = 128; N = 192; KP = 128;
        k0 = (rem%4)*32; n0 = (rem/4)*32;
        in = gru_Wi + (long)z*K*N; out = gruT + (long)z*N*KP;
    } else if (bid < 528) {
        int b2 = bid-144; int z = b2/192, rem = b2%192;
        K = 384; N = 512; KP = 384;
        k0 = (rem%12)*32; n0 = (rem/12)*32;
        in = lstm_Wi + (long)z*K*N; out = lstmT + (long)z*N*KP;
    } else if (bid < 720) {
        int b2 = bid-528; int z = b2/96, rem = b2%96;
        K = 256; N = 384; KP = 256;
        k0 = (rem%8)*32; n0 = (rem/8)*32;
        in = rgn_Wx + (long)z*K*N; out = rgnT + (long)z*N*KP;
    } else if (bid < 732) {
        int rem = bid-720;
        K = 74; N = 128; KP = 96;
        k0 = (rem%3)*32; n0 = (rem/3)*32;
        in = pa; out = projaT;
    } else {
        int rem = bid-732;
        K = 35; N = 128; KP = 64;
        k0 = (rem%2)*32; n0 = (rem/2)*32;
        in = pv; out = projvT;
    }

    __shared__ float t[32][33];
    int tx = threadIdx.x, ty = threadIdx.y;
#pragma unroll
    for (int i=0;i<32;i+=8) {
        int k = k0+ty+i, n = n0+tx;
        t[ty+i][tx] = (k<K && n<N) ? in[(long)k*N+n] : 0.f;
    }
    __syncthreads();
#pragma unroll
    for (int i=0;i<32;i+=8) {
        int n = n0+ty+i, k = k0+tx;
        if (n<N && k<KP) out[(long)n*KP+k] = __float2half(t[tx][ty+i]);
    }
}

// both input conversions in one launch (contiguous av buffer)
__global__ void conv2(const float* __restrict__ ac, const float* __restrict__ vid,
                      __half* __restrict__ av)
{
    const long TOT_A = (long)BS*96;
    const long TOT_V = (long)BS*64;
    for (long i = (long)blockIdx.x*blockDim.x + threadIdx.x; i < TOT_A + TOT_V;
         i += (long)gridDim.x*blockDim.x) {
        if (i < TOT_A) {
            long row = i/96; int k = (int)(i - row*96);
            av[i] = (k<74) ? __float2half(ac[row*74 + k]) : __float2half(0.f);
        } else {
            long j = i - TOT_A;
            long row = j/64; int k = (int)(j - row*64);
            av[TOT_A + j] = (k<35) ? __float2half(vid[row*35 + k]) : __float2half(0.f);
        }
    }
}

// ---------------------------------------------------------------------------
// x_h -> xT_h transpose
// ---------------------------------------------------------------------------
__global__ void xtrans(const __half* __restrict__ xin, __half* __restrict__ xout)
{
    __shared__ __half sm[64][130];
    int mb = blockIdx.x;
    int m = mb>>6, b = mb&63;
    int s0 = blockIdx.y*64;
    int tid = threadIdx.x;
    const __half* src = xin + ((long)m*BS + (long)b*Ss + s0)*128;
#pragma unroll
    for (int i=0;i<32;i++) {
        int idx = tid + i*256;
        int s = idx>>7, d = idx&127;
        sm[s][d] = src[(long)s*128 + d];
    }
    __syncthreads();
    __half* dst = xout + (long)mb*128*Ss;
#pragma unroll
    for (int i=0;i<32;i++) {
        int idx = tid + i*256;
        int d = idx>>6, ss = idx&63;
        dst[(long)d*Ss + s0 + ss] = sm[ss][d];
    }
}

// ---------------------------------------------------------------------------
// TF32 GEMM (embedding projection only). fp16 output, 3-stage pipeline.
// ---------------------------------------------------------------------------
#define ASTR 36
#define BSTR 136
#define AWORDS (128*ASTR)
#define STG_WORDS (2*AWORDS)

__launch_bounds__(256, 2)
__global__ void gemm_tf(const float* __restrict__ A, const float* __restrict__ W,
                        const float* __restrict__ bias, __half* __restrict__ C,
                        int M, int N, int K, int ldc,
                        const int* __restrict__ gidx)
{
    extern __shared__ uint32_t smp[];
    int m0 = blockIdx.y*128, n0 = blockIdx.x*128;
    int tid = threadIdx.x;
    int warp = tid>>5, lane = tid&31;
    int g = lane>>2, tig = lane&3;
    int wm = (warp&1)*64, wn = (warp>>1)*32;

    float c[4][4][4];
#pragma unroll
    for (int mt=0;mt<4;mt++)
#pragma unroll
        for (int nt=0;nt<4;nt++)
#pragma unroll
            for (int i=0;i<4;i++) c[mt][nt][i]=0.f;

    int lrow = tid>>3;
    int akq  = (tid&7)*4;
    const float* arp[4];
#pragma unroll
    for (int p=0;p<4;p++)
        arp[p] = A + (long)gidx[m0 + lrow + p*32]*(long)K;
    int bnk = tid>>5;
    int bn4 = (tid&31)*4;

    auto load_tile = [&](int st, int k0) {
        uint32_t* As = smp + st*STG_WORDS;
        uint32_t* Bs = As + AWORDS;
#pragma unroll
        for (int p=0;p<4;p++) {
            int gk = k0 + akq;
            int bytes = (K - gk)*4; bytes = bytes<0?0:(bytes>16?16:bytes);
            const float* src = bytes ? (arp[p] + gk) : A;
            cpa16(s2u(&As[(lrow + p*32)*ASTR + akq]), src, bytes);
        }
#pragma unroll
        for (int p=0;p<4;p++) {
            int k = bnk + p*8;
            int ok = ((k0+k) < K) && ((n0+bn4) < N);
            const float* src = ok ? (W + (long)(k0+k)*N + n0 + bn4) : W;
            cpa16(s2u(&Bs[k*BSTR + bn4]), src, ok ? 16 : 0);
        }
    };
    auto compute = [&](int st) {
        const uint32_t* As = smp + st*STG_WORDS;
        const uint32_t* Bs = As + AWORDS;
#pragma unroll
        for (int ks=0;ks<4;ks++) {
            uint32_t a[4][4], b[4][2];
#pragma unroll
            for (int mt=0;mt<4;mt++) {
                int base = (wm + mt*16 + g)*ASTR + ks*8 + tig;
                a[mt][0] = As[base];
                a[mt][1] = As[base + 8*ASTR];
                a[mt][2] = As[base + 4];
                a[mt][3] = As[base + 8*ASTR + 4];
            }
#pragma unroll
            for (int nt=0;nt<4;nt++) {
                int base = (ks*8 + tig)*BSTR + wn + nt*8 + g;
                b[nt][0] = Bs[base];
                b[nt][1] = Bs[base + 4*BSTR];
            }
#pragma unroll
            for (int mt=0;mt<4;mt++)
#pragma unroll
                for (int nt=0;nt<4;nt++)
                    mma_tf32(c[mt][nt], a[mt], b[nt]);
        }
    };

    int ktn = (K+31)>>5;
    load_tile(0, 0);
    asm volatile("cp.async.commit_group;");
    if (ktn > 1) load_tile(1, 32);
    asm volatile("cp.async.commit_group;");
    for (int kt=0; kt<ktn; kt++) {
        asm volatile("cp.async.wait_group 1;");
        __syncthreads();
        if (kt+2 < ktn) load_tile((kt+2)%3, (kt+2)*32);
        asm volatile("cp.async.commit_group;");
        compute(kt%3);
        __syncthreads();
    }

#pragma unroll
    for (int mt=0;mt<4;mt++) {
        long m = m0 + wm + mt*16 + g;
#pragma unroll
        for (int nt=0;nt<4;nt++) {
            int n = n0 + wn + nt*8 + tig*2;
            if (n < N) {
                float bx = bias[n], by = bias[n+1];
                *(__half2*)&C[m*ldc + n] = __floats2half2_rn(c[mt][nt][0]+bx, c[mt][nt][1]+by);
                *(__half2*)&C[(m+8)*ldc + n] = __floats2half2_rn(c[mt][nt][2]+bx, c[mt][nt][3]+by);
            }
        }
    }
}

// ---------------------------------------------------------------------------
// FP16 NT GEMM. OUT16: 0 = fp32 C, 1 = fp16 C.
// MODE 0: generic z-batched; MODE 1: A shared per 2 z (GRU);
// MODE 2: merged ac/vid proj.
// ---------------------------------------------------------------------------
#define HSTR 20
#define HA_WORDS (128*HSTR)
#define HSTG (2*HA_WORDS)

template<int MODE, int OUT16>
__launch_bounds__(256, 2)
__global__ void gemm_h(const __half* __restrict__ A, const __half* __restrict__ B,
                       const float* __restrict__ bias, void* __restrict__ Cv,
                       int M, int N, int K,
                       long sA, long sB, long sBias, long sC, int ldc,
                       const float* __restrict__ bias2)
{
    extern __shared__ uint32_t smp[];
    int z = blockIdx.z;
    const __half *Ab, *Bp;
    const float* bp;
    if (MODE == 2) {
        K  = z ? 64 : 96;
        Ab = z ? (A + (long)BS*96) : A;
        Bp = z ? (B + 128*96) : B;
        bp = z ? bias2 : bias;
    } else {
        Ab = A + (MODE==1 ? (long)(z>>1)*sA : (long)z*sA);
        Bp = B + (long)z*sB;
        bp = bias + (long)z*sBias;
    }

    int m0 = blockIdx.y*128, n0 = blockIdx.x*128;
    int tid = threadIdx.x;
    int warp = tid>>5, lane = tid&31;
    int g = lane>>2, tig = lane&3;
    int wm = (warp&1)*64, wn = (warp>>1)*32;

    float c[4][4][4];
#pragma unroll
    for (int mt=0;mt<4;mt++)
#pragma unroll
        for (int nt=0;nt<4;nt++)
#pragma unroll
            for (int i=0;i<4;i++) c[mt][nt][i]=0.f;

    int lrow = tid>>1;
    int lseg = (tid&1)*8;
    const __half* arow = Ab + (long)(m0+lrow)*K;
    const __half* brow = Bp + (long)(n0+lrow)*K;
    bool bok = (n0+lrow) < N;

    auto load_tile = [&](int st, int k0) {
        uint32_t* As = smp + st*HSTG;
        uint32_t* Bs = As + HA_WORDS;
        cpa16(s2u(&As[lrow*HSTR + lseg]),     arow + k0 + lseg*2,     16);
        cpa16(s2u(&As[lrow*HSTR + lseg + 4]), arow + k0 + lseg*2 + 8, 16);
        cpa16(s2u(&Bs[lrow*HSTR + lseg]),     bok ? (brow + k0 + lseg*2)     : brow, bok?16:0);
        cpa16(s2u(&Bs[lrow*HSTR + lseg + 4]), bok ? (brow + k0 + lseg*2 + 8) : brow, bok?16:0);
    };
    auto compute = [&](int st) {
        const uint32_t* As = smp + st*HSTG;
        const uint32_t* Bs = As + HA_WORDS;
#pragma unroll
        for (int ks=0;ks<2;ks++) {
            uint32_t a[4][4], b[4][2];
#pragma unroll
            for (int mt=0;mt<4;mt++) {
                int base = (wm + mt*16 + g)*HSTR + ks*8 + tig;
                a[mt][0] = As[base];
                a[mt][1] = As[base + 8*HSTR];
                a[mt][2] = As[base + 4];
                a[mt][3] = As[base + 8*HSTR + 4];
            }
#pragma unroll
            for (int nt=0;nt<4;nt++) {
                int base = (wn + nt*8 + g)*HSTR + ks*8 + tig;
                b[nt][0] = Bs[base];
                b[nt][1] = Bs[base + 4];
            }
#pragma unroll
            for (int mt=0;mt<4;mt++)
#pragma unroll
                for (int nt=0;nt<4;nt++)
                    mma_f16(c[mt][nt], a[mt], b[nt]);
        }
    };

    int ktn = K>>5;
    load_tile(0, 0);
    asm volatile("cp.async.commit_group;");
    if (ktn > 1) load_tile(1, 32);
    asm volatile("cp.async.commit_group;");
    for (int kt=0; kt<ktn; kt++) {
        asm volatile("cp.async.wait_group 1;");
        __syncthreads();
        if (kt+2 < ktn) load_tile((kt+2)%3, (kt+2)*32);
        asm volatile("cp.async.commit_group;");
        compute(kt%3);
        __syncthreads();
    }

#pragma unroll
    for (int mt=0;mt<4;mt++) {
        long m = m0 + wm + mt*16 + g;
#pragma unroll
        for (int nt=0;nt<4;nt++) {
            int n = n0 + wn + nt*8 + tig*2;
            if (n < N) {
                float bx = bp[n], by = bp[n+1];
                float v00 = c[mt][nt][0]+bx, v01 = c[mt][nt][1]+by;
                float v10 = c[mt][nt][2]+bx, v11 = c[mt][nt][3]+by;
                if (OUT16) {
                    __half* Cb = (__half*)Cv + (long)z*sC;
                    *(__half2*)&Cb[m*ldc + n] = __floats2half2_rn(v00, v01);
                    *(__half2*)&Cb[(m+8)*ldc + n] = __floats2half2_rn(v10, v11);
                } else {
                    float* Cb = (float*)Cv + (long)z*sC;
                    float2 v0; v0.x = v00; v0.y = v01;
                    float2 v1; v1.x = v10; v1.y = v11;
                    *(float2*)&Cb[m*ldc + n] = v0;
                    *(float2*)&Cb[(m+8)*ldc + n] = v1;
                }
            }
        }
    }
}

// ---------------------------------------------------------------------------
// Fused fp16 QK^T + softmax -> P_h. Block tile 64x256, warp tile 32x64,
// 2 CTAs/SM. grid (1, 4, 384).
// ---------------------------------------------------------------------------
#define QA64 (64*HSTR)
#define QB256 (256*HSTR)
#define Q64_STG (QA64 + QB256)

__launch_bounds__(256, 2)
__global__ void qk_softmax_h(const __half* __restrict__ x, __half* __restrict__ P,
                             float scale)
{
    extern __shared__ uint32_t smp[];
    const int qtab[6]  = {0,0,1,1,2,2};
    const int kvtab[6] = {1,2,0,2,0,1};

    int z = blockIdx.z;
    int p = z>>6, b = z&63;
    const __half* Ab = x + ((long)qtab[p]*BS + (long)b*Ss)*128;
    const __half* Bp = x + ((long)kvtab[p]*BS + (long)b*Ss)*128;
    __half* Cb = P + (long)z*Ss*Ss;
    int m0 = blockIdx.y*64;
    int tid = threadIdx.x;
    int warp = tid>>5, lane = tid&31;
    int g = lane>>2, tig = lane&3;
    int wm = (warp&1)*32, wn = (warp>>1)*64;

    float c[2][8][4];
#pragma unroll
    for (int mt=0;mt<2;mt++)
#pragma unroll
        for (int nt=0;nt<8;nt++)
#pragma unroll
            for (int i=0;i<4;i++) c[mt][nt][i]=0.f;

    int arow_i = tid>>2;
    int aseg = (tid&3)*4;
    const __half* arow = Ab + (long)(m0+arow_i)*128;
    const __half* brow = Bp + (long)tid*128;

    auto load_tile = [&](int st, int k0) {
        uint32_t* As = smp + st*Q64_STG;
        uint32_t* Bs = As + QA64;
        cpa16(s2u(&As[arow_i*HSTR + aseg]), arow + k0 + aseg*2, 16);
#pragma unroll
        for (int h=0;h<4;h++)
            cpa16(s2u(&Bs[tid*HSTR + h*4]), brow + k0 + h*8, 16);
    };
    auto compute = [&](int st) {
        const uint32_t* As = smp + st*Q64_STG;
        const uint32_t* Bs = As + QA64;
#pragma unroll
        for (int ks=0;ks<2;ks++) {
            uint32_t a[2][4], bb[8][2];
#pragma unroll
            for (int mt=0;mt<2;mt++) {
                int base = (wm + mt*16 + g)*HSTR + ks*8 + tig;
                a[mt][0] = As[base];
                a[mt][1] = As[base + 8*HSTR];
                a[mt][2] = As[base + 4];
                a[mt][3] = As[base + 8*HSTR + 4];
            }
#pragma unroll
            for (int nt=0;nt<8;nt++) {
                int base = (wn + nt*8 + g)*HSTR + ks*8 + tig;
                bb[nt][0] = Bs[base];
                bb[nt][1] = Bs[base + 4];
            }
#pragma unroll
            for (int mt=0;mt<2;mt++)
#pragma unroll
                for (int nt=0;nt<8;nt++)
                    mma_f16(c[mt][nt], a[mt], bb[nt]);
        }
    };

    load_tile(0, 0);
    asm volatile("cp.async.commit_group;");
    load_tile(1, 32);
    asm volatile("cp.async.commit_group;");
    for (int kt=0; kt<4; kt++) {
        asm volatile("cp.async.wait_group 1;");
        __syncthreads();
        if (kt+2 < 4) load_tile((kt+2)%3, (kt+2)*32);
        asm volatile("cp.async.commit_group;");
        compute(kt%3);
        __syncthreads();
    }

#pragma unroll
    for (int mt=0;mt<2;mt++)
#pragma unroll
        for (int nt=0;nt<8;nt++)
#pragma unroll
            for (int i=0;i<4;i++) c[mt][nt][i] *= scale;

    float* red = (float*)smp;
    int wcol = warp>>1;
    float rmax[2][2], rinv[2][2];

#pragma unroll
    for (int mt=0;mt<2;mt++)
#pragma unroll
        for (int h=0;h<2;h++) {
            float m = -1e30f;
#pragma unroll
            for (int nt=0;nt<8;nt++)
                m = fmaxf(m, fmaxf(c[mt][nt][2*h], c[mt][nt][2*h+1]));
            m = fmaxf(m, __shfl_xor_sync(0xffffffffu, m, 1));
            m = fmaxf(m, __shfl_xor_sync(0xffffffffu, m, 2));
            if (tig == 0) red[(wm + mt*16 + g + h*8)*4 + wcol] = m;
        }
    __syncthreads();
#pragma unroll
    for (int mt=0;mt<2;mt++)
#pragma unroll
        for (int h=0;h<2;h++) {
            int r = wm + mt*16 + g + h*8;
            rmax[mt][h] = fmaxf(fmaxf(red[r*4], red[r*4+1]),
                                fmaxf(red[r*4+2], red[r*4+3]));
        }
    __syncthreads();
#pragma unroll
    for (int mt=0;mt<2;mt++)
#pragma unroll
        for (int h=0;h<2;h++) {
            float s = 0.f;
#pragma unroll
            for (int nt=0;nt<8;nt++) {
                float e0 = __expf(c[mt][nt][2*h]   - rmax[mt][h]);
                float e1 = __expf(c[mt][nt][2*h+1] - rmax[mt][h]);
                c[mt][nt][2*h]   = e0;
                c[mt][nt][2*h+1] = e1;
                s += e0 + e1;
            }
            s += __shfl_xor_sync(0xffffffffu, s, 1);
            s += __shfl_xor_sync(0xffffffffu, s, 2);
            if (tig == 0) red[(wm + mt*16 + g + h*8)*4 + wcol] = s;
        }
    __syncthreads();
#pragma unroll
    for (int mt=0;mt<2;mt++)
#pragma unroll
        for (int h=0;h<2;h++) {
            int r = wm + mt*16 + g + h*8;
            rinv[mt][h] = 1.f/(red[r*4] + red[r*4+1] + red[r*4+2] + red[r*4+3]);
        }
#pragma unroll
    for (int mt=0;mt<2;mt++)
#pragma unroll
        for (int h=0;h<2;h++) {
            long row = m0 + wm + mt*16 + g + h*8;
#pragma unroll
            for (int nt=0;nt<8;nt++) {
                int col = wn + nt*8 + tig*2;
                *(__half2*)&Cb[row*256 + col] =
                    __floats2half2_rn(c[mt][nt][2*h]   * rinv[mt][h],
                                      c[mt][nt][2*h+1] * rinv[mt][h]);
            }
        }
}

// ---------------------------------------------------------------------------
// Merged PV: base read from x_h (fp16), writes tstep_h only.
// ---------------------------------------------------------------------------
__launch_bounds__(256, 2)
__global__ void pv_h(const __half* __restrict__ P, const __half* __restrict__ xT,
                     const __half* __restrict__ x_h, __half* __restrict__ tstep_h)
{
    extern __shared__ uint32_t smp[];
    const int kvtab[6] = {1,2,0,2,0,1};
    int z = blockIdx.z;
    int qq = z>>6, b = z&63;
    const __half* baseq = x_h + ((long)qq*BS + (long)b*Ss)*128;
    __half* Ch = tstep_h + (long)qq*128 + (long)b*Ss*384;

    int m0 = blockIdx.y*128;
    int tid = threadIdx.x;
    int warp = tid>>5, lane = tid&31;
    int g = lane>>2, tig = lane&3;
    int wm = (warp&1)*64, wn = (warp>>1)*32;

    float c[4][4][4];
#pragma unroll
    for (int mt=0;mt<4;mt++)
#pragma unroll
        for (int nt=0;nt<4;nt++)
#pragma unroll
            for (int i=0;i<4;i++) c[mt][nt][i]=0.f;

    int lrow = tid>>1;
    int lseg = (tid&1)*8;

    auto load_tile = [&](int st, int gk) {
        int p = 2*qq + (gk>>3);
        int k0 = (gk&7)*32;
        const __half* ar = P + ((long)p*64 + b)*(long)Ss*Ss + (long)(m0+lrow)*Ss + k0;
        const __half* br = xT + ((long)kvtab[p]*64 + b)*128l*Ss + (long)lrow*Ss + k0;
        uint32_t* As = smp + st*HSTG;
        uint32_t* Bs = As + HA_WORDS;
        cpa16(s2u(&As[lrow*HSTR + lseg]),     ar + lseg*2,     16);
        cpa16(s2u(&As[lrow*HSTR + lseg + 4]), ar + lseg*2 + 8, 16);
        cpa16(s2u(&Bs[lrow*HSTR + lseg]),     br + lseg*2,     16);
        cpa16(s2u(&Bs[lrow*HSTR + lseg + 4]), br + lseg*2 + 8, 16);
    };
    auto compute = [&](int st) {
        const uint32_t* As = smp + st*HSTG;
        const uint32_t* Bs = As + HA_WORDS;
#pragma unroll
        for (int ks=0;ks<2;ks++) {
            uint32_t a[4][4], bb[4][2];
#pragma unroll
            for (int mt=0;mt<4;mt++) {
                int base = (wm + mt*16 + g)*HSTR + ks*8 + tig;
                a[mt][0] = As[base];
                a[mt][1] = As[base + 8*HSTR];
                a[mt][2] = As[base + 4];
                a[mt][3] = As[base + 8*HSTR + 4];
            }
#pragma unroll
            for (int nt=0;nt<4;nt++) {
                int base = (wn + nt*8 + g)*HSTR + ks*8 + tig;
                bb[nt][0] = Bs[base];
                bb[nt][1] = Bs[base + 4];
            }
#pragma unroll
            for (int mt=0;mt<4;mt++)
#pragma unroll
                for (int nt=0;nt<4;nt++)
                    mma_f16(c[mt][nt], a[mt], bb[nt]);
        }
    };

    load_tile(0, 0);
    asm volatile("cp.async.commit_group;");
    load_tile(1, 1);
    asm volatile("cp.async.commit_group;");
    for (int gk=0; gk<16; gk++) {
        asm volatile("cp.async.wait_group 1;");
        __syncthreads();
        if (gk+2 < 16) load_tile((gk+2)%3, gk+2);
        asm volatile("cp.async.commit_group;");
        compute(gk%3);
        __syncthreads();
    }

#pragma unroll
    for (int mt=0;mt<4;mt++) {
        long m = m0 + wm + mt*16 + g;
#pragma unroll
        for (int nt=0;nt<4;nt++) {
            int n = wn + nt*8 + tig*2;
            float2 b0 = __half22float2(*(const __half2*)&baseq[m*128 + n]);
            float2 b1 = __half22float2(*(const __half2*)&baseq[(m+8)*128 + n]);
            *(__half2*)&Ch[m*384 + n] =
                __floats2half2_rn(c[mt][nt][0]+b0.x, c[mt][nt][1]+b0.y);
            *(__half2*)&Ch[(m+8)*384 + n] =
                __floats2half2_rn(c[mt][nt][2]+b1.x, c[mt][nt][3]+b1.y);
        }
    }
}

// ---------------------------------------------------------------------------
// biGRU (R9 layout, fp16 xg, 4 accumulator chains).
// ---------------------------------------------------------------------------
__launch_bounds__(192, 3)
__global__ void gru_rec(const __half* __restrict__ xg_all, const float* __restrict__ Wh,
                        const float* __restrict__ bh, __half* __restrict__ x_h)
{
    int bx = blockIdx.x;
    int m = bx>>7, d = (bx>>6)&1, b = bx&63, md = m*2+d;
    int j = threadIdx.x;
    ull w2[32];
#pragma unroll
    for (int q=0;q<32;q++)
        w2[q] = pk(Wh[((long)md*64 + 2*q)*192 + j], Wh[((long)md*64 + 2*q+1)*192 + j]);
    float bhj = bh[md*192 + j];
    __shared__ alignas(16) float h_s[64];
    __shared__ float pre_s[192], xn_s[64];
    uint32_t hsa = s2u(h_s);
    if (j<64) h_s[j]=0.f;
    const __half* xg = xg_all + ((long)md*BS + (long)b*Ss)*192;
    int s0 = d ? (Ss-1) : 0;
    float xg_cur = __half2float(xg[(long)s0*192 + j]);
    for (int t=0;t<Ss;t++) {
        int s = d ? (Ss-1-t) : t;
        int sn = d ? (Ss-2-t) : (t+1);
        sn = sn < 0 ? 0 : (sn > Ss-1 ? Ss-1 : sn);
        __syncthreads();
        float xg_nxt = __half2float(xg[(long)sn*192 + j]);
        ull a0 = pk(bhj, 0.f), a1 = 0ull, a2 = 0ull, a3 = 0ull;
#pragma unroll
        for (int q=0;q<8;q++) {
            ull h0,h1,h2,h3;
            lds2x64(h0,h1, hsa + (2*q)*16);
            lds2x64(h2,h3, hsa + (2*q+1)*16);
            ffma2(a0, h0, w2[4*q]);
            ffma2(a1, h1, w2[4*q+1]);
            ffma2(a2, h2, w2[4*q+2]);
            ffma2(a3, h3, w2[4*q+3]);
        }
        float2 f0 = upk(a0), f1 = upk(a1), f2 = upk(a2), f3 = upk(a3);
        float acc = (f0.x + f0.y) + (f1.x + f1.y) + (f2.x + f2.y) + (f3.x + f3.y);
        float xgv = xg_cur;
        if (j<128) pre_s[j] = acc + xgv;
        else { pre_s[j] = acc; xn_s[j-128] = xgv; }
        __syncthreads();
        if (j<64) {
            float r = sigf(pre_s[j]);
            float zg = sigf(pre_s[64+j]);
            float n = tanhfast(xn_s[j] + r*pre_s[128+j]);
            float hn = (1.f-zg)*n + zg*h_s[j];
            h_s[j] = hn;
            long row = (long)b*Ss + s;
            x_h[((long)m*BS + row)*128 + d*64 + j] = __float2half(hn);
        }
        xg_cur = xg_nxt;
    }
}

// ---------------------------------------------------------------------------
// biLSTM (R9 layout, fp16 xg, 4 accumulator chains).
// ---------------------------------------------------------------------------
__launch_bounds__(512, 1)
__global__ void lstm_rec(const __half* __restrict__ xg_all, const float* __restrict__ Wh,
                         const float* __restrict__ bh, __half* __restrict__ sf_h)
{
    extern __shared__ unsigned char smraw[];
    ull*   Wlo2  = (ull*)smraw;
    float* h_s   = (float*)(smraw + 16*512*8);
    float* pre_s = (float*)(smraw + 16*512*8 + 512);
    int bx = blockIdx.x, d = bx>>6, b = bx&63;
    int j = threadIdx.x;
    const float* Whd = Wh + (long)d*128*512;
    ull w2[48];
#pragma unroll
    for (int q=0;q<48;q++)
        w2[q] = pk(Whd[(long)(2*q)*512 + j], Whd[(long)(2*q+1)*512 + j]);
    for (int q=0;q<16;q++)
        Wlo2[q*512 + j] = pk(Whd[(long)(96+2*q)*512 + j], Whd[(long)(97+2*q)*512 + j]);
    float bhj = bh[d*512 + j];
    float c = 0.f;
    if (j<128) h_s[j]=0.f;
    uint32_t hsa = s2u(h_s);
    const __half* xg = xg_all + ((long)d*BS + (long)b*Ss)*512;
    int s0 = d ? (Ss-1) : 0;
    float xg_cur = __half2float(xg[(long)s0*512 + j]);
    for (int t=0;t<Ss;t++) {
        int s = d ? (Ss-1-t) : t;
        int sn = d ? (Ss-2-t) : (t+1);
        sn = sn < 0 ? 0 : (sn > Ss-1 ? Ss-1 : sn);
        __syncthreads();
        float xg_nxt = __half2float(xg[(long)sn*512 + j]);
        ull a0 = pk(bhj, 0.f), a1 = 0ull, a2 = 0ull, a3 = 0ull;
#pragma unroll
        for (int q=0;q<12;q++) {
            ull h0,h1,h2,h3;
            lds2x64(h0,h1, hsa + (2*q)*16);
            lds2x64(h2,h3, hsa + (2*q+1)*16);
            ffma2(a0, h0, w2[4*q]);
            ffma2(a1, h1, w2[4*q+1]);
            ffma2(a2, h2, w2[4*q+2]);
            ffma2(a3, h3, w2[4*q+3]);
        }
#pragma unroll
        for (int q=0;q<4;q++) {
            ull h0,h1,h2,h3;
            lds2x64(h0,h1, hsa + 384 + (2*q)*16);
            lds2x64(h2,h3, hsa + 384 + (2*q+1)*16);
            ffma2(a0, h0, Wlo2[(4*q)*512 + j]);
            ffma2(a1, h1, Wlo2[(4*q+1)*512 + j]);
            ffma2(a2, h2, Wlo2[(4*q+2)*512 + j]);
            ffma2(a3, h3, Wlo2[(4*q+3)*512 + j]);
        }
        float2 f0 = upk(a0), f1 = upk(a1), f2 = upk(a2), f3 = upk(a3);
        float acc = (f0.x + f0.y) + (f1.x + f1.y) + (f2.x + f2.y) + (f3.x + f3.y) + xg_cur;
        pre_s[j] = acc;
        __syncthreads();
        if (j<128) {
            float ig = pre_s[j], fg = pre_s[128+j], gg = pre_s[256+j], og = pre_s[384+j];
            c = sigf(fg)*c + sigf(ig)*tanhfast(gg);
            float h = sigf(og)*tanhfast(c);
            h_s[j] = h;
            sf_h[((long)b*Ss + s)*256 + d*128 + j] = __float2half(h);
        }
        xg_cur = xg_nxt;
    }
}

// ---------------------------------------------------------------------------
// RGN (R9 layout, fp16 xg, 4 accumulator chains).
// ---------------------------------------------------------------------------
__launch_bounds__(384, 1)
__global__ void rgn_rec(const __half* __restrict__ xg_all, const float* __restrict__ Wh,
                        const float* __restrict__ state0, const float* __restrict__ state1,
                        float* __restrict__ outbuf)
{
    __shared__ alignas(16) float h_s[128];
    __shared__ float pre_s[384], xn_s[128];
    int bx = blockIdx.x, kk = bx>>6, b = bx&63;
    int j = threadIdx.x;
    const float* Whd = Wh + (long)kk*128*384;
    ull w2[64];
#pragma unroll
    for (int q=0;q<64;q++)
        w2[q] = pk(Whd[(long)(2*q)*384 + j], Whd[(long)(2*q+1)*384 + j]);
    if (j<128) h_s[j] = (kk==0?state0:state1)[b*128 + j];
    uint32_t hsa = s2u(h_s);
    const __half* xg = xg_all + ((long)kk*BS + (long)b*Ss)*384;
    int s0 = kk ? (Ss-1) : 0;
    float xg_cur = __half2float(xg[(long)s0*384 + j]);
    for (int t=0;t<Ss;t++) {
        int sn = kk ? (Ss-2-t) : (t+1);
        sn = sn < 0 ? 0 : (sn > Ss-1 ? Ss-1 : sn);
        __syncthreads();
        float xg_nxt = __half2float(xg[(long)sn*384 + j]);
        ull a0 = 0ull, a1 = 0ull, a2 = 0ull, a3 = 0ull;
#pragma unroll
        for (int q=0;q<16;q++) {
            ull h0,h1,h2,h3;
            lds2x64(h0,h1, hsa + (2*q)*16);
            lds2x64(h2,h3, hsa + (2*q+1)*16);
            ffma2(a0, h0, w2[4*q]);
            ffma2(a1, h1, w2[4*q+1]);
            ffma2(a2, h2, w2[4*q+2]);
            ffma2(a3, h3, w2[4*q+3]);
        }
        float2 f0 = upk(a0), f1 = upk(a1), f2 = upk(a2), f3 = upk(a3);
        float acc = (f0.x + f0.y) + (f1.x + f1.y) + (f2.x + f2.y) + (f3.x + f3.y);
        float xgv = xg_cur;
        if (j<256) pre_s[j] = acc + xgv;
        else { pre_s[j] = acc; xn_s[j-256] = xgv; }
        __syncthreads();
        if (j<128) {
            float r = sigf(pre_s[j]);
            float z = sigf(pre_s[128+j]);
            float n = tanhfast(xn_s[j] + r*pre_s[256+j]);
            h_s[j] = (1.f-z)*n + z*h_s[j];
        }
        xg_cur = xg_nxt;
    }
    __syncthreads();
    if (j<128) outbuf[((long)kk*64 + b)*128 + j] = h_s[j];
}

__launch_bounds__(32)
__global__ void final_fc(const float* __restrict__ outbuf,
                         const float* __restrict__ fc1W, const float* __restrict__ fc1b,
                         const float* __restrict__ fc2W, const float* __restrict__ fc2b,
                         float* __restrict__ out)
{
    int b = blockIdx.x, t = threadIdx.x;
    float acc = fc1b[t];
    for (int k=0;k<128;k++) {
        float x = outbuf[b*128+k] + outbuf[64*128 + b*128 + k];
        acc += x * fc1W[k*32 + t];
    }
    float h = acc > 0.f ? acc : 0.01f*acc;
    float v = h * fc2W[t];
#pragma unroll
    for (int o=16;o;o>>=1) v += __shfl_xor_sync(0xffffffffu, v, o);
    if (t==0) out[b] = v + fc2b[0];
}

extern "C" void kernel_launch(void* const* d_in, const int* in_sizes, int n_in,
                              void* d_out, int out_size)
{
    (void)in_sizes; (void)n_in; (void)out_size;
    const int*   sentences = (const int*)  d_in[0];
    const float* acoustic  = (const float*)d_in[1];
    const float* video     = (const float*)d_in[2];
    const float* state0    = (const float*)d_in[3];
    const float* state1    = (const float*)d_in[4];
    const float* emb       = (const float*)d_in[5];
    const float* proj_l_W  = (const float*)d_in[6];
    const float* proj_l_b  = (const float*)d_in[7];
    const float* proj_a_W  = (const float*)d_in[8];
    const float* proj_a_b  = (const float*)d_in[9];
    const float* proj_v_W  = (const float*)d_in[10];
    const float* proj_v_b  = (const float*)d_in[11];
    const float* gru_Wi    = (const float*)d_in[12];
    const float* gru_Wh    = (const float*)d_in[13];
    const float* gru_bi    = (const float*)d_in[14];
    const float* gru_bh    = (const float*)d_in[15];
    const float* lstm_Wi   = (const float*)d_in[16];
    const float* lstm_Wh   = (const float*)d_in[17];
    const float* lstm_bi   = (const float*)d_in[18];
    const float* lstm_bh   = (const float*)d_in[19];
    const float* rgn_Wx    = (const float*)d_in[20];
    const float* rgn_Wh    = (const float*)d_in[21];
    const float* rgn_b     = (const float*)d_in[22];
    const float* fc1_W     = (const float*)d_in[23];
    const float* fc1_b     = (const float*)d_in[24];
    const float* fc2_W     = (const float*)d_in[25];
    const float* fc2_b     = (const float*)d_in[26];
    float* out = (float*)d_out;

    float *rgn_out;
    __half *xg_gru,*xg_lstm,*xg_rgn;
    __half *seq_h,*x_h,*xT_h,*P_h,*tstep_h,*sf_h,*WT_h,*av_h;
    cudaGetSymbolAddress((void**)&xg_gru, g_xg_gru);
    cudaGetSymbolAddress((void**)&xg_lstm, g_xg_lstm);
    cudaGetSymbolAddress((void**)&xg_rgn, g_xg_rgn);
    cudaGetSymbolAddress((void**)&rgn_out, g_rgn_out);
    cudaGetSymbolAddress((void**)&seq_h, g_seq_h);
    cudaGetSymbolAddress((void**)&x_h, g_x_h);
    cudaGetSymbolAddress((void**)&xT_h, g_xT_h);
    cudaGetSymbolAddress((void**)&P_h, g_P_h);
    cudaGetSymbolAddress((void**)&tstep_h, g_tstep_h);
    cudaGetSymbolAddress((void**)&sf_h, g_sf_h);
    cudaGetSymbolAddress((void**)&WT_h, g_WT_h);
    cudaGetSymbolAddress((void**)&av_h, g_av_h);
    __half* gruT  = WT_h;
    __half* lstmT = gruT + 6*192*128;
    __half* rgnT  = lstmT + 2l*512*384;
    __half* projaT = rgnT + 2l*384*256;

    const size_t shm_tf3 = 3u*STG_WORDS*4u;
    const size_t shm_h   = 3u*HSTG*4u;
    const size_t shm_qk  = 3u*Q64_STG*4u;
    cudaFuncSetAttribute(gemm_tf, cudaFuncAttributeMaxDynamicSharedMemorySize, (int)shm_tf3);
    cudaFuncSetAttribute(gemm_h<0,1>, cudaFuncAttributeMaxDynamicSharedMemorySize, (int)shm_h);
    cudaFuncSetAttribute(gemm_h<1,1>, cudaFuncAttributeMaxDynamicSharedMemorySize, (int)shm_h);
    cudaFuncSetAttribute(gemm_h<2,1>, cudaFuncAttributeMaxDynamicSharedMemorySize, (int)shm_h);
    cudaFuncSetAttribute(qk_softmax_h, cudaFuncAttributeMaxDynamicSharedMemorySize, (int)shm_qk);
    cudaFuncSetAttribute(pv_h, cudaFuncAttributeMaxDynamicSharedMemorySize, (int)shm_h);
    cudaFuncSetAttribute(lstm_rec, cudaFuncAttributeMaxDynamicSharedMemorySize, 72*1024);

    // prep (2 launches)
    wtrans_all<<<740, dim3(32,8)>>>(gru_Wi, lstm_Wi, rgn_Wx, proj_a_W, proj_v_W, WT_h);
    conv2<<<1024, 256>>>(acoustic, video, av_h);

    // modality projections -> seq_h
    gemm_tf<<<dim3(1, BS/128, 1), 256, shm_tf3>>>(
        emb, proj_l_W, proj_l_b, seq_h, BS, 128, DL, 128, sentences);
    gemm_h<2,1><<<dim3(1, BS/128, 2), 256, shm_h>>>(
        av_h, projaT, proj_a_b, seq_h + 1l*BS*DH, BS, 128, 0,
        0, 0, 0, (long)BS*DH, 128, proj_v_b);

    // GRU input projections (z=6) -> fp16 xg
    gemm_h<1,1><<<dim3(2, BS/128, 6), 256, shm_h>>>(
        seq_h, gruT, gru_bi, xg_gru, BS, 192, 128,
        (long)BS*DH, 192l*128, 192, (long)BS*192, 192, nullptr);

    // biGRU (writes x_h only)
    gru_rec<<<3*2*64, 192>>>(xg_gru, gru_Wh, gru_bh, x_h);
    xtrans<<<dim3(192, 4), 256>>>(x_h, xT_h);

    // JCAF
    const float scale = 0.08838834764831845f;
    qk_softmax_h<<<dim3(1, 4, 384), 256, shm_qk>>>(x_h, P_h, scale);
    pv_h<<<dim3(1, 2, 192), 256, shm_h>>>(P_h, xT_h, x_h, tstep_h);

    // LSTM input projections (z=2) -> fp16 xg
    gemm_h<0,1><<<dim3(4, BS/128, 2), 256, shm_h>>>(
        tstep_h, lstmT, lstm_bi, xg_lstm, BS, 512, 384,
        0, 512l*384, 512, (long)BS*512, 512, nullptr);

    lstm_rec<<<2*64, 512, 16*512*8 + 512 + 2048>>>(xg_lstm, lstm_Wh, lstm_bh, sf_h);

    // RGN input projections (z=2) -> fp16 xg
    gemm_h<0,1><<<dim3(3, BS/128, 2), 256, shm_h>>>(
        sf_h, rgnT, rgn_b, xg_rgn, BS, 384, 256,
        0, 384l*256, 384, (long)BS*384, 384, nullptr);

    rgn_rec<<<2*64, 384>>>(xg_rgn, rgn_Wh, state0, state1, rgn_out);

    final_fc<<<Bb, 32>>>(rgn_out, fc1_W, fc1_b, fc2_W, fc2_b, out);
}

// round 16
// speedup vs baseline: 1.5013x; 1.1328x over previous
#include <cuda_runtime.h>
#include <cuda_fp16.h>
#include <math.h>
#include <stdint.h>

#define Bb 64
#define Ss 256
#define BS (Bb*Ss)
#define DL 300
#define DA 74
#define DV 35
#define DH 128

// fp32 scratch
__device__ float g_rgn_out[2u*Bb*128];
// fp16 scratch
__device__ __half g_xg_gru[6u*BS*192];
__device__ __half g_xg_lstm[2u*BS*512];
__device__ __half g_xg_rgn[2u*BS*384];
__device__ __half g_seq_h[3u*BS*DH];
__device__ __half g_x_h[3u*BS*DH];
__device__ __half g_xT_h[3u*(unsigned)Bb*128*Ss];
__device__ __half g_P_h[6u*(unsigned)Bb*Ss*Ss];
__device__ __half g_tstep_h[(unsigned)BS*384];
__device__ __half g_sf_h[(unsigned)BS*256];
__device__ __half g_av_h[(unsigned)BS*96 + (unsigned)BS*64];
__device__ __half g_WT_h[757760];

typedef unsigned long long ull;

__device__ __forceinline__ uint32_t s2u(const void* p) {
    return (uint32_t)__cvta_generic_to_shared(p);
}
__device__ __forceinline__ void cpa16(uint32_t dst, const void* src, int bytes) {
    asm volatile("cp.async.cg.shared.global [%0], [%1], 16, %2;"
                 :: "r"(dst), "l"(src), "r"(bytes));
}
__device__ __forceinline__ void mma_tf32(float c[4], const uint32_t a[4], const uint32_t b[2]) {
    asm volatile(
        "mma.sync.aligned.m16n8k8.row.col.f32.tf32.tf32.f32 "
        "{%0,%1,%2,%3}, {%4,%5,%6,%7}, {%8,%9}, {%0,%1,%2,%3};"
        : "+f"(c[0]), "+f"(c[1]), "+f"(c[2]), "+f"(c[3])
        : "r"(a[0]), "r"(a[1]), "r"(a[2]), "r"(a[3]), "r"(b[0]), "r"(b[1]));
}
__device__ __forceinline__ void mma_f16(float c[4], const uint32_t a[4], const uint32_t b[2]) {
    asm volatile(
        "mma.sync.aligned.m16n8k16.row.col.f32.f16.f16.f32 "
        "{%0,%1,%2,%3}, {%4,%5,%6,%7}, {%8,%9}, {%0,%1,%2,%3};"
        : "+f"(c[0]), "+f"(c[1]), "+f"(c[2]), "+f"(c[3])
        : "r"(a[0]), "r"(a[1]), "r"(a[2]), "r"(a[3]), "r"(b[0]), "r"(b[1]));
}
__device__ __forceinline__ ull pk(float x, float y) {
    ull r; asm("mov.b64 %0,{%1,%2};" : "=l"(r) : "f"(x), "f"(y)); return r;
}
__device__ __forceinline__ float2 upk(ull v) {
    float2 f; asm("mov.b64 {%0,%1},%2;" : "=f"(f.x), "=f"(f.y) : "l"(v)); return f;
}
__device__ __forceinline__ void ffma2(ull &d, ull a, ull b) {
    asm volatile("fma.rn.f32x2 %0, %1, %2, %0;" : "+l"(d) : "l"(a), "l"(b));
}
__device__ __forceinline__ void lds2x64(ull &a, ull &b, uint32_t addr) {
    asm volatile("ld.shared.v2.b64 {%0,%1},[%2];" : "=l"(a), "=l"(b) : "r"(addr));
}
__device__ __forceinline__ float tanhfast(float x) {
    float y; asm("tanh.approx.f32 %0,%1;" : "=f"(y) : "f"(x)); return y;
}
// sigmoid via tanh.approx: sigma(x) = 0.5*tanh(0.5x) + 0.5
__device__ __forceinline__ float sigf(float x) {
    return fmaf(tanhfast(0.5f*x), 0.5f, 0.5f);
}

// ---------------------------------------------------------------------------
// Prep: weight transposes [0,740) + input conversions [740,1252). One launch.
// ---------------------------------------------------------------------------
#define PREP_WT 740
#define PREP_CONV 512
__global__ void prep_all(const float* __restrict__ gru_Wi,
                         const float* __restrict__ lstm_Wi,
                         const float* __restrict__ rgn_Wx,
                         const float* __restrict__ pa,
                         const float* __restrict__ pv,
                         __half* __restrict__ WT,
                         const float* __restrict__ ac, const float* __restrict__ vid,
                         __half* __restrict__ av)
{
    int bid = blockIdx.x;
    int tx = threadIdx.x, ty = threadIdx.y;

    if (bid >= PREP_WT) {
        const long TOT_A = (long)BS*96;
        const long TOT_V = (long)BS*64;
        long t = (long)(bid - PREP_WT)*256 + ty*32 + tx;
        long stride = (long)PREP_CONV*256;
        for (long i = t; i < TOT_A + TOT_V; i += stride) {
            if (i < TOT_A) {
                long row = i/96; int k = (int)(i - row*96);
                av[i] = (k<74) ? __float2half(ac[row*74 + k]) : __float2half(0.f);
            } else {
                long j = i - TOT_A;
                long row = j/64; int k = (int)(j - row*64);
                av[TOT_A + j] = (k<35) ? __float2half(vid[row*35 + k]) : __float2half(0.f);
            }
        }
        return;
    }

    __half* gruT  = WT;
    __half* lstmT = gruT + 6*192*128;
    __half* rgnT  = lstmT + 2l*512*384;
    __half* projaT = rgnT + 2l*384*256;
    __half* projvT = projaT + 128*96;

    const float* in; __half* out;
    int K, N, KP, k0, n0;
    if (bid < 144) {
        int z = bid/24, rem = bid%24;
        K = 128; N = 192; KP = 128;
        k0 = (rem%4)*32; n0 = (rem/4)*32;
        in = gru_Wi + (long)z*K*N; out = gruT + (long)z*N*KP;
    } else if (bid < 528) {
        int b2 = bid-144; int z = b2/192, rem = b2%192;
        K = 384; N = 512; KP = 384;
        k0 = (rem%12)*32; n0 = (rem/12)*32;
        in = lstm_Wi + (long)z*K*N; out = lstmT + (long)z*N*KP;
    } else if (bid < 720) {
        int b2 = bid-528; int z = b2/96, rem = b2%96;
        K = 256; N = 384; KP = 256;
        k0 = (rem%8)*32; n0 = (rem/8)*32;
        in = rgn_Wx + (long)z*K*N; out = rgnT + (long)z*N*KP;
    } else if (bid < 732) {
        int rem = bid-720;
        K = 74; N = 128; KP = 96;
        k0 = (rem%3)*32; n0 = (rem/3)*32;
        in = pa; out = projaT;
    } else {
        int rem = bid-732;
        K = 35; N = 128; KP = 64;
        k0 = (rem%2)*32; n0 = (rem/2)*32;
        in = pv; out = projvT;
    }

    __shared__ float t[32][33];
#pragma unroll
    for (int i=0;i<32;i+=8) {
        int k = k0+ty+i, n = n0+tx;
        t[ty+i][tx] = (k<K && n<N) ? in[(long)k*N+n] : 0.f;
    }
    __syncthreads();
#pragma unroll
    for (int i=0;i<32;i+=8) {
        int n = n0+ty+i, k = k0+tx;
        if (n<N && k<KP) out[(long)n*KP+k] = __float2half(t[tx][ty+i]);
    }
}

// ---------------------------------------------------------------------------
// x_h -> xT_h transpose
// ---------------------------------------------------------------------------
__global__ void xtrans(const __half* __restrict__ xin, __half* __restrict__ xout)
{
    __shared__ __half sm[64][130];
    int mb = blockIdx.x;
    int m = mb>>6, b = mb&63;
    int s0 = blockIdx.y*64;
    int tid = threadIdx.x;
    const __half* src = xin + ((long)m*BS + (long)b*Ss + s0)*128;
#pragma unroll
    for (int i=0;i<32;i++) {
        int idx = tid + i*256;
        int s = idx>>7, d = idx&127;
        sm[s][d] = src[(long)s*128 + d];
    }
    __syncthreads();
    __half* dst = xout + (long)mb*128*Ss;
#pragma unroll
    for (int i=0;i<32;i++) {
        int idx = tid + i*256;
        int d = idx>>6, ss = idx&63;
        dst[(long)d*Ss + s0 + ss] = sm[ss][d];
    }
}

// ---------------------------------------------------------------------------
// TF32 GEMM (embedding projection only). fp16 output, 3-stage pipeline.
// ---------------------------------------------------------------------------
#define ASTR 36
#define BSTR 136
#define AWORDS (128*ASTR)
#define STG_WORDS (2*AWORDS)

__launch_bounds__(256, 2)
__global__ void gemm_tf(const float* __restrict__ A, const float* __restrict__ W,
                        const float* __restrict__ bias, __half* __restrict__ C,
                        int M, int N, int K, int ldc,
                        const int* __restrict__ gidx)
{
    extern __shared__ uint32_t smp[];
    int m0 = blockIdx.y*128, n0 = blockIdx.x*128;
    int tid = threadIdx.x;
    int warp = tid>>5, lane = tid&31;
    int g = lane>>2, tig = lane&3;
    int wm = (warp&1)*64, wn = (warp>>1)*32;

    float c[4][4][4];
#pragma unroll
    for (int mt=0;mt<4;mt++)
#pragma unroll
        for (int nt=0;nt<4;nt++)
#pragma unroll
            for (int i=0;i<4;i++) c[mt][nt][i]=0.f;

    int lrow = tid>>3;
    int akq  = (tid&7)*4;
    const float* arp[4];
#pragma unroll
    for (int p=0;p<4;p++)
        arp[p] = A + (long)gidx[m0 + lrow + p*32]*(long)K;
    int bnk = tid>>5;
    int bn4 = (tid&31)*4;

    auto load_tile = [&](int st, int k0) {
        uint32_t* As = smp + st*STG_WORDS;
        uint32_t* Bs = As + AWORDS;
#pragma unroll
        for (int p=0;p<4;p++) {
            int gk = k0 + akq;
            int bytes = (K - gk)*4; bytes = bytes<0?0:(bytes>16?16:bytes);
            const float* src = bytes ? (arp[p] + gk) : A;
            cpa16(s2u(&As[(lrow + p*32)*ASTR + akq]), src, bytes);
        }
#pragma unroll
        for (int p=0;p<4;p++) {
            int k = bnk + p*8;
            int ok = ((k0+k) < K) && ((n0+bn4) < N);
            const float* src = ok ? (W + (long)(k0+k)*N + n0 + bn4) : W;
            cpa16(s2u(&Bs[k*BSTR + bn4]), src, ok ? 16 : 0);
        }
    };
    auto compute = [&](int st) {
        const uint32_t* As = smp + st*STG_WORDS;
        const uint32_t* Bs = As + AWORDS;
#pragma unroll
        for (int ks=0;ks<4;ks++) {
            uint32_t a[4][4], b[4][2];
#pragma unroll
            for (int mt=0;mt<4;mt++) {
                int base = (wm + mt*16 + g)*ASTR + ks*8 + tig;
                a[mt][0] = As[base];
                a[mt][1] = As[base + 8*ASTR];
                a[mt][2] = As[base + 4];
                a[mt][3] = As[base + 8*ASTR + 4];
            }
#pragma unroll
            for (int nt=0;nt<4;nt++) {
                int base = (ks*8 + tig)*BSTR + wn + nt*8 + g;
                b[nt][0] = Bs[base];
                b[nt][1] = Bs[base + 4*BSTR];
            }
#pragma unroll
            for (int mt=0;mt<4;mt++)
#pragma unroll
                for (int nt=0;nt<4;nt++)
                    mma_tf32(c[mt][nt], a[mt], b[nt]);
        }
    };

    int ktn = (K+31)>>5;
    load_tile(0, 0);
    asm volatile("cp.async.commit_group;");
    if (ktn > 1) load_tile(1, 32);
    asm volatile("cp.async.commit_group;");
    for (int kt=0; kt<ktn; kt++) {
        asm volatile("cp.async.wait_group 1;");
        __syncthreads();
        if (kt+2 < ktn) load_tile((kt+2)%3, (kt+2)*32);
        asm volatile("cp.async.commit_group;");
        compute(kt%3);
        __syncthreads();
    }

#pragma unroll
    for (int mt=0;mt<4;mt++) {
        long m = m0 + wm + mt*16 + g;
#pragma unroll
        for (int nt=0;nt<4;nt++) {
            int n = n0 + wn + nt*8 + tig*2;
            if (n < N) {
                float bx = bias[n], by = bias[n+1];
                *(__half2*)&C[m*ldc + n] = __floats2half2_rn(c[mt][nt][0]+bx, c[mt][nt][1]+by);
                *(__half2*)&C[(m+8)*ldc + n] = __floats2half2_rn(c[mt][nt][2]+bx, c[mt][nt][3]+by);
            }
        }
    }
}

// ---------------------------------------------------------------------------
// FP16 NT GEMM. OUT16: 0 = fp32 C, 1 = fp16 C.
// MODE 0: generic z-batched; MODE 1: A shared per 2 z (GRU); MODE 2: av proj.
// ---------------------------------------------------------------------------
#define HSTR 20
#define HA_WORDS (128*HSTR)
#define HSTG (2*HA_WORDS)

template<int MODE, int OUT16>
__launch_bounds__(256, 2)
__global__ void gemm_h(const __half* __restrict__ A, const __half* __restrict__ B,
                       const float* __restrict__ bias, void* __restrict__ Cv,
                       int M, int N, int K,
                       long sA, long sB, long sBias, long sC, int ldc,
                       const float* __restrict__ bias2)
{
    extern __shared__ uint32_t smp[];
    int z = blockIdx.z;
    const __half *Ab, *Bp;
    const float* bp;
    if (MODE == 2) {
        K  = z ? 64 : 96;
        Ab = z ? (A + (long)BS*96) : A;
        Bp = z ? (B + 128*96) : B;
        bp = z ? bias2 : bias;
    } else {
        Ab = A + (MODE==1 ? (long)(z>>1)*sA : (long)z*sA);
        Bp = B + (long)z*sB;
        bp = bias + (long)z*sBias;
    }

    int m0 = blockIdx.y*128, n0 = blockIdx.x*128;
    int tid = threadIdx.x;
    int warp = tid>>5, lane = tid&31;
    int g = lane>>2, tig = lane&3;
    int wm = (warp&1)*64, wn = (warp>>1)*32;

    float c[4][4][4];
#pragma unroll
    for (int mt=0;mt<4;mt++)
#pragma unroll
        for (int nt=0;nt<4;nt++)
#pragma unroll
            for (int i=0;i<4;i++) c[mt][nt][i]=0.f;

    int lrow = tid>>1;
    int lseg = (tid&1)*8;
    const __half* arow = Ab + (long)(m0+lrow)*K;
    const __half* brow = Bp + (long)(n0+lrow)*K;
    bool bok = (n0+lrow) < N;

    auto load_tile = [&](int st, int k0) {
        uint32_t* As = smp + st*HSTG;
        uint32_t* Bs = As + HA_WORDS;
        cpa16(s2u(&As[lrow*HSTR + lseg]),     arow + k0 + lseg*2,     16);
        cpa16(s2u(&As[lrow*HSTR + lseg + 4]), arow + k0 + lseg*2 + 8, 16);
        cpa16(s2u(&Bs[lrow*HSTR + lseg]),     bok ? (brow + k0 + lseg*2)     : brow, bok?16:0);
        cpa16(s2u(&Bs[lrow*HSTR + lseg + 4]), bok ? (brow + k0 + lseg*2 + 8) : brow, bok?16:0);
    };
    auto compute = [&](int st) {
        const uint32_t* As = smp + st*HSTG;
        const uint32_t* Bs = As + HA_WORDS;
#pragma unroll
        for (int ks=0;ks<2;ks++) {
            uint32_t a[4][4], b[4][2];
#pragma unroll
            for (int mt=0;mt<4;mt++) {
                int base = (wm + mt*16 + g)*HSTR + ks*8 + tig;
                a[mt][0] = As[base];
                a[mt][1] = As[base + 8*HSTR];
                a[mt][2] = As[base + 4];
                a[mt][3] = As[base + 8*HSTR + 4];
            }
#pragma unroll
            for (int nt=0;nt<4;nt++) {
                int base = (wn + nt*8 + g)*HSTR + ks*8 + tig;
                b[nt][0] = Bs[base];
                b[nt][1] = Bs[base + 4];
            }
#pragma unroll
            for (int mt=0;mt<4;mt++)
#pragma unroll
                for (int nt=0;nt<4;nt++)
                    mma_f16(c[mt][nt], a[mt], b[nt]);
        }
    };

    int ktn = K>>5;
    load_tile(0, 0);
    asm volatile("cp.async.commit_group;");
    if (ktn > 1) load_tile(1, 32);
    asm volatile("cp.async.commit_group;");
    for (int kt=0; kt<ktn; kt++) {
        asm volatile("cp.async.wait_group 1;");
        __syncthreads();
        if (kt+2 < ktn) load_tile((kt+2)%3, (kt+2)*32);
        asm volatile("cp.async.commit_group;");
        compute(kt%3);
        __syncthreads();
    }

#pragma unroll
    for (int mt=0;mt<4;mt++) {
        long m = m0 + wm + mt*16 + g;
#pragma unroll
        for (int nt=0;nt<4;nt++) {
            int n = n0 + wn + nt*8 + tig*2;
            if (n < N) {
                float bx = bp[n], by = bp[n+1];
                float v00 = c[mt][nt][0]+bx, v01 = c[mt][nt][1]+by;
                float v10 = c[mt][nt][2]+bx, v11 = c[mt][nt][3]+by;
                if (OUT16) {
                    __half* Cb = (__half*)Cv + (long)z*sC;
                    *(__half2*)&Cb[m*ldc + n] = __floats2half2_rn(v00, v01);
                    *(__half2*)&Cb[(m+8)*ldc + n] = __floats2half2_rn(v10, v11);
                } else {
                    float* Cb = (float*)Cv + (long)z*sC;
                    float2 v0; v0.x = v00; v0.y = v01;
                    float2 v1; v1.x = v10; v1.y = v11;
                    *(float2*)&Cb[m*ldc + n] = v0;
                    *(float2*)&Cb[(m+8)*ldc + n] = v1;
                }
            }
        }
    }
}

// ---------------------------------------------------------------------------
// Fused fp16 QK^T + softmax -> P_h. Block tile 64x256, warp tile 32x64,
// 2 CTAs/SM. grid (1, 4, 384).
// ---------------------------------------------------------------------------
#define QA64 (64*HSTR)
#define QB256 (256*HSTR)
#define Q64_STG (QA64 + QB256)

__launch_bounds__(256, 2)
__global__ void qk_softmax_h(const __half* __restrict__ x, __half* __restrict__ P,
                             float scale)
{
    extern __shared__ uint32_t smp[];
    const int qtab[6]  = {0,0,1,1,2,2};
    const int kvtab[6] = {1,2,0,2,0,1};

    int z = blockIdx.z;
    int p = z>>6, b = z&63;
    const __half* Ab = x + ((long)qtab[p]*BS + (long)b*Ss)*128;
    const __half* Bp = x + ((long)kvtab[p]*BS + (long)b*Ss)*128;
    __half* Cb = P + (long)z*Ss*Ss;
    int m0 = blockIdx.y*64;
    int tid = threadIdx.x;
    int warp = tid>>5, lane = tid&31;
    int g = lane>>2, tig = lane&3;
    int wm = (warp&1)*32, wn = (warp>>1)*64;

    float c[2][8][4];
#pragma unroll
    for (int mt=0;mt<2;mt++)
#pragma unroll
        for (int nt=0;nt<8;nt++)
#pragma unroll
            for (int i=0;i<4;i++) c[mt][nt][i]=0.f;

    int arow_i = tid>>2;
    int aseg = (tid&3)*4;
    const __half* arow = Ab + (long)(m0+arow_i)*128;
    const __half* brow = Bp + (long)tid*128;

    auto load_tile = [&](int st, int k0) {
        uint32_t* As = smp + st*Q64_STG;
        uint32_t* Bs = As + QA64;
        cpa16(s2u(&As[arow_i*HSTR + aseg]), arow + k0 + aseg*2, 16);
#pragma unroll
        for (int h=0;h<4;h++)
            cpa16(s2u(&Bs[tid*HSTR + h*4]), brow + k0 + h*8, 16);
    };
    auto compute = [&](int st) {
        const uint32_t* As = smp + st*Q64_STG;
        const uint32_t* Bs = As + QA64;
#pragma unroll
        for (int ks=0;ks<2;ks++) {
            uint32_t a[2][4], bb[8][2];
#pragma unroll
            for (int mt=0;mt<2;mt++) {
                int base = (wm + mt*16 + g)*HSTR + ks*8 + tig;
                a[mt][0] = As[base];
                a[mt][1] = As[base + 8*HSTR];
                a[mt][2] = As[base + 4];
                a[mt][3] = As[base + 8*HSTR + 4];
            }
#pragma unroll
            for (int nt=0;nt<8;nt++) {
                int base = (wn + nt*8 + g)*HSTR + ks*8 + tig;
                bb[nt][0] = Bs[base];
                bb[nt][1] = Bs[base + 4];
            }
#pragma unroll
            for (int mt=0;mt<2;mt++)
#pragma unroll
                for (int nt=0;nt<8;nt++)
                    mma_f16(c[mt][nt], a[mt], bb[nt]);
        }
    };

    load_tile(0, 0);
    asm volatile("cp.async.commit_group;");
    load_tile(1, 32);
    asm volatile("cp.async.commit_group;");
    for (int kt=0; kt<4; kt++) {
        asm volatile("cp.async.wait_group 1;");
        __syncthreads();
        if (kt+2 < 4) load_tile((kt+2)%3, (kt+2)*32);
        asm volatile("cp.async.commit_group;");
        compute(kt%3);
        __syncthreads();
    }

#pragma unroll
    for (int mt=0;mt<2;mt++)
#pragma unroll
        for (int nt=0;nt<8;nt++)
#pragma unroll
            for (int i=0;i<4;i++) c[mt][nt][i] *= scale;

    float* red = (float*)smp;
    int wcol = warp>>1;
    float rmax[2][2], rinv[2][2];

#pragma unroll
    for (int mt=0;mt<2;mt++)
#pragma unroll
        for (int h=0;h<2;h++) {
            float m = -1e30f;
#pragma unroll
            for (int nt=0;nt<8;nt++)
                m = fmaxf(m, fmaxf(c[mt][nt][2*h], c[mt][nt][2*h+1]));
            m = fmaxf(m, __shfl_xor_sync(0xffffffffu, m, 1));
            m = fmaxf(m, __shfl_xor_sync(0xffffffffu, m, 2));
            if (tig == 0) red[(wm + mt*16 + g + h*8)*4 + wcol] = m;
        }
    __syncthreads();
#pragma unroll
    for (int mt=0;mt<2;mt++)
#pragma unroll
        for (int h=0;h<2;h++) {
            int r = wm + mt*16 + g + h*8;
            rmax[mt][h] = fmaxf(fmaxf(red[r*4], red[r*4+1]),
                                fmaxf(red[r*4+2], red[r*4+3]));
        }
    __syncthreads();
#pragma unroll
    for (int mt=0;mt<2;mt++)
#pragma unroll
        for (int h=0;h<2;h++) {
            float s = 0.f;
#pragma unroll
            for (int nt=0;nt<8;nt++) {
                float e0 = __expf(c[mt][nt][2*h]   - rmax[mt][h]);
                float e1 = __expf(c[mt][nt][2*h+1] - rmax[mt][h]);
                c[mt][nt][2*h]   = e0;
                c[mt][nt][2*h+1] = e1;
                s += e0 + e1;
            }
            s += __shfl_xor_sync(0xffffffffu, s, 1);
            s += __shfl_xor_sync(0xffffffffu, s, 2);
            if (tig == 0) red[(wm + mt*16 + g + h*8)*4 + wcol] = s;
        }
    __syncthreads();
#pragma unroll
    for (int mt=0;mt<2;mt++)
#pragma unroll
        for (int h=0;h<2;h++) {
            int r = wm + mt*16 + g + h*8;
            rinv[mt][h] = 1.f/(red[r*4] + red[r*4+1] + red[r*4+2] + red[r*4+3]);
        }
#pragma unroll
    for (int mt=0;mt<2;mt++)
#pragma unroll
        for (int h=0;h<2;h++) {
            long row = m0 + wm + mt*16 + g + h*8;
#pragma unroll
            for (int nt=0;nt<8;nt++) {
                int col = wn + nt*8 + tig*2;
                *(__half2*)&Cb[row*256 + col] =
                    __floats2half2_rn(c[mt][nt][2*h]   * rinv[mt][h],
                                      c[mt][nt][2*h+1] * rinv[mt][h]);
            }
        }
}

// ---------------------------------------------------------------------------
// Merged PV: base read from x_h (fp16), writes tstep_h only.
// ---------------------------------------------------------------------------
__launch_bounds__(256, 2)
__global__ void pv_h(const __half* __restrict__ P, const __half* __restrict__ xT,
                     const __half* __restrict__ x_h, __half* __restrict__ tstep_h)
{
    extern __shared__ uint32_t smp[];
    const int kvtab[6] = {1,2,0,2,0,1};
    int z = blockIdx.z;
    int qq = z>>6, b = z&63;
    const __half* baseq = x_h + ((long)qq*BS + (long)b*Ss)*128;
    __half* Ch = tstep_h + (long)qq*128 + (long)b*Ss*384;

    int m0 = blockIdx.y*128;
    int tid = threadIdx.x;
    int warp = tid>>5, lane = tid&31;
    int g = lane>>2, tig = lane&3;
    int wm = (warp&1)*64, wn = (warp>>1)*32;

    float c[4][4][4];
#pragma unroll
    for (int mt=0;mt<4;mt++)
#pragma unroll
        for (int nt=0;nt<4;nt++)
#pragma unroll
            for (int i=0;i<4;i++) c[mt][nt][i]=0.f;

    int lrow = tid>>1;
    int lseg = (tid&1)*8;

    auto load_tile = [&](int st, int gk) {
        int p = 2*qq + (gk>>3);
        int k0 = (gk&7)*32;
        const __half* ar = P + ((long)p*64 + b)*(long)Ss*Ss + (long)(m0+lrow)*Ss + k0;
        const __half* br = xT + ((long)kvtab[p]*64 + b)*128l*Ss + (long)lrow*Ss + k0;
        uint32_t* As = smp + st*HSTG;
        uint32_t* Bs = As + HA_WORDS;
        cpa16(s2u(&As[lrow*HSTR + lseg]),     ar + lseg*2,     16);
        cpa16(s2u(&As[lrow*HSTR + lseg + 4]), ar + lseg*2 + 8, 16);
        cpa16(s2u(&Bs[lrow*HSTR + lseg]),     br + lseg*2,     16);
        cpa16(s2u(&Bs[lrow*HSTR + lseg + 4]), br + lseg*2 + 8, 16);
    };
    auto compute = [&](int st) {
        const uint32_t* As = smp + st*HSTG;
        const uint32_t* Bs = As + HA_WORDS;
#pragma unroll
        for (int ks=0;ks<2;ks++) {
            uint32_t a[4][4], bb[4][2];
#pragma unroll
            for (int mt=0;mt<4;mt++) {
                int base = (wm + mt*16 + g)*HSTR + ks*8 + tig;
                a[mt][0] = As[base];
                a[mt][1] = As[base + 8*HSTR];
                a[mt][2] = As[base + 4];
                a[mt][3] = As[base + 8*HSTR + 4];
            }
#pragma unroll
            for (int nt=0;nt<4;nt++) {
                int base = (wn + nt*8 + g)*HSTR + ks*8 + tig;
                bb[nt][0] = Bs[base];
                bb[nt][1] = Bs[base + 4];
            }
#pragma unroll
            for (int mt=0;mt<4;mt++)
#pragma unroll
                for (int nt=0;nt<4;nt++)
                    mma_f16(c[mt][nt], a[mt], bb[nt]);
        }
    };

    load_tile(0, 0);
    asm volatile("cp.async.commit_group;");
    load_tile(1, 1);
    asm volatile("cp.async.commit_group;");
    for (int gk=0; gk<16; gk++) {
        asm volatile("cp.async.wait_group 1;");
        __syncthreads();
        if (gk+2 < 16) load_tile((gk+2)%3, gk+2);
        asm volatile("cp.async.commit_group;");
        compute(gk%3);
        __syncthreads();
    }

#pragma unroll
    for (int mt=0;mt<4;mt++) {
        long m = m0 + wm + mt*16 + g;
#pragma unroll
        for (int nt=0;nt<4;nt++) {
            int n = wn + nt*8 + tig*2;
            float2 b0 = __half22float2(*(const __half2*)&baseq[m*128 + n]);
            float2 b1 = __half22float2(*(const __half2*)&baseq[(m+8)*128 + n]);
            *(__half2*)&Ch[m*384 + n] =
                __floats2half2_rn(c[mt][nt][0]+b0.x, c[mt][nt][1]+b0.y);
            *(__half2*)&Ch[(m+8)*384 + n] =
                __floats2half2_rn(c[mt][nt][2]+b1.x, c[mt][nt][3]+b1.y);
        }
    }
}

// ---------------------------------------------------------------------------
// biGRU (R9 layout, fp16 xg, 4 accumulator chains, tanh-sigmoid).
// ---------------------------------------------------------------------------
__launch_bounds__(192, 3)
__global__ void gru_rec(const __half* __restrict__ xg_all, const float* __restrict__ Wh,
                        const float* __restrict__ bh, __half* __restrict__ x_h)
{
    int bx = blockIdx.x;
    int m = bx>>7, d = (bx>>6)&1, b = bx&63, md = m*2+d;
    int j = threadIdx.x;
    ull w2[32];
#pragma unroll
    for (int q=0;q<32;q++)
        w2[q] = pk(Wh[((long)md*64 + 2*q)*192 + j], Wh[((long)md*64 + 2*q+1)*192 + j]);
    float bhj = bh[md*192 + j];
    __shared__ alignas(16) float h_s[64];
    __shared__ float pre_s[192], xn_s[64];
    uint32_t hsa = s2u(h_s);
    if (j<64) h_s[j]=0.f;
    const __half* xg = xg_all + ((long)md*BS + (long)b*Ss)*192;
    int s0 = d ? (Ss-1) : 0;
    float xg_cur = __half2float(xg[(long)s0*192 + j]);
    for (int t=0;t<Ss;t++) {
        int s = d ? (Ss-1-t) : t;
        int sn = d ? (Ss-2-t) : (t+1);
        sn = sn < 0 ? 0 : (sn > Ss-1 ? Ss-1 : sn);
        __syncthreads();
        float xg_nxt = __half2float(xg[(long)sn*192 + j]);
        ull a0 = pk(bhj, 0.f), a1 = 0ull, a2 = 0ull, a3 = 0ull;
#pragma unroll
        for (int q=0;q<8;q++) {
            ull h0,h1,h2,h3;
            lds2x64(h0,h1, hsa + (2*q)*16);
            lds2x64(h2,h3, hsa + (2*q+1)*16);
            ffma2(a0, h0, w2[4*q]);
            ffma2(a1, h1, w2[4*q+1]);
            ffma2(a2, h2, w2[4*q+2]);
            ffma2(a3, h3, w2[4*q+3]);
        }
        float2 f0 = upk(a0), f1 = upk(a1), f2 = upk(a2), f3 = upk(a3);
        float acc = (f0.x + f0.y) + (f1.x + f1.y) + (f2.x + f2.y) + (f3.x + f3.y);
        float xgv = xg_cur;
        if (j<128) pre_s[j] = acc + xgv;
        else { pre_s[j] = acc; xn_s[j-128] = xgv; }
        __syncthreads();
        if (j<64) {
            float r = sigf(pre_s[j]);
            float zg = sigf(pre_s[64+j]);
            float n = tanhfast(xn_s[j] + r*pre_s[128+j]);
            float hn = (1.f-zg)*n + zg*h_s[j];
            h_s[j] = hn;
            long row = (long)b*Ss + s;
            x_h[((long)m*BS + row)*128 + d*64 + j] = __float2half(hn);
        }
        xg_cur = xg_nxt;
    }
}

// ---------------------------------------------------------------------------
// biLSTM (R9 layout, fp16 xg, 4 accumulator chains, tanh-sigmoid).
// ---------------------------------------------------------------------------
__launch_bounds__(512, 1)
__global__ void lstm_rec(const __half* __restrict__ xg_all, const float* __restrict__ Wh,
                         const float* __restrict__ bh, __half* __restrict__ sf_h)
{
    extern __shared__ unsigned char smraw[];
    ull*   Wlo2  = (ull*)smraw;
    float* h_s   = (float*)(smraw + 16*512*8);
    float* pre_s = (float*)(smraw + 16*512*8 + 512);
    int bx = blockIdx.x, d = bx>>6, b = bx&63;
    int j = threadIdx.x;
    const float* Whd = Wh + (long)d*128*512;
    ull w2[48];
#pragma unroll
    for (int q=0;q<48;q++)
        w2[q] = pk(Whd[(long)(2*q)*512 + j], Whd[(long)(2*q+1)*512 + j]);
    for (int q=0;q<16;q++)
        Wlo2[q*512 + j] = pk(Whd[(long)(96+2*q)*512 + j], Whd[(long)(97+2*q)*512 + j]);
    float bhj = bh[d*512 + j];
    float c = 0.f;
    if (j<128) h_s[j]=0.f;
    uint32_t hsa = s2u(h_s);
    const __half* xg = xg_all + ((long)d*BS + (long)b*Ss)*512;
    int s0 = d ? (Ss-1) : 0;
    float xg_cur = __half2float(xg[(long)s0*512 + j]);
    for (int t=0;t<Ss;t++) {
        int s = d ? (Ss-1-t) : t;
        int sn = d ? (Ss-2-t) : (t+1);
        sn = sn < 0 ? 0 : (sn > Ss-1 ? Ss-1 : sn);
        __syncthreads();
        float xg_nxt = __half2float(xg[(long)sn*512 + j]);
        ull a0 = pk(bhj, 0.f), a1 = 0ull, a2 = 0ull, a3 = 0ull;
#pragma unroll
        for (int q=0;q<12;q++) {
            ull h0,h1,h2,h3;
            lds2x64(h0,h1, hsa + (2*q)*16);
            lds2x64(h2,h3, hsa + (2*q+1)*16);
            ffma2(a0, h0, w2[4*q]);
            ffma2(a1, h1, w2[4*q+1]);
            ffma2(a2, h2, w2[4*q+2]);
            ffma2(a3, h3, w2[4*q+3]);
        }
#pragma unroll
        for (int q=0;q<4;q++) {
            ull h0,h1,h2,h3;
            lds2x64(h0,h1, hsa + 384 + (2*q)*16);
            lds2x64(h2,h3, hsa + 384 + (2*q+1)*16);
            ffma2(a0, h0, Wlo2[(4*q)*512 + j]);
            ffma2(a1, h1, Wlo2[(4*q+1)*512 + j]);
            ffma2(a2, h2, Wlo2[(4*q+2)*512 + j]);
            ffma2(a3, h3, Wlo2[(4*q+3)*512 + j]);
        }
        float2 f0 = upk(a0), f1 = upk(a1), f2 = upk(a2), f3 = upk(a3);
        float acc = (f0.x + f0.y) + (f1.x + f1.y) + (f2.x + f2.y) + (f3.x + f3.y) + xg_cur;
        pre_s[j] = acc;
        __syncthreads();
        if (j<128) {
            float ig = pre_s[j], fg = pre_s[128+j], gg = pre_s[256+j], og = pre_s[384+j];
            c = sigf(fg)*c + sigf(ig)*tanhfast(gg);
            float h = sigf(og)*tanhfast(c);
            h_s[j] = h;
            sf_h[((long)b*Ss + s)*256 + d*128 + j] = __float2half(h);
        }
        xg_cur = xg_nxt;
    }
}

// ---------------------------------------------------------------------------
// RGN (R9 layout, fp16 xg, 4 accumulator chains, tanh-sigmoid).
// ---------------------------------------------------------------------------
__launch_bounds__(384, 1)
__global__ void rgn_rec(const __half* __restrict__ xg_all, const float* __restrict__ Wh,
                        const float* __restrict__ state0, const float* __restrict__ state1,
                        float* __restrict__ outbuf)
{
    __shared__ alignas(16) float h_s[128];
    __shared__ float pre_s[384], xn_s[128];
    int bx = blockIdx.x, kk = bx>>6, b = bx&63;
    int j = threadIdx.x;
    const float* Whd = Wh + (long)kk*128*384;
    ull w2[64];
#pragma unroll
    for (int q=0;q<64;q++)
        w2[q] = pk(Whd[(long)(2*q)*384 + j], Whd[(long)(2*q+1)*384 + j]);
    if (j<128) h_s[j] = (kk==0?state0:state1)[b*128 + j];
    uint32_t hsa = s2u(h_s);
    const __half* xg = xg_all + ((long)kk*BS + (long)b*Ss)*384;
    int s0 = kk ? (Ss-1) : 0;
    float xg_cur = __half2float(xg[(long)s0*384 + j]);
    for (int t=0;t<Ss;t++) {
        int sn = kk ? (Ss-2-t) : (t+1);
        sn = sn < 0 ? 0 : (sn > Ss-1 ? Ss-1 : sn);
        __syncthreads();
        float xg_nxt = __half2float(xg[(long)sn*384 + j]);
        ull a0 = 0ull, a1 = 0ull, a2 = 0ull, a3 = 0ull;
#pragma unroll
        for (int q=0;q<16;q++) {
            ull h0,h1,h2,h3;
            lds2x64(h0,h1, hsa + (2*q)*16);
            lds2x64(h2,h3, hsa + (2*q+1)*16);
            ffma2(a0, h0, w2[4*q]);
            ffma2(a1, h1, w2[4*q+1]);
            ffma2(a2, h2, w2[4*q+2]);
            ffma2(a3, h3, w2[4*q+3]);
        }
        float2 f0 = upk(a0), f1 = upk(a1), f2 = upk(a2), f3 = upk(a3);
        float acc = (f0.x + f0.y) + (f1.x + f1.y) + (f2.x + f2.y) + (f3.x + f3.y);
        float xgv = xg_cur;
        if (j<256) pre_s[j] = acc + xgv;
        else { pre_s[j] = acc; xn_s[j-256] = xgv; }
        __syncthreads();
        if (j<128) {
            float r = sigf(pre_s[j]);
            float z = sigf(pre_s[128+j]);
            float n = tanhfast(xn_s[j] + r*pre_s[256+j]);
            h_s[j] = (1.f-z)*n + z*h_s[j];
        }
        xg_cur = xg_nxt;
    }
    __syncthreads();
    if (j<128) outbuf[((long)kk*64 + b)*128 + j] = h_s[j];
}

__launch_bounds__(32)
__global__ void final_fc(const float* __restrict__ outbuf,
                         const float* __restrict__ fc1W, const float* __restrict__ fc1b,
                         const float* __restrict__ fc2W, const float* __restrict__ fc2b,
                         float* __restrict__ out)
{
    int b = blockIdx.x, t = threadIdx.x;
    float acc = fc1b[t];
    for (int k=0;k<128;k++) {
        float x = outbuf[b*128+k] + outbuf[64*128 + b*128 + k];
        acc += x * fc1W[k*32 + t];
    }
    float h = acc > 0.f ? acc : 0.01f*acc;
    float v = h * fc2W[t];
#pragma unroll
    for (int o=16;o;o>>=1) v += __shfl_xor_sync(0xffffffffu, v, o);
    if (t==0) out[b] = v + fc2b[0];
}

extern "C" void kernel_launch(void* const* d_in, const int* in_sizes, int n_in,
                              void* d_out, int out_size)
{
    (void)in_sizes; (void)n_in; (void)out_size;
    const int*   sentences = (const int*)  d_in[0];
    const float* acoustic  = (const float*)d_in[1];
    const float* video     = (const float*)d_in[2];
    const float* state0    = (const float*)d_in[3];
    const float* state1    = (const float*)d_in[4];
    const float* emb       = (const float*)d_in[5];
    const float* proj_l_W  = (const float*)d_in[6];
    const float* proj_l_b  = (const float*)d_in[7];
    const float* proj_a_W  = (const float*)d_in[8];
    const float* proj_a_b  = (const float*)d_in[9];
    const float* proj_v_W  = (const float*)d_in[10];
    const float* proj_v_b  = (const float*)d_in[11];
    const float* gru_Wi    = (const float*)d_in[12];
    const float* gru_Wh    = (const float*)d_in[13];
    const float* gru_bi    = (const float*)d_in[14];
    const float* gru_bh    = (const float*)d_in[15];
    const float* lstm_Wi   = (const float*)d_in[16];
    const float* lstm_Wh   = (const float*)d_in[17];
    const float* lstm_bi   = (const float*)d_in[18];
    const float* lstm_bh   = (const float*)d_in[19];
    const float* rgn_Wx    = (const float*)d_in[20];
    const float* rgn_Wh    = (const float*)d_in[21];
    const float* rgn_b     = (const float*)d_in[22];
    const float* fc1_W     = (const float*)d_in[23];
    const float* fc1_b     = (const float*)d_in[24];
    const float* fc2_W     = (const float*)d_in[25];
    const float* fc2_b     = (const float*)d_in[26];
    float* out = (float*)d_out;

    float *rgn_out;
    __half *xg_gru,*xg_lstm,*xg_rgn;
    __half *seq_h,*x_h,*xT_h,*P_h,*tstep_h,*sf_h,*WT_h,*av_h;
    cudaGetSymbolAddress((void**)&xg_gru, g_xg_gru);
    cudaGetSymbolAddress((void**)&xg_lstm, g_xg_lstm);
    cudaGetSymbolAddress((void**)&xg_rgn, g_xg_rgn);
    cudaGetSymbolAddress((void**)&rgn_out, g_rgn_out);
    cudaGetSymbolAddress((void**)&seq_h, g_seq_h);
    cudaGetSymbolAddress((void**)&x_h, g_x_h);
    cudaGetSymbolAddress((void**)&xT_h, g_xT_h);
    cudaGetSymbolAddress((void**)&P_h, g_P_h);
    cudaGetSymbolAddress((void**)&tstep_h, g_tstep_h);
    cudaGetSymbolAddress((void**)&sf_h, g_sf_h);
    cudaGetSymbolAddress((void**)&WT_h, g_WT_h);
    cudaGetSymbolAddress((void**)&av_h, g_av_h);
    __half* gruT  = WT_h;
    __half* lstmT = gruT + 6*192*128;
    __half* rgnT  = lstmT + 2l*512*384;
    __half* projaT = rgnT + 2l*384*256;

    const size_t shm_tf3 = 3u*STG_WORDS*4u;
    const size_t shm_h   = 3u*HSTG*4u;
    const size_t shm_qk  = 3u*Q64_STG*4u;
    cudaFuncSetAttribute(gemm_tf, cudaFuncAttributeMaxDynamicSharedMemorySize, (int)shm_tf3);
    cudaFuncSetAttribute(gemm_h<0,1>, cudaFuncAttributeMaxDynamicSharedMemorySize, (int)shm_h);
    cudaFuncSetAttribute(gemm_h<1,1>, cudaFuncAttributeMaxDynamicSharedMemorySize, (int)shm_h);
    cudaFuncSetAttribute(gemm_h<2,1>, cudaFuncAttributeMaxDynamicSharedMemorySize, (int)shm_h);
    cudaFuncSetAttribute(qk_softmax_h, cudaFuncAttributeMaxDynamicSharedMemorySize, (int)shm_qk);
    cudaFuncSetAttribute(pv_h, cudaFuncAttributeMaxDynamicSharedMemorySize, (int)shm_h);
    cudaFuncSetAttribute(lstm_rec, cudaFuncAttributeMaxDynamicSharedMemorySize, 72*1024);

    // prep (one launch: all weight transposes + input conversions)
    prep_all<<<PREP_WT + PREP_CONV, dim3(32,8)>>>(
        gru_Wi, lstm_Wi, rgn_Wx, proj_a_W, proj_v_W, WT_h,
        acoustic, video, av_h);

    // modality projections -> seq_h
    gemm_tf<<<dim3(1, BS/128, 1), 256, shm_tf3>>>(
        emb, proj_l_W, proj_l_b, seq_h, BS, 128, DL, 128, sentences);
    gemm_h<2,1><<<dim3(1, BS/128, 2), 256, shm_h>>>(
        av_h, projaT, proj_a_b, seq_h + 1l*BS*DH, BS, 128, 0,
        0, 0, 0, (long)BS*DH, 128, proj_v_b);

    // GRU input projections (z=6) -> fp16 xg
    gemm_h<1,1><<<dim3(2, BS/128, 6), 256, shm_h>>>(
        seq_h, gruT, gru_bi, xg_gru, BS, 192, 128,
        (long)BS*DH, 192l*128, 192, (long)BS*192, 192, nullptr);

    // biGRU (writes x_h only)
    gru_rec<<<3*2*64, 192>>>(xg_gru, gru_Wh, gru_bh, x_h);
    xtrans<<<dim3(192, 4), 256>>>(x_h, xT_h);

    // JCAF
    const float scale = 0.08838834764831845f;
    qk_softmax_h<<<dim3(1, 4, 384), 256, shm_qk>>>(x_h, P_h, scale);
    pv_h<<<dim3(1, 2, 192), 256, shm_h>>>(P_h, xT_h, x_h, tstep_h);

    // LSTM input projections (z=2) -> fp16 xg
    gemm_h<0,1><<<dim3(4, BS/128, 2), 256, shm_h>>>(
        tstep_h, lstmT, lstm_bi, xg_lstm, BS, 512, 384,
        0, 512l*384, 512, (long)BS*512, 512, nullptr);

    lstm_rec<<<2*64, 512, 16*512*8 + 512 + 2048>>>(xg_lstm, lstm_Wh, lstm_bh, sf_h);

    // RGN input projections (z=2) -> fp16 xg
    gemm_h<0,1><<<dim3(3, BS/128, 2), 256, shm_h>>>(
        sf_h, rgnT, rgn_b, xg_rgn, BS, 384, 256,
        0, 384l*256, 384, (long)BS*384, 384, nullptr);

    rgn_rec<<<2*64, 384>>>(xg_rgn, rgn_Wh, state0, state1, rgn_out);

    final_fc<<<Bb, 32>>>(rgn_out, fc1_W, fc1_b, fc2_W, fc2_b, out);
}